// round 2
// baseline (speedup 1.0000x reference)
#include <cuda_runtime.h>

constexpr int BATCH = 256;

// ---------------- scratch (device globals; no allocation allowed) ----------------
__device__ __align__(16) float g_cat1[BATCH * 32 * 256];   // layer1 concat (relu'd)
__device__ __align__(16) float g_out1[BATCH * 64 * 256];   // layer1 pointwise out == layer2 unshuffled input
__device__ __align__(16) float g_cat2[BATCH * 64 * 256];   // layer2 concat (relu'd)
__device__ __align__(16) float g_h2[BATCH * 32768];        // flattened (shuffle folded) fc1 input
__device__ __align__(16) float g_fc1p[4 * BATCH * 1024];   // split-K partials
__device__ __align__(16) float g_hr[BATCH * 1024];         // relu(fc1)

// ======================= Layer 1: 3x3 conv (12 -> 16) =======================
__global__ __launch_bounds__(256) void k_l1_conv(const float* __restrict__ x,
                                                 const float* __restrict__ wa,
                                                 const float* __restrict__ ba) {
    __shared__ float xs[12 * 256];        // unshuffled input tile
    __shared__ float ws[12 * 9 * 16];     // [c][tap][oc]
    int b = blockIdx.x, tid = threadIdx.x;

    for (int i = tid; i < 12 * 256; i += 256) {
        int cu = i >> 8, t = i & 255;
        int h = t >> 4, w = t & 15;
        int c = cu >> 2, ii = (cu >> 1) & 1, jj = cu & 1;
        xs[i] = x[((b * 3 + c) * 32 + (2 * h + ii)) * 32 + 2 * w + jj];
    }
    for (int i = tid; i < 12 * 9 * 16; i += 256) {
        int oc = i & 15, ck = i >> 4;
        int c = ck / 9, tap = ck % 9;
        ws[i] = wa[(oc * 12 + c) * 9 + tap];
    }
    __syncthreads();

    int t = tid, h = t >> 4, w = t & 15;
    float acc[16];
#pragma unroll
    for (int o = 0; o < 16; o++) acc[o] = ba[o];
    for (int c = 0; c < 12; c++) {
        float p[9];
#pragma unroll
        for (int dy = 0; dy < 3; dy++)
#pragma unroll
            for (int dx = 0; dx < 3; dx++) {
                int y = h + dy - 1, xq = w + dx - 1;
                p[dy * 3 + dx] = (y >= 0 && y < 16 && xq >= 0 && xq < 16)
                                     ? xs[c * 256 + y * 16 + xq] : 0.f;
            }
#pragma unroll
        for (int tap = 0; tap < 9; tap++) {
            const float4* wv = (const float4*)&ws[(c * 9 + tap) * 16];
            float s = p[tap];
#pragma unroll
            for (int q = 0; q < 4; q++) {
                float4 w4 = wv[q];
                acc[q * 4 + 0] += s * w4.x; acc[q * 4 + 1] += s * w4.y;
                acc[q * 4 + 2] += s * w4.z; acc[q * 4 + 3] += s * w4.w;
            }
        }
    }
#pragma unroll
    for (int o = 0; o < 16; o++)
        g_cat1[((b * 32 + o) * 256) + t] = fmaxf(acc[o], 0.f);
}

// ======================= Layer 1: kNN branch (12ch, 64 samples, top-9, 16 out) ===
__global__ __launch_bounds__(256) void k_l1_knn(const float* __restrict__ x,
                                                const int* __restrict__ idx,
                                                const float* __restrict__ wb,
                                                const float* __restrict__ bb) {
    __shared__ float ss[12 * 64];       // samp[c][n]
    __shared__ float sn[64];
    __shared__ float ws[12 * 9 * 16];   // [c][k][oc]
    int b = blockIdx.x, tid = threadIdx.x;

    for (int i = tid; i < 12 * 64; i += 256) {
        int c = i >> 6, n = i & 63;
        int ts = idx[n];
        int h = ts >> 4, w = ts & 15;
        int cc = c >> 2, ii = (c >> 1) & 1, jj = c & 1;
        ss[i] = x[((b * 3 + cc) * 32 + (2 * h + ii)) * 32 + 2 * w + jj];
    }
    for (int i = tid; i < 12 * 9 * 16; i += 256) {
        int oc = i & 15, ck = i >> 4;
        int c = ck / 9, k = ck % 9;
        ws[i] = wb[(oc * 12 + c) * 9 + k];
    }
    __syncthreads();
    if (tid < 64) {
        float s = 0.f;
#pragma unroll
        for (int c = 0; c < 12; c++) { float v = ss[c * 64 + tid]; s += v * v; }
        sn[tid] = s;
    }
    __syncthreads();

    int t = tid, h = t >> 4, w = t & 15;
    float xr[12]; float xn = 0.f;
#pragma unroll
    for (int c = 0; c < 12; c++) {
        int cc = c >> 2, ii = (c >> 1) & 1, jj = c & 1;
        float v = x[((b * 3 + cc) * 32 + (2 * h + ii)) * 32 + 2 * w + jj];
        xr[c] = v; xn += v * v;
    }

    // top-9 smallest dist, stable ties (lower sample index wins)
    float bd[9]; int bi[9];
#pragma unroll
    for (int k = 0; k < 9; k++) { bd[k] = 3.0e38f; bi[k] = 0; }
    for (int n = 0; n < 64; n++) {
        float dot = 0.f;
#pragma unroll
        for (int c = 0; c < 12; c++) dot += xr[c] * ss[c * 64 + n];
        float d = xn + sn[n] - 2.f * dot;
        if (d < bd[8]) {
            bool placed = false;
#pragma unroll
            for (int j = 8; j > 0; --j) {
                if (!placed) {
                    if (d < bd[j - 1]) { bd[j] = bd[j - 1]; bi[j] = bi[j - 1]; }
                    else { bd[j] = d; bi[j] = n; placed = true; }
                }
            }
            if (!placed) { bd[0] = d; bi[0] = n; }
        }
    }

    float acc[16];
#pragma unroll
    for (int o = 0; o < 16; o++) acc[o] = bb[o];
#pragma unroll
    for (int c = 0; c < 12; c++) {
        float sg[9];
#pragma unroll
        for (int k = 0; k < 9; k++) sg[k] = ss[c * 64 + bi[k]];
#pragma unroll
        for (int k = 0; k < 9; k++) {
            const float4* wv = (const float4*)&ws[(c * 9 + k) * 16];
            float s = sg[k];
#pragma unroll
            for (int q = 0; q < 4; q++) {
                float4 w4 = wv[q];
                acc[q * 4 + 0] += s * w4.x; acc[q * 4 + 1] += s * w4.y;
                acc[q * 4 + 2] += s * w4.z; acc[q * 4 + 3] += s * w4.w;
            }
        }
    }
#pragma unroll
    for (int o = 0; o < 16; o++)
        g_cat1[((b * 32 + 16 + o) * 256) + t] = fmaxf(acc[o], 0.f);
}

// ======================= Layer 1: 1x1 conv (32 -> 64) =======================
__global__ __launch_bounds__(256) void k_l1_pw(const float* __restrict__ wp,
                                               const float* __restrict__ bp) {
    __shared__ float ws[64 * 32];
    int b = blockIdx.x, tid = threadIdx.x;
    for (int i = tid; i < 64 * 32; i += 256) ws[i] = wp[i];
    __syncthreads();
    float xv[32];
#pragma unroll
    for (int c = 0; c < 32; c++) xv[c] = g_cat1[(b * 32 + c) * 256 + tid];
    for (int oc = 0; oc < 64; oc++) {
        float acc = bp[oc];
        const float4* wv = (const float4*)&ws[oc * 32];
#pragma unroll
        for (int q = 0; q < 8; q++) {
            float4 w4 = wv[q];
            acc += xv[q * 4 + 0] * w4.x + xv[q * 4 + 1] * w4.y
                 + xv[q * 4 + 2] * w4.z + xv[q * 4 + 3] * w4.w;
        }
        g_out1[(b * 64 + oc) * 256 + tid] = acc;  // shuffle/unshuffle pair cancels
    }
}

// ======================= Layer 2: 3x3 conv (64 -> 32) =======================
__global__ __launch_bounds__(256) void k_l2_conv(const float* __restrict__ wa,
                                                 const float* __restrict__ ba) {
    extern __shared__ float sm[];
    float* xs = sm;               // 64*256
    float* ws = sm + 64 * 256;    // [c][tap][oc] 64*9*32
    int b = blockIdx.x, tid = threadIdx.x;
    for (int i = tid; i < 64 * 256; i += 256) xs[i] = g_out1[b * 64 * 256 + i];
    for (int i = tid; i < 64 * 9 * 32; i += 256) {
        int oc = i & 31, ck = i >> 5;
        int c = ck / 9, tap = ck % 9;
        ws[i] = wa[(oc * 64 + c) * 9 + tap];
    }
    __syncthreads();

    int t = tid, h = t >> 4, w = t & 15;
    float acc[32];
#pragma unroll
    for (int o = 0; o < 32; o++) acc[o] = ba[o];
    for (int c = 0; c < 64; c++) {
        float p[9];
#pragma unroll
        for (int dy = 0; dy < 3; dy++)
#pragma unroll
            for (int dx = 0; dx < 3; dx++) {
                int y = h + dy - 1, xq = w + dx - 1;
                p[dy * 3 + dx] = (y >= 0 && y < 16 && xq >= 0 && xq < 16)
                                     ? xs[c * 256 + y * 16 + xq] : 0.f;
            }
#pragma unroll
        for (int tap = 0; tap < 9; tap++) {
            const float4* wv = (const float4*)&ws[(c * 9 + tap) * 32];
            float s = p[tap];
#pragma unroll
            for (int q = 0; q < 8; q++) {
                float4 w4 = wv[q];
                acc[q * 4 + 0] += s * w4.x; acc[q * 4 + 1] += s * w4.y;
                acc[q * 4 + 2] += s * w4.z; acc[q * 4 + 3] += s * w4.w;
            }
        }
    }
#pragma unroll
    for (int o = 0; o < 32; o++)
        g_cat2[((b * 64 + o) * 256) + t] = fmaxf(acc[o], 0.f);
}

// ======================= Layer 2: kNN branch (64ch, 64 samples, top-9, 32 out) ===
__global__ __launch_bounds__(256) void k_l2_knn(const int* __restrict__ idx,
                                                const float* __restrict__ wb,
                                                const float* __restrict__ bb) {
    extern __shared__ float sm[];
    float* ss = sm;               // samp[c][n] 64*64
    float* ws = sm + 64 * 64;     // [c][k][oc] 64*9*32
    __shared__ float sn[64];
    int b = blockIdx.x, tid = threadIdx.x;

    for (int i = tid; i < 64 * 64; i += 256) {
        int c = i >> 6, n = i & 63;
        ss[i] = g_out1[(b * 64 + c) * 256 + idx[n]];
    }
    for (int i = tid; i < 64 * 9 * 32; i += 256) {
        int oc = i & 31, ck = i >> 5;
        int c = ck / 9, k = ck % 9;
        ws[i] = wb[(oc * 64 + c) * 9 + k];
    }
    __syncthreads();
    if (tid < 64) {
        float s = 0.f;
        for (int c = 0; c < 64; c++) { float v = ss[c * 64 + tid]; s += v * v; }
        sn[tid] = s;
    }
    __syncthreads();

    int t = tid;
    float xr[64]; float xn = 0.f;
#pragma unroll
    for (int c = 0; c < 64; c++) {
        float v = g_out1[(b * 64 + c) * 256 + t];
        xr[c] = v; xn += v * v;
    }

    float bd[9]; int bi[9];
#pragma unroll
    for (int k = 0; k < 9; k++) { bd[k] = 3.0e38f; bi[k] = 0; }
    for (int n = 0; n < 64; n++) {
        float dot = 0.f;
#pragma unroll
        for (int c = 0; c < 64; c++) dot += xr[c] * ss[c * 64 + n];
        float d = xn + sn[n] - 2.f * dot;
        if (d < bd[8]) {
            bool placed = false;
#pragma unroll
            for (int j = 8; j > 0; --j) {
                if (!placed) {
                    if (d < bd[j - 1]) { bd[j] = bd[j - 1]; bi[j] = bi[j - 1]; }
                    else { bd[j] = d; bi[j] = n; placed = true; }
                }
            }
            if (!placed) { bd[0] = d; bi[0] = n; }
        }
    }

    float acc[32];
#pragma unroll
    for (int o = 0; o < 32; o++) acc[o] = bb[o];
    for (int c = 0; c < 64; c++) {
        float sg[9];
#pragma unroll
        for (int k = 0; k < 9; k++) sg[k] = ss[c * 64 + bi[k]];
#pragma unroll
        for (int k = 0; k < 9; k++) {
            const float4* wv = (const float4*)&ws[(c * 9 + k) * 32];
            float s = sg[k];
#pragma unroll
            for (int q = 0; q < 8; q++) {
                float4 w4 = wv[q];
                acc[q * 4 + 0] += s * w4.x; acc[q * 4 + 1] += s * w4.y;
                acc[q * 4 + 2] += s * w4.z; acc[q * 4 + 3] += s * w4.w;
            }
        }
    }
#pragma unroll
    for (int o = 0; o < 32; o++)
        g_cat2[((b * 64 + 32 + o) * 256) + t] = fmaxf(acc[o], 0.f);
}

// ======================= Layer 2: 1x1 conv (64 -> 128) + final shuffle + flatten ==
__global__ __launch_bounds__(256) void k_l2_pw(const float* __restrict__ wp,
                                               const float* __restrict__ bp) {
    __shared__ float ws[128 * 64];
    int b = blockIdx.x, tid = threadIdx.x;
    for (int i = tid; i < 128 * 64; i += 256) ws[i] = wp[i];
    __syncthreads();
    float xv[64];
#pragma unroll
    for (int c = 0; c < 64; c++) xv[c] = g_cat2[(b * 64 + c) * 256 + tid];
    int h = tid >> 4, w = tid & 15;
    for (int oc = 0; oc < 128; oc++) {
        float acc = bp[oc];
        const float4* wv = (const float4*)&ws[oc * 64];
#pragma unroll
        for (int q = 0; q < 16; q++) {
            float4 w4 = wv[q];
            acc += xv[q * 4 + 0] * w4.x + xv[q * 4 + 1] * w4.y
                 + xv[q * 4 + 2] * w4.z + xv[q * 4 + 3] * w4.w;
        }
        // pixel_shuffle(r=2) folded into flatten order
        int cp = oc >> 2, ii = (oc >> 1) & 1, jj = oc & 1;
        g_h2[b * 32768 + cp * 1024 + (2 * h + ii) * 32 + 2 * w + jj] = acc;
    }
}

// ======================= fc1 GEMM: C[256,1024] = h2[256,32768] @ W^T, split-K=4 ===
__global__ __launch_bounds__(256) void k_fc1(const float* __restrict__ W) {
    __shared__ __align__(16) float As[16][68];
    __shared__ __align__(16) float Ws[16][68];
    int n0 = blockIdx.x * 64, m0 = blockIdx.y * 64, sk = blockIdx.z;
    int tid = threadIdx.x;
    int tx = tid & 15, ty = tid >> 4;
    int lm = tid >> 2, lk = (tid & 3) * 4;

    float acc[4][4];
#pragma unroll
    for (int i = 0; i < 4; i++)
#pragma unroll
        for (int j = 0; j < 4; j++) acc[i][j] = 0.f;

    long k0 = (long)sk * 8192;
    const float* aptr = &g_h2[(long)(m0 + lm) * 32768 + k0 + lk];
    const float* wptr = &W[(long)(n0 + lm) * 32768 + k0 + lk];

    for (int kt = 0; kt < 8192; kt += 16) {
        float4 av = *(const float4*)(aptr + kt);
        float4 wv = *(const float4*)(wptr + kt);
        As[lk + 0][lm] = av.x; As[lk + 1][lm] = av.y;
        As[lk + 2][lm] = av.z; As[lk + 3][lm] = av.w;
        Ws[lk + 0][lm] = wv.x; Ws[lk + 1][lm] = wv.y;
        Ws[lk + 2][lm] = wv.z; Ws[lk + 3][lm] = wv.w;
        __syncthreads();
#pragma unroll
        for (int kk = 0; kk < 16; kk++) {
            float4 a4 = *(const float4*)&As[kk][ty * 4];
            float4 b4 = *(const float4*)&Ws[kk][tx * 4];
            acc[0][0] += a4.x * b4.x; acc[0][1] += a4.x * b4.y;
            acc[0][2] += a4.x * b4.z; acc[0][3] += a4.x * b4.w;
            acc[1][0] += a4.y * b4.x; acc[1][1] += a4.y * b4.y;
            acc[1][2] += a4.y * b4.z; acc[1][3] += a4.y * b4.w;
            acc[2][0] += a4.z * b4.x; acc[2][1] += a4.z * b4.y;
            acc[2][2] += a4.z * b4.z; acc[2][3] += a4.z * b4.w;
            acc[3][0] += a4.w * b4.x; acc[3][1] += a4.w * b4.y;
            acc[3][2] += a4.w * b4.z; acc[3][3] += a4.w * b4.w;
        }
        __syncthreads();
    }
#pragma unroll
    for (int i = 0; i < 4; i++)
#pragma unroll
        for (int j = 0; j < 4; j++)
            g_fc1p[((long)sk * BATCH + (m0 + ty * 4 + i)) * 1024 + n0 + tx * 4 + j] = acc[i][j];
}

__global__ __launch_bounds__(256) void k_fc1_finish(const float* __restrict__ fc1b) {
    int i = blockIdx.x * 256 + threadIdx.x;
    int n = i & 1023;
    float s = g_fc1p[i] + g_fc1p[BATCH * 1024 + i]
            + g_fc1p[2 * BATCH * 1024 + i] + g_fc1p[3 * BATCH * 1024 + i];
    g_hr[i] = fmaxf(s + fc1b[n], 0.f);
}

// ======================= fc2: [256,1024] @ [1024,10]^T + bias ====================
__global__ __launch_bounds__(256) void k_fc2(const float* __restrict__ w2,
                                             const float* __restrict__ b2,
                                             float* __restrict__ out) {
    __shared__ float red[10 * 256];
    int b = blockIdx.x, tid = threadIdx.x;
    float p[10];
#pragma unroll
    for (int n = 0; n < 10; n++) p[n] = 0.f;
    for (int j = tid; j < 1024; j += 256) {
        float hv = g_hr[b * 1024 + j];
#pragma unroll
        for (int n = 0; n < 10; n++) p[n] += hv * w2[n * 1024 + j];
    }
#pragma unroll
    for (int n = 0; n < 10; n++) red[n * 256 + tid] = p[n];
    __syncthreads();
    for (int s = 128; s > 0; s >>= 1) {
        if (tid < s) {
#pragma unroll
            for (int n = 0; n < 10; n++) red[n * 256 + tid] += red[n * 256 + tid + s];
        }
        __syncthreads();
    }
    if (tid < 10) out[b * 10 + tid] = red[tid * 256] + b2[tid];
}

// =================================================================================
extern "C" void kernel_launch(void* const* d_in, const int* in_sizes, int n_in,
                              void* d_out, int out_size) {
    const float* x    = (const float*)d_in[0];
    const int*   idx1 = (const int*)d_in[1];
    const int*   idx2 = (const int*)d_in[2];
    const float* w1a  = (const float*)d_in[3];
    const float* b1a  = (const float*)d_in[4];
    const float* w1b  = (const float*)d_in[5];
    const float* b1b  = (const float*)d_in[6];
    const float* w1p  = (const float*)d_in[7];
    const float* b1p  = (const float*)d_in[8];
    const float* w2a  = (const float*)d_in[9];
    const float* b2a  = (const float*)d_in[10];
    const float* w2b  = (const float*)d_in[11];
    const float* b2b  = (const float*)d_in[12];
    const float* w2p  = (const float*)d_in[13];
    const float* b2p  = (const float*)d_in[14];
    const float* fc1w = (const float*)d_in[15];
    const float* fc1b = (const float*)d_in[16];
    const float* fc2w = (const float*)d_in[17];
    const float* fc2b = (const float*)d_in[18];
    float* out = (float*)d_out;

    const int smem_conv2 = (64 * 256 + 64 * 9 * 32) * 4;   // 139264 B
    const int smem_knn2  = (64 * 64 + 64 * 9 * 32) * 4;    //  90112 B
    cudaFuncSetAttribute(k_l2_conv, cudaFuncAttributeMaxDynamicSharedMemorySize, smem_conv2);
    cudaFuncSetAttribute(k_l2_knn,  cudaFuncAttributeMaxDynamicSharedMemorySize, smem_knn2);

    k_l1_conv<<<BATCH, 256>>>(x, w1a, b1a);
    k_l1_knn<<<BATCH, 256>>>(x, idx1, w1b, b1b);
    k_l1_pw<<<BATCH, 256>>>(w1p, b1p);
    k_l2_conv<<<BATCH, 256, smem_conv2>>>(w2a, b2a);
    k_l2_knn<<<BATCH, 256, smem_knn2>>>(idx2, w2b, b2b);
    k_l2_pw<<<BATCH, 256>>>(w2p, b2p);
    k_fc1<<<dim3(16, 4, 4), 256>>>(fc1w);
    k_fc1_finish<<<1024, 256>>>(fc1b);
    k_fc2<<<BATCH, 256>>>(fc2w, fc2b, out);
}

// round 3
// speedup vs baseline: 1.0554x; 1.0554x over previous
#include <cuda_runtime.h>

typedef unsigned long long ull;
constexpr int BATCH = 256;

// ---------------- scratch (device globals) ----------------
__device__ __align__(16) float g_cat1[BATCH * 32 * 256];
__device__ __align__(16) float g_out1[BATCH * 64 * 256];
__device__ __align__(16) float g_cat2[BATCH * 64 * 256];
__device__ __align__(16) float g_h2[BATCH * 32768];
__device__ __align__(16) float g_fc1p[4 * BATCH * 1024];
__device__ __align__(16) float g_hr[BATCH * 1024];
__device__ __align__(16) float g_r1a[1728];    // [c*9+tap][16oc]
__device__ __align__(16) float g_r1b[1728];
__device__ __align__(16) float g_r2a[18432];   // [c*9+tap][32oc]
__device__ __align__(16) float g_r2b[18432];

// ---------------- f32x2 helpers ----------------
__device__ __forceinline__ ull pack2(float lo, float hi) {
    ull r;
    asm("mov.b64 %0, {%1, %2};" : "=l"(r) : "r"(__float_as_uint(lo)), "r"(__float_as_uint(hi)));
    return r;
}
__device__ __forceinline__ ull packd(float s) { return pack2(s, s); }
__device__ __forceinline__ void fma2(ull& d, ull a, ull b) {
    asm("fma.rn.f32x2 %0, %1, %2, %3;" : "=l"(d) : "l"(a), "l"(b), "l"(d));
}
__device__ __forceinline__ float2 unpk(ull v) {
    unsigned lo, hi;
    asm("mov.b64 {%0, %1}, %2;" : "=r"(lo), "=r"(hi) : "l"(v));
    float2 f; f.x = __uint_as_float(lo); f.y = __uint_as_float(hi);
    return f;
}

// ---------------- weight repack ----------------
__global__ __launch_bounds__(256) void k_repack(const float* __restrict__ w1a,
                                                const float* __restrict__ w1b,
                                                const float* __restrict__ w2a,
                                                const float* __restrict__ w2b) {
    int i = blockIdx.x * 256 + threadIdx.x;
    if (i < 1728) {
        int oc = i / 108, rest = i % 108;          // [oc][c*9+tap]
        g_r1a[rest * 16 + oc] = w1a[i];
        g_r1b[rest * 16 + oc] = w1b[i];
    }
    if (i < 18432) {
        int oc = i / 576, rest = i % 576;
        g_r2a[rest * 32 + oc] = w2a[i];
        g_r2b[rest * 32 + oc] = w2b[i];
    }
}

// ======================= Layer 1: 3x3 conv (12 -> 16) =======================
__global__ __launch_bounds__(256) void k_l1_conv(const float* __restrict__ x,
                                                 const float* __restrict__ ba) {
    __shared__ __align__(16) float xs[12 * 256];
    __shared__ __align__(16) float wsh[1728];
    int b = blockIdx.x, tid = threadIdx.x;

    for (int i = tid; i < 12 * 256; i += 256) {
        int cu = i >> 8, t = i & 255;
        int h = t >> 4, w = t & 15;
        int c = cu >> 2, ii = (cu >> 1) & 1, jj = cu & 1;
        xs[i] = x[((b * 3 + c) * 32 + (2 * h + ii)) * 32 + 2 * w + jj];
    }
    for (int i = tid; i < 1728; i += 256) wsh[i] = g_r1a[i];
    __syncthreads();

    int t = tid, h = t >> 4, w = t & 15;
    ull acc[8];
#pragma unroll
    for (int o = 0; o < 8; o++) acc[o] = pack2(ba[2 * o], ba[2 * o + 1]);
    for (int c = 0; c < 12; c++) {
        float p[9];
#pragma unroll
        for (int dy = 0; dy < 3; dy++)
#pragma unroll
            for (int dx = 0; dx < 3; dx++) {
                int y = h + dy - 1, xq = w + dx - 1;
                p[dy * 3 + dx] = (y >= 0 && y < 16 && xq >= 0 && xq < 16)
                                     ? xs[c * 256 + y * 16 + xq] : 0.f;
            }
#pragma unroll
        for (int tap = 0; tap < 9; tap++) {
            ull s2 = packd(p[tap]);
            const longlong2* wv = (const longlong2*)&wsh[(c * 9 + tap) * 16];
#pragma unroll
            for (int q = 0; q < 4; q++) {
                longlong2 w4 = wv[q];
                fma2(acc[q * 2 + 0], s2, (ull)w4.x);
                fma2(acc[q * 2 + 1], s2, (ull)w4.y);
            }
        }
    }
#pragma unroll
    for (int o = 0; o < 8; o++) {
        float2 v = unpk(acc[o]);
        g_cat1[((b * 32 + 2 * o) * 256) + t] = fmaxf(v.x, 0.f);
        g_cat1[((b * 32 + 2 * o + 1) * 256) + t] = fmaxf(v.y, 0.f);
    }
}

// ======================= Layer 1: kNN branch =======================
__global__ __launch_bounds__(256) void k_l1_knn(const float* __restrict__ x,
                                                const int* __restrict__ idx,
                                                const float* __restrict__ bb) {
    __shared__ __align__(16) float ss[12 * 64];   // [c][n]
    __shared__ float sn[64];
    __shared__ __align__(16) float wsh[1728];
    int b = blockIdx.x, tid = threadIdx.x;

    for (int i = tid; i < 12 * 64; i += 256) {
        int c = i >> 6, n = i & 63;
        int ts = idx[n];
        int h = ts >> 4, w = ts & 15;
        int cc = c >> 2, ii = (c >> 1) & 1, jj = c & 1;
        ss[i] = x[((b * 3 + cc) * 32 + (2 * h + ii)) * 32 + 2 * w + jj];
    }
    for (int i = tid; i < 1728; i += 256) wsh[i] = g_r1b[i];
    __syncthreads();
    if (tid < 64) {
        float s = 0.f;
#pragma unroll
        for (int c = 0; c < 12; c++) { float v = ss[c * 64 + tid]; s += v * v; }
        sn[tid] = s;
    }
    __syncthreads();

    int t = tid, h = t >> 4, w = t & 15;
    float xr[12]; float xn = 0.f;
#pragma unroll
    for (int c = 0; c < 12; c++) {
        int cc = c >> 2, ii = (c >> 1) & 1, jj = c & 1;
        float v = x[((b * 3 + cc) * 32 + (2 * h + ii)) * 32 + 2 * w + jj];
        xr[c] = v; xn += v * v;
    }

    float bd[9]; int bi[9];
#pragma unroll
    for (int k = 0; k < 9; k++) { bd[k] = 3.0e38f; bi[k] = 0; }
    for (int n = 0; n < 64; n++) {
        float dot = 0.f;
#pragma unroll
        for (int c = 0; c < 12; c++) dot += xr[c] * ss[c * 64 + n];
        float d = xn + sn[n] - 2.f * dot;
        if (d < bd[8]) {
            bool placed = false;
#pragma unroll
            for (int j = 8; j > 0; --j) {
                if (!placed) {
                    if (d < bd[j - 1]) { bd[j] = bd[j - 1]; bi[j] = bi[j - 1]; }
                    else { bd[j] = d; bi[j] = n; placed = true; }
                }
            }
            if (!placed) { bd[0] = d; bi[0] = n; }
        }
    }

    ull acc[8];
#pragma unroll
    for (int o = 0; o < 8; o++) acc[o] = pack2(bb[2 * o], bb[2 * o + 1]);
#pragma unroll
    for (int c = 0; c < 12; c++) {
#pragma unroll
        for (int k = 0; k < 9; k++) {
            ull s2 = packd(ss[c * 64 + bi[k]]);
            const longlong2* wv = (const longlong2*)&wsh[(c * 9 + k) * 16];
#pragma unroll
            for (int q = 0; q < 4; q++) {
                longlong2 w4 = wv[q];
                fma2(acc[q * 2 + 0], s2, (ull)w4.x);
                fma2(acc[q * 2 + 1], s2, (ull)w4.y);
            }
        }
    }
#pragma unroll
    for (int o = 0; o < 8; o++) {
        float2 v = unpk(acc[o]);
        g_cat1[((b * 32 + 16 + 2 * o) * 256) + t] = fmaxf(v.x, 0.f);
        g_cat1[((b * 32 + 17 + 2 * o) * 256) + t] = fmaxf(v.y, 0.f);
    }
}

// ======================= Layer 1: 1x1 conv (32 -> 64) =======================
__global__ __launch_bounds__(256) void k_l1_pw(const float* __restrict__ wp,
                                               const float* __restrict__ bp) {
    __shared__ __align__(16) float ws[64 * 32];
    int b = blockIdx.x, tid = threadIdx.x;
    for (int i = tid; i < 64 * 32; i += 256) ws[i] = wp[i];
    __syncthreads();
    ull xv[16];
#pragma unroll
    for (int c2 = 0; c2 < 16; c2++) {
        float f0 = g_cat1[(b * 32 + 2 * c2) * 256 + tid];
        float f1 = g_cat1[(b * 32 + 2 * c2 + 1) * 256 + tid];
        xv[c2] = pack2(f0, f1);
    }
    for (int oc = 0; oc < 64; oc++) {
        ull a2 = 0ull;
        const longlong2* wv = (const longlong2*)&ws[oc * 32];
#pragma unroll
        for (int q = 0; q < 8; q++) {
            longlong2 w4 = wv[q];
            fma2(a2, xv[q * 2 + 0], (ull)w4.x);
            fma2(a2, xv[q * 2 + 1], (ull)w4.y);
        }
        float2 v = unpk(a2);
        g_out1[(b * 64 + oc) * 256 + tid] = v.x + v.y + bp[oc];
    }
}

// ======================= Layer 2: 3x3 conv (64 -> 32), oc-split x2 ==============
__global__ __launch_bounds__(256) void k_l2_conv(const float* __restrict__ ba) {
    extern __shared__ __align__(16) float sm[];
    float* xs = sm;                 // 64*256
    float* wsh = sm + 64 * 256;     // [c*9+tap][16oc]
    int b = blockIdx.x, oc0 = blockIdx.y * 16, tid = threadIdx.x;
    for (int i = tid; i < 64 * 256; i += 256) xs[i] = g_out1[b * 64 * 256 + i];
    for (int i = tid; i < 576 * 16; i += 256) {
        int row = i >> 4, o = i & 15;
        wsh[i] = g_r2a[row * 32 + oc0 + o];
    }
    __syncthreads();

    int t = tid, h = t >> 4, w = t & 15;
    ull acc[8];
#pragma unroll
    for (int o = 0; o < 8; o++) acc[o] = pack2(ba[oc0 + 2 * o], ba[oc0 + 2 * o + 1]);
    for (int c = 0; c < 64; c++) {
        float p[9];
#pragma unroll
        for (int dy = 0; dy < 3; dy++)
#pragma unroll
            for (int dx = 0; dx < 3; dx++) {
                int y = h + dy - 1, xq = w + dx - 1;
                p[dy * 3 + dx] = (y >= 0 && y < 16 && xq >= 0 && xq < 16)
                                     ? xs[c * 256 + y * 16 + xq] : 0.f;
            }
#pragma unroll
        for (int tap = 0; tap < 9; tap++) {
            ull s2 = packd(p[tap]);
            const longlong2* wv = (const longlong2*)&wsh[(c * 9 + tap) * 16];
#pragma unroll
            for (int q = 0; q < 4; q++) {
                longlong2 w4 = wv[q];
                fma2(acc[q * 2 + 0], s2, (ull)w4.x);
                fma2(acc[q * 2 + 1], s2, (ull)w4.y);
            }
        }
    }
#pragma unroll
    for (int o = 0; o < 8; o++) {
        float2 v = unpk(acc[o]);
        g_cat2[((b * 64 + oc0 + 2 * o) * 256) + t] = fmaxf(v.x, 0.f);
        g_cat2[((b * 64 + oc0 + 2 * o + 1) * 256) + t] = fmaxf(v.y, 0.f);
    }
}

// ======================= Layer 2: kNN branch, oc-split x2 =======================
__global__ __launch_bounds__(256) void k_l2_knn(const int* __restrict__ idx,
                                                const float* __restrict__ bb) {
    extern __shared__ __align__(16) float sm[];
    float* ss = sm;                 // [n][c] rows of 68
    float* wsh = sm + 64 * 68;      // [c*9+k][16oc]
    __shared__ float sn[64];
    int b = blockIdx.x, oc0 = blockIdx.y * 16, tid = threadIdx.x;

    for (int i = tid; i < 64 * 64; i += 256) {
        int n = i >> 6, c = i & 63;
        ss[n * 68 + c] = g_out1[(b * 64 + c) * 256 + idx[n]];
    }
    for (int i = tid; i < 576 * 16; i += 256) {
        int row = i >> 4, o = i & 15;
        wsh[i] = g_r2b[row * 32 + oc0 + o];
    }
    __syncthreads();
    if (tid < 64) {
        float s = 0.f;
        for (int c = 0; c < 64; c++) { float v = ss[tid * 68 + c]; s += v * v; }
        sn[tid] = s;
    }
    __syncthreads();

    int t = tid;
    ull xr2[32]; float xn = 0.f;
#pragma unroll
    for (int c2 = 0; c2 < 32; c2++) {
        float f0 = g_out1[(b * 64 + 2 * c2) * 256 + t];
        float f1 = g_out1[(b * 64 + 2 * c2 + 1) * 256 + t];
        xn += f0 * f0 + f1 * f1;
        xr2[c2] = pack2(f0, f1);
    }

    float bd[9]; int bi[9];
#pragma unroll
    for (int k = 0; k < 9; k++) { bd[k] = 3.0e38f; bi[k] = 0; }
    for (int n = 0; n < 64; n++) {
        const longlong2* sp = (const longlong2*)&ss[n * 68];
        ull d2 = 0ull;
#pragma unroll
        for (int j = 0; j < 16; j++) {
            longlong2 s4 = sp[j];
            fma2(d2, xr2[2 * j + 0], (ull)s4.x);
            fma2(d2, xr2[2 * j + 1], (ull)s4.y);
        }
        float2 dv = unpk(d2);
        float d = xn + sn[n] - 2.f * (dv.x + dv.y);
        if (d < bd[8]) {
            bool placed = false;
#pragma unroll
            for (int j = 8; j > 0; --j) {
                if (!placed) {
                    if (d < bd[j - 1]) { bd[j] = bd[j - 1]; bi[j] = bi[j - 1]; }
                    else { bd[j] = d; bi[j] = n; placed = true; }
                }
            }
            if (!placed) { bd[0] = d; bi[0] = n; }
        }
    }

    ull acc[8];
#pragma unroll
    for (int o = 0; o < 8; o++) acc[o] = pack2(bb[oc0 + 2 * o], bb[oc0 + 2 * o + 1]);
    for (int c = 0; c < 64; c++) {
        float sg[9];
#pragma unroll
        for (int k = 0; k < 9; k++) sg[k] = ss[bi[k] * 68 + c];
#pragma unroll
        for (int k = 0; k < 9; k++) {
            ull s2 = packd(sg[k]);
            const longlong2* wv = (const longlong2*)&wsh[(c * 9 + k) * 16];
#pragma unroll
            for (int q = 0; q < 4; q++) {
                longlong2 w4 = wv[q];
                fma2(acc[q * 2 + 0], s2, (ull)w4.x);
                fma2(acc[q * 2 + 1], s2, (ull)w4.y);
            }
        }
    }
#pragma unroll
    for (int o = 0; o < 8; o++) {
        float2 v = unpk(acc[o]);
        g_cat2[((b * 64 + 32 + oc0 + 2 * o) * 256) + t] = fmaxf(v.x, 0.f);
        g_cat2[((b * 64 + 33 + oc0 + 2 * o) * 256) + t] = fmaxf(v.y, 0.f);
    }
}

// ======================= Layer 2: 1x1 conv (64 -> 128) + shuffle/flatten ========
__global__ __launch_bounds__(256) void k_l2_pw(const float* __restrict__ wp,
                                               const float* __restrict__ bp) {
    __shared__ __align__(16) float ws[128 * 64];
    int b = blockIdx.x, tid = threadIdx.x;
    for (int i = tid; i < 128 * 64; i += 256) ws[i] = wp[i];
    __syncthreads();
    ull xv[32];
#pragma unroll
    for (int c2 = 0; c2 < 32; c2++) {
        float f0 = g_cat2[(b * 64 + 2 * c2) * 256 + tid];
        float f1 = g_cat2[(b * 64 + 2 * c2 + 1) * 256 + tid];
        xv[c2] = pack2(f0, f1);
    }
    int h = tid >> 4, w = tid & 15;
    for (int oc = 0; oc < 128; oc++) {
        ull a2 = 0ull;
        const longlong2* wv = (const longlong2*)&ws[oc * 64];
#pragma unroll
        for (int q = 0; q < 16; q++) {
            longlong2 w4 = wv[q];
            fma2(a2, xv[q * 2 + 0], (ull)w4.x);
            fma2(a2, xv[q * 2 + 1], (ull)w4.y);
        }
        float2 v = unpk(a2);
        float acc = v.x + v.y + bp[oc];
        int cp = oc >> 2, ii = (oc >> 1) & 1, jj = oc & 1;
        g_h2[b * 32768 + cp * 1024 + (2 * h + ii) * 32 + 2 * w + jj] = acc;
    }
}

// ======================= fc1 GEMM (f32x2 k-paired, 128x64 tile, split-K=4) ======
__global__ __launch_bounds__(256) void k_fc1(const float* __restrict__ W) {
    __shared__ __align__(16) float As[128 * 20];   // [m][k], pad 20
    __shared__ __align__(16) float Ws2[8 * 132];   // [kpair][n as float2], pad

    int n0 = blockIdx.x * 64, m0 = blockIdx.y * 128, sk = blockIdx.z;
    int tid = threadIdx.x;
    int tx = tid & 15, ty = tid >> 4;

    int ar = tid >> 1, akq = (tid & 1) * 8;       // A fill: row, k-offset
    int wr = tid >> 2, wkq = (tid & 3) * 4;       // W fill
    int wg = wkq >> 1;                            // kpair group (0,2,4,6)

    const float* ap = g_h2 + (m0 + ar) * 32768 + sk * 8192 + akq;
    const float* wp = W + (n0 + wr) * 32768 + sk * 8192 + wkq;

    ull acc[8][4];
#pragma unroll
    for (int i = 0; i < 8; i++)
#pragma unroll
        for (int j = 0; j < 4; j++) acc[i][j] = 0ull;

    float4 a0 = *(const float4*)(ap);
    float4 a1 = *(const float4*)(ap + 4);
    float4 wv = *(const float4*)(wp);

    for (int kt = 0; kt < 8192; kt += 16) {
        *(float4*)&As[ar * 20 + akq] = a0;
        *(float4*)&As[ar * 20 + akq + 4] = a1;
        *(float2*)&Ws2[wg * 132 + 2 * wr] = make_float2(wv.x, wv.y);
        *(float2*)&Ws2[(wg + 1) * 132 + 2 * wr] = make_float2(wv.z, wv.w);
        __syncthreads();

        if (kt + 16 < 8192) {
            a0 = *(const float4*)(ap + kt + 16);
            a1 = *(const float4*)(ap + kt + 20);
            wv = *(const float4*)(wp + kt + 16);
        }

#pragma unroll
        for (int kp = 0; kp < 4; kp++) {
            longlong2 a8[8];
#pragma unroll
            for (int i = 0; i < 8; i++)
                a8[i] = *(const longlong2*)&As[(ty * 8 + i) * 20 + 4 * kp];
            longlong2 b0 = *(const longlong2*)&Ws2[(2 * kp) * 132 + 4 * tx];
            longlong2 b1 = *(const longlong2*)&Ws2[(2 * kp) * 132 + 4 * tx + 64];
            longlong2 c0 = *(const longlong2*)&Ws2[(2 * kp + 1) * 132 + 4 * tx];
            longlong2 c1 = *(const longlong2*)&Ws2[(2 * kp + 1) * 132 + 4 * tx + 64];
#pragma unroll
            for (int i = 0; i < 8; i++) {
                fma2(acc[i][0], (ull)a8[i].x, (ull)b0.x);
                fma2(acc[i][1], (ull)a8[i].x, (ull)b0.y);
                fma2(acc[i][2], (ull)a8[i].x, (ull)b1.x);
                fma2(acc[i][3], (ull)a8[i].x, (ull)b1.y);
                fma2(acc[i][0], (ull)a8[i].y, (ull)c0.x);
                fma2(acc[i][1], (ull)a8[i].y, (ull)c0.y);
                fma2(acc[i][2], (ull)a8[i].y, (ull)c1.x);
                fma2(acc[i][3], (ull)a8[i].y, (ull)c1.y);
            }
        }
        __syncthreads();
    }

#pragma unroll
    for (int i = 0; i < 8; i++)
#pragma unroll
        for (int j = 0; j < 4; j++) {
            float2 v = unpk(acc[i][j]);
            float s = v.x + v.y;
            int n_off = (j < 2) ? (2 * tx + j) : (2 * tx + 32 + (j - 2));
            g_fc1p[((sk * BATCH) + (m0 + ty * 8 + i)) * 1024 + n0 + n_off] = s;
        }
}

__global__ __launch_bounds__(256) void k_fc1_finish(const float* __restrict__ fc1b) {
    int i = blockIdx.x * 256 + threadIdx.x;
    int n = i & 1023;
    float s = g_fc1p[i] + g_fc1p[BATCH * 1024 + i]
            + g_fc1p[2 * BATCH * 1024 + i] + g_fc1p[3 * BATCH * 1024 + i];
    g_hr[i] = fmaxf(s + fc1b[n], 0.f);
}

// ======================= fc2 ====================================================
__global__ __launch_bounds__(256) void k_fc2(const float* __restrict__ w2,
                                             const float* __restrict__ b2,
                                             float* __restrict__ out) {
    __shared__ float red[10 * 256];
    int b = blockIdx.x, tid = threadIdx.x;
    float p[10];
#pragma unroll
    for (int n = 0; n < 10; n++) p[n] = 0.f;
    for (int j = tid; j < 1024; j += 256) {
        float hv = g_hr[b * 1024 + j];
#pragma unroll
        for (int n = 0; n < 10; n++) p[n] += hv * w2[n * 1024 + j];
    }
#pragma unroll
    for (int n = 0; n < 10; n++) red[n * 256 + tid] = p[n];
    __syncthreads();
    for (int s = 128; s > 0; s >>= 1) {
        if (tid < s) {
#pragma unroll
            for (int n = 0; n < 10; n++) red[n * 256 + tid] += red[n * 256 + tid + s];
        }
        __syncthreads();
    }
    if (tid < 10) out[b * 10 + tid] = red[tid * 256] + b2[tid];
}

// =================================================================================
extern "C" void kernel_launch(void* const* d_in, const int* in_sizes, int n_in,
                              void* d_out, int out_size) {
    const float* x    = (const float*)d_in[0];
    const int*   idx1 = (const int*)d_in[1];
    const int*   idx2 = (const int*)d_in[2];
    const float* w1a  = (const float*)d_in[3];
    const float* b1a  = (const float*)d_in[4];
    const float* w1b  = (const float*)d_in[5];
    const float* b1b  = (const float*)d_in[6];
    const float* w1p  = (const float*)d_in[7];
    const float* b1p  = (const float*)d_in[8];
    const float* w2a  = (const float*)d_in[9];
    const float* b2a  = (const float*)d_in[10];
    const float* w2b  = (const float*)d_in[11];
    const float* b2b  = (const float*)d_in[12];
    const float* w2p  = (const float*)d_in[13];
    const float* b2p  = (const float*)d_in[14];
    const float* fc1w = (const float*)d_in[15];
    const float* fc1b = (const float*)d_in[16];
    const float* fc2w = (const float*)d_in[17];
    const float* fc2b = (const float*)d_in[18];
    float* out = (float*)d_out;

    const int smem_conv2 = (64 * 256 + 576 * 16) * 4;   // 102400 B
    const int smem_knn2  = (64 * 68 + 576 * 16) * 4;    //  54272 B
    cudaFuncSetAttribute(k_l2_conv, cudaFuncAttributeMaxDynamicSharedMemorySize, smem_conv2);
    cudaFuncSetAttribute(k_l2_knn,  cudaFuncAttributeMaxDynamicSharedMemorySize, smem_knn2);

    k_repack<<<72, 256>>>(w1a, w1b, w2a, w2b);
    k_l1_conv<<<BATCH, 256>>>(x, b1a);
    k_l1_knn<<<BATCH, 256>>>(x, idx1, b1b);
    k_l1_pw<<<BATCH, 256>>>(w1p, b1p);
    k_l2_conv<<<dim3(BATCH, 2), 256, smem_conv2>>>(b2a);
    k_l2_knn<<<dim3(BATCH, 2), 256, smem_knn2>>>(idx2, b2b);
    k_l2_pw<<<BATCH, 256>>>(w2p, b2p);
    k_fc1<<<dim3(16, 2, 4), 256>>>(fc1w);
    k_fc1_finish<<<1024, 256>>>(fc1b);
    k_fc2<<<BATCH, 256>>>(fc2w, fc2b, out);
}

// round 5
// speedup vs baseline: 1.6905x; 1.6018x over previous
#include <cuda_runtime.h>
#include <cuda_bf16.h>

typedef unsigned long long ull;
constexpr int BATCH = 256;

// ---------------- scratch (device globals) ----------------
__device__ __align__(16) float g_cat1[BATCH * 32 * 256];
__device__ __align__(16) float g_out1[BATCH * 64 * 256];
__device__ __align__(16) float g_cat2[BATCH * 64 * 256];
__device__ __align__(16) float g_h2[BATCH * 32768];
__device__ __align__(16) float g_fc1p[8 * BATCH * 1024];
__device__ __align__(16) float g_hr[BATCH * 1024];
__device__ __align__(16) float g_r1a[1728];
__device__ __align__(16) float g_r1b[1728];
__device__ __align__(16) float g_r2a[18432];
__device__ __align__(16) float g_r2b[18432];
__device__ __align__(16) __nv_bfloat16 g_ahi[BATCH * 32768];
__device__ __align__(16) __nv_bfloat16 g_alo[BATCH * 32768];

// ---------------- f32x2 helpers ----------------
__device__ __forceinline__ ull pack2(float lo, float hi) {
    ull r;
    asm("mov.b64 %0, {%1, %2};" : "=l"(r) : "r"(__float_as_uint(lo)), "r"(__float_as_uint(hi)));
    return r;
}
__device__ __forceinline__ ull packd(float s) { return pack2(s, s); }
__device__ __forceinline__ void fma2(ull& d, ull a, ull b) {
    asm("fma.rn.f32x2 %0, %1, %2, %3;" : "=l"(d) : "l"(a), "l"(b), "l"(d));
}
__device__ __forceinline__ float2 unpk(ull v) {
    unsigned lo, hi;
    asm("mov.b64 {%0, %1}, %2;" : "=r"(lo), "=r"(hi) : "l"(v));
    float2 f; f.x = __uint_as_float(lo); f.y = __uint_as_float(hi);
    return f;
}

// ---------------- mma.sync helpers (family-portable tensor path) ----------------
__device__ __forceinline__ unsigned smem_u32(const void* p) {
    unsigned a;
    asm("{ .reg .u64 t; cvta.to.shared.u64 t, %1; cvt.u32.u64 %0, t; }" : "=r"(a) : "l"(p));
    return a;
}
__device__ __forceinline__ void ldsm4(unsigned& r0, unsigned& r1, unsigned& r2, unsigned& r3,
                                      unsigned addr) {
    asm volatile("ldmatrix.sync.aligned.m8n8.x4.shared.b16 {%0,%1,%2,%3}, [%4];"
                 : "=r"(r0), "=r"(r1), "=r"(r2), "=r"(r3) : "r"(addr));
}
__device__ __forceinline__ void mma16816(float* c, const unsigned* a, const unsigned* b) {
    asm volatile(
        "mma.sync.aligned.m16n8k16.row.col.f32.bf16.bf16.f32 "
        "{%0,%1,%2,%3},{%4,%5,%6,%7},{%8,%9},{%0,%1,%2,%3};"
        : "+f"(c[0]), "+f"(c[1]), "+f"(c[2]), "+f"(c[3])
        : "r"(a[0]), "r"(a[1]), "r"(a[2]), "r"(a[3]), "r"(b[0]), "r"(b[1]));
}
__device__ __forceinline__ void cpa16(unsigned dst, const void* src) {
    asm volatile("cp.async.cg.shared.global [%0], [%1], 16;" :: "r"(dst), "l"(src));
}
__device__ __forceinline__ void cpa_commit() { asm volatile("cp.async.commit_group;"); }
__device__ __forceinline__ void cpa_wait0() {
    asm volatile("cp.async.wait_group 0;" ::: "memory");
}
__device__ __forceinline__ void sts128(unsigned addr, uint4 v) {
    asm volatile("st.shared.v4.b32 [%0], {%1,%2,%3,%4};"
                 :: "r"(addr), "r"(v.x), "r"(v.y), "r"(v.z), "r"(v.w));
}
__device__ __forceinline__ unsigned pkbf(float a, float b) {
    __nv_bfloat16 ha = __float2bfloat16(a), hb = __float2bfloat16(b);
    return ((unsigned)__bfloat16_as_ushort(hb) << 16) | __bfloat16_as_ushort(ha);
}

// ---------------- weight repack ----------------
__global__ __launch_bounds__(256) void k_repack(const float* __restrict__ w1a,
                                                const float* __restrict__ w1b,
                                                const float* __restrict__ w2a,
                                                const float* __restrict__ w2b) {
    int i = blockIdx.x * 256 + threadIdx.x;
    if (i < 1728) {
        int oc = i / 108, rest = i % 108;
        g_r1a[rest * 16 + oc] = w1a[i];
        g_r1b[rest * 16 + oc] = w1b[i];
    }
    if (i < 18432) {
        int oc = i / 576, rest = i % 576;
        g_r2a[rest * 32 + oc] = w2a[i];
        g_r2b[rest * 32 + oc] = w2b[i];
    }
}

// ---------------- fp32 -> bf16 hi/lo split for A ----------------
__global__ __launch_bounds__(256) void k_cvt_a() {
    long i = (long)blockIdx.x * 256 + threadIdx.x;
    float4 v = ((const float4*)g_h2)[i];
    __nv_bfloat16 h0 = __float2bfloat16(v.x), h1 = __float2bfloat16(v.y);
    __nv_bfloat16 h2 = __float2bfloat16(v.z), h3 = __float2bfloat16(v.w);
    uint2 hi, lo;
    hi.x = ((unsigned)__bfloat16_as_ushort(h1) << 16) | __bfloat16_as_ushort(h0);
    hi.y = ((unsigned)__bfloat16_as_ushort(h3) << 16) | __bfloat16_as_ushort(h2);
    lo.x = pkbf(v.x - __bfloat162float(h0), v.y - __bfloat162float(h1));
    lo.y = pkbf(v.z - __bfloat162float(h2), v.w - __bfloat162float(h3));
    ((uint2*)g_ahi)[i] = hi;
    ((uint2*)g_alo)[i] = lo;
}

// ======================= Layer 1: 3x3 conv (12 -> 16) =======================
__global__ __launch_bounds__(256) void k_l1_conv(const float* __restrict__ x,
                                                 const float* __restrict__ ba) {
    __shared__ __align__(16) float xs[12 * 256];
    __shared__ __align__(16) float wsh[1728];
    int b = blockIdx.x, tid = threadIdx.x;

    for (int i = tid; i < 12 * 256; i += 256) {
        int cu = i >> 8, t = i & 255;
        int h = t >> 4, w = t & 15;
        int c = cu >> 2, ii = (cu >> 1) & 1, jj = cu & 1;
        xs[i] = x[((b * 3 + c) * 32 + (2 * h + ii)) * 32 + 2 * w + jj];
    }
    for (int i = tid; i < 1728; i += 256) wsh[i] = g_r1a[i];
    __syncthreads();

    int t = tid, h = t >> 4, w = t & 15;
    ull acc[8];
#pragma unroll
    for (int o = 0; o < 8; o++) acc[o] = pack2(ba[2 * o], ba[2 * o + 1]);
    for (int c = 0; c < 12; c++) {
        float p[9];
#pragma unroll
        for (int dy = 0; dy < 3; dy++)
#pragma unroll
            for (int dx = 0; dx < 3; dx++) {
                int y = h + dy - 1, xq = w + dx - 1;
                p[dy * 3 + dx] = (y >= 0 && y < 16 && xq >= 0 && xq < 16)
                                     ? xs[c * 256 + y * 16 + xq] : 0.f;
            }
#pragma unroll
        for (int tap = 0; tap < 9; tap++) {
            ull s2 = packd(p[tap]);
            const longlong2* wv = (const longlong2*)&wsh[(c * 9 + tap) * 16];
#pragma unroll
            for (int q = 0; q < 4; q++) {
                longlong2 w4 = wv[q];
                fma2(acc[q * 2 + 0], s2, (ull)w4.x);
                fma2(acc[q * 2 + 1], s2, (ull)w4.y);
            }
        }
    }
#pragma unroll
    for (int o = 0; o < 8; o++) {
        float2 v = unpk(acc[o]);
        g_cat1[((b * 32 + 2 * o) * 256) + t] = fmaxf(v.x, 0.f);
        g_cat1[((b * 32 + 2 * o + 1) * 256) + t] = fmaxf(v.y, 0.f);
    }
}

// ======================= Layer 1: kNN branch =======================
__global__ __launch_bounds__(256) void k_l1_knn(const float* __restrict__ x,
                                                const int* __restrict__ idx,
                                                const float* __restrict__ bb) {
    __shared__ __align__(16) float ss[12 * 64];
    __shared__ float sn[64];
    __shared__ __align__(16) float wsh[1728];
    int b = blockIdx.x, tid = threadIdx.x;

    for (int i = tid; i < 12 * 64; i += 256) {
        int c = i >> 6, n = i & 63;
        int ts = idx[n];
        int h = ts >> 4, w = ts & 15;
        int cc = c >> 2, ii = (c >> 1) & 1, jj = c & 1;
        ss[i] = x[((b * 3 + cc) * 32 + (2 * h + ii)) * 32 + 2 * w + jj];
    }
    for (int i = tid; i < 1728; i += 256) wsh[i] = g_r1b[i];
    __syncthreads();
    if (tid < 64) {
        float s = 0.f;
#pragma unroll
        for (int c = 0; c < 12; c++) { float v = ss[c * 64 + tid]; s += v * v; }
        sn[tid] = s;
    }
    __syncthreads();

    int t = tid, h = t >> 4, w = t & 15;
    float xr[12]; float xn = 0.f;
#pragma unroll
    for (int c = 0; c < 12; c++) {
        int cc = c >> 2, ii = (c >> 1) & 1, jj = c & 1;
        float v = x[((b * 3 + cc) * 32 + (2 * h + ii)) * 32 + 2 * w + jj];
        xr[c] = v; xn += v * v;
    }

    float bd[9]; int bi[9];
#pragma unroll
    for (int k = 0; k < 9; k++) { bd[k] = 3.0e38f; bi[k] = 0; }
    for (int n = 0; n < 64; n++) {
        float dot = 0.f;
#pragma unroll
        for (int c = 0; c < 12; c++) dot += xr[c] * ss[c * 64 + n];
        float d = xn + sn[n] - 2.f * dot;
        if (d < bd[8]) {
            bool placed = false;
#pragma unroll
            for (int j = 8; j > 0; --j) {
                if (!placed) {
                    if (d < bd[j - 1]) { bd[j] = bd[j - 1]; bi[j] = bi[j - 1]; }
                    else { bd[j] = d; bi[j] = n; placed = true; }
                }
            }
            if (!placed) { bd[0] = d; bi[0] = n; }
        }
    }

    ull acc[8];
#pragma unroll
    for (int o = 0; o < 8; o++) acc[o] = pack2(bb[2 * o], bb[2 * o + 1]);
#pragma unroll
    for (int c = 0; c < 12; c++) {
#pragma unroll
        for (int k = 0; k < 9; k++) {
            ull s2 = packd(ss[c * 64 + bi[k]]);
            const longlong2* wv = (const longlong2*)&wsh[(c * 9 + k) * 16];
#pragma unroll
            for (int q = 0; q < 4; q++) {
                longlong2 w4 = wv[q];
                fma2(acc[q * 2 + 0], s2, (ull)w4.x);
                fma2(acc[q * 2 + 1], s2, (ull)w4.y);
            }
        }
    }
#pragma unroll
    for (int o = 0; o < 8; o++) {
        float2 v = unpk(acc[o]);
        g_cat1[((b * 32 + 16 + 2 * o) * 256) + t] = fmaxf(v.x, 0.f);
        g_cat1[((b * 32 + 17 + 2 * o) * 256) + t] = fmaxf(v.y, 0.f);
    }
}

// ======================= Layer 1: 1x1 conv (32 -> 64) =======================
__global__ __launch_bounds__(256) void k_l1_pw(const float* __restrict__ wp,
                                               const float* __restrict__ bp) {
    __shared__ __align__(16) float ws[64 * 32];
    int b = blockIdx.x, tid = threadIdx.x;
    for (int i = tid; i < 64 * 32; i += 256) ws[i] = wp[i];
    __syncthreads();
    ull xv[16];
#pragma unroll
    for (int c2 = 0; c2 < 16; c2++) {
        float f0 = g_cat1[(b * 32 + 2 * c2) * 256 + tid];
        float f1 = g_cat1[(b * 32 + 2 * c2 + 1) * 256 + tid];
        xv[c2] = pack2(f0, f1);
    }
    for (int oc = 0; oc < 64; oc++) {
        ull a2 = 0ull;
        const longlong2* wv = (const longlong2*)&ws[oc * 32];
#pragma unroll
        for (int q = 0; q < 8; q++) {
            longlong2 w4 = wv[q];
            fma2(a2, xv[q * 2 + 0], (ull)w4.x);
            fma2(a2, xv[q * 2 + 1], (ull)w4.y);
        }
        float2 v = unpk(a2);
        g_out1[(b * 64 + oc) * 256 + tid] = v.x + v.y + bp[oc];
    }
}

// ======================= Layer 2: 3x3 conv (64 -> 32), oc-split x2 ==============
__global__ __launch_bounds__(256) void k_l2_conv(const float* __restrict__ ba) {
    extern __shared__ __align__(16) float sm[];
    float* xs = sm;
    float* wsh = sm + 64 * 256;
    int b = blockIdx.x, oc0 = blockIdx.y * 16, tid = threadIdx.x;
    for (int i = tid; i < 64 * 256; i += 256) xs[i] = g_out1[b * 64 * 256 + i];
    for (int i = tid; i < 576 * 16; i += 256) {
        int row = i >> 4, o = i & 15;
        wsh[i] = g_r2a[row * 32 + oc0 + o];
    }
    __syncthreads();

    int t = tid, h = t >> 4, w = t & 15;
    ull acc[8];
#pragma unroll
    for (int o = 0; o < 8; o++) acc[o] = pack2(ba[oc0 + 2 * o], ba[oc0 + 2 * o + 1]);
    for (int c = 0; c < 64; c++) {
        float p[9];
#pragma unroll
        for (int dy = 0; dy < 3; dy++)
#pragma unroll
            for (int dx = 0; dx < 3; dx++) {
                int y = h + dy - 1, xq = w + dx - 1;
                p[dy * 3 + dx] = (y >= 0 && y < 16 && xq >= 0 && xq < 16)
                                     ? xs[c * 256 + y * 16 + xq] : 0.f;
            }
#pragma unroll
        for (int tap = 0; tap < 9; tap++) {
            ull s2 = packd(p[tap]);
            const longlong2* wv = (const longlong2*)&wsh[(c * 9 + tap) * 16];
#pragma unroll
            for (int q = 0; q < 4; q++) {
                longlong2 w4 = wv[q];
                fma2(acc[q * 2 + 0], s2, (ull)w4.x);
                fma2(acc[q * 2 + 1], s2, (ull)w4.y);
            }
        }
    }
#pragma unroll
    for (int o = 0; o < 8; o++) {
        float2 v = unpk(acc[o]);
        g_cat2[((b * 64 + oc0 + 2 * o) * 256) + t] = fmaxf(v.x, 0.f);
        g_cat2[((b * 64 + oc0 + 2 * o + 1) * 256) + t] = fmaxf(v.y, 0.f);
    }
}

// ======================= Layer 2: kNN branch, oc-split x2 =======================
__global__ __launch_bounds__(256) void k_l2_knn(const int* __restrict__ idx,
                                                const float* __restrict__ bb) {
    extern __shared__ __align__(16) float sm[];
    float* ss = sm;
    float* wsh = sm + 64 * 68;
    __shared__ float sn[64];
    int b = blockIdx.x, oc0 = blockIdx.y * 16, tid = threadIdx.x;

    for (int i = tid; i < 64 * 64; i += 256) {
        int n = i >> 6, c = i & 63;
        ss[n * 68 + c] = g_out1[(b * 64 + c) * 256 + idx[n]];
    }
    for (int i = tid; i < 576 * 16; i += 256) {
        int row = i >> 4, o = i & 15;
        wsh[i] = g_r2b[row * 32 + oc0 + o];
    }
    __syncthreads();
    if (tid < 64) {
        float s = 0.f;
        for (int c = 0; c < 64; c++) { float v = ss[tid * 68 + c]; s += v * v; }
        sn[tid] = s;
    }
    __syncthreads();

    int t = tid;
    ull xr2[32]; float xn = 0.f;
#pragma unroll
    for (int c2 = 0; c2 < 32; c2++) {
        float f0 = g_out1[(b * 64 + 2 * c2) * 256 + t];
        float f1 = g_out1[(b * 64 + 2 * c2 + 1) * 256 + t];
        xn += f0 * f0 + f1 * f1;
        xr2[c2] = pack2(f0, f1);
    }

    float bd[9]; int bi[9];
#pragma unroll
    for (int k = 0; k < 9; k++) { bd[k] = 3.0e38f; bi[k] = 0; }
    for (int n = 0; n < 64; n++) {
        const longlong2* sp = (const longlong2*)&ss[n * 68];
        ull d2 = 0ull;
#pragma unroll
        for (int j = 0; j < 16; j++) {
            longlong2 s4 = sp[j];
            fma2(d2, xr2[2 * j + 0], (ull)s4.x);
            fma2(d2, xr2[2 * j + 1], (ull)s4.y);
        }
        float2 dv = unpk(d2);
        float d = xn + sn[n] - 2.f * (dv.x + dv.y);
        if (d < bd[8]) {
            bool placed = false;
#pragma unroll
            for (int j = 8; j > 0; --j) {
                if (!placed) {
                    if (d < bd[j - 1]) { bd[j] = bd[j - 1]; bi[j] = bi[j - 1]; }
                    else { bd[j] = d; bi[j] = n; placed = true; }
                }
            }
            if (!placed) { bd[0] = d; bi[0] = n; }
        }
    }

    ull acc[8];
#pragma unroll
    for (int o = 0; o < 8; o++) acc[o] = pack2(bb[oc0 + 2 * o], bb[oc0 + 2 * o + 1]);
    for (int c = 0; c < 64; c++) {
        float sg[9];
#pragma unroll
        for (int k = 0; k < 9; k++) sg[k] = ss[bi[k] * 68 + c];
#pragma unroll
        for (int k = 0; k < 9; k++) {
            ull s2 = packd(sg[k]);
            const longlong2* wv = (const longlong2*)&wsh[(c * 9 + k) * 16];
#pragma unroll
            for (int q = 0; q < 4; q++) {
                longlong2 w4 = wv[q];
                fma2(acc[q * 2 + 0], s2, (ull)w4.x);
                fma2(acc[q * 2 + 1], s2, (ull)w4.y);
            }
        }
    }
#pragma unroll
    for (int o = 0; o < 8; o++) {
        float2 v = unpk(acc[o]);
        g_cat2[((b * 64 + 32 + oc0 + 2 * o) * 256) + t] = fmaxf(v.x, 0.f);
        g_cat2[((b * 64 + 33 + oc0 + 2 * o) * 256) + t] = fmaxf(v.y, 0.f);
    }
}

// ======================= Layer 2: 1x1 conv (64 -> 128) + shuffle/flatten ========
__global__ __launch_bounds__(256) void k_l2_pw(const float* __restrict__ wp,
                                               const float* __restrict__ bp) {
    __shared__ __align__(16) float ws[128 * 64];
    int b = blockIdx.x, tid = threadIdx.x;
    for (int i = tid; i < 128 * 64; i += 256) ws[i] = wp[i];
    __syncthreads();
    ull xv[32];
#pragma unroll
    for (int c2 = 0; c2 < 32; c2++) {
        float f0 = g_cat2[(b * 64 + 2 * c2) * 256 + tid];
        float f1 = g_cat2[(b * 64 + 2 * c2 + 1) * 256 + tid];
        xv[c2] = pack2(f0, f1);
    }
    int h = tid >> 4, w = tid & 15;
    for (int oc = 0; oc < 128; oc++) {
        ull a2 = 0ull;
        const longlong2* wv = (const longlong2*)&ws[oc * 64];
#pragma unroll
        for (int q = 0; q < 16; q++) {
            longlong2 w4 = wv[q];
            fma2(a2, xv[q * 2 + 0], (ull)w4.x);
            fma2(a2, xv[q * 2 + 1], (ull)w4.y);
        }
        float2 v = unpk(a2);
        float acc = v.x + v.y + bp[oc];
        int cp = oc >> 2, ii = (oc >> 1) & 1, jj = oc & 1;
        g_h2[b * 32768 + cp * 1024 + (2 * h + ii) * 32 + 2 * w + jj] = acc;
    }
}

// ======================= fc1: bf16 split GEMM via mma.sync ======================
// C[256,1024] = A @ W^T;  AhWh + AhWl + AlWh, fp32 acc.
// Grid (16 n-tiles, 1, 8 splitk). CTA: M=256, N=64, kc=32, 2-stage pipeline.
// smem stage: Ah 16K | Al 16K | Wh 4K | Wl 4K  = 40960 B; x2 = 81920 B.
__global__ __launch_bounds__(256) void k_fc1t(const float* __restrict__ W) {
    extern __shared__ __align__(16) char smem[];
    unsigned sbase = smem_u32(smem);
    int tid = threadIdx.x, lane = tid & 31, warp = tid >> 5;
    int n0 = blockIdx.x * 64, sk = blockIdx.z;
    long kbase = (long)sk * 4096;

    int m_base = (warp & 3) * 64;      // warp m offset
    int n_base = (warp >> 2) * 32;     // warp n offset

    // --- fill lane assignments ---
    // A: 4 chunks each for Ah and Al per stage per thread
    int aq[4], ac[4];
#pragma unroll
    for (int j = 0; j < 4; j++) { int q = tid + j * 256; aq[j] = q >> 2; ac[j] = q & 3; }
    // W: thread -> row tid>>2, chunk tid&3 (8 floats)
    int wr = tid >> 2, wc = tid & 3;
    unsigned wsw = (unsigned)((wc ^ ((wr >> 1) & 3)) << 4);

    float acc[4][4][4];
#pragma unroll
    for (int i = 0; i < 4; i++)
#pragma unroll
        for (int j = 0; j < 4; j++)
#pragma unroll
            for (int q = 0; q < 4; q++) acc[i][j][q] = 0.f;

    const float* wgp = W + (long)(n0 + wr) * 32768 + kbase + wc * 8;

    // ---- prologue: stage 0 ----
    float4 w0a = *(const float4*)(wgp);
    float4 w0b = *(const float4*)(wgp + 4);
#pragma unroll
    for (int j = 0; j < 4; j++) {
        int r = aq[j], c = ac[j];
        unsigned sw = (unsigned)(r * 64 + ((c ^ ((r >> 1) & 3)) << 4));
        cpa16(sbase + sw, g_ahi + (long)r * 32768 + kbase + c * 8);
        cpa16(sbase + 16384 + sw, g_alo + (long)r * 32768 + kbase + c * 8);
    }
    cpa_commit();
    {
        uint4 hi, lo;
        hi.x = pkbf(w0a.x, w0a.y); hi.y = pkbf(w0a.z, w0a.w);
        hi.z = pkbf(w0b.x, w0b.y); hi.w = pkbf(w0b.z, w0b.w);
        __nv_bfloat16 t0 = __float2bfloat16(w0a.x), t1 = __float2bfloat16(w0a.y);
        __nv_bfloat16 t2 = __float2bfloat16(w0a.z), t3 = __float2bfloat16(w0a.w);
        __nv_bfloat16 t4 = __float2bfloat16(w0b.x), t5 = __float2bfloat16(w0b.y);
        __nv_bfloat16 t6 = __float2bfloat16(w0b.z), t7 = __float2bfloat16(w0b.w);
        lo.x = pkbf(w0a.x - __bfloat162float(t0), w0a.y - __bfloat162float(t1));
        lo.y = pkbf(w0a.z - __bfloat162float(t2), w0a.w - __bfloat162float(t3));
        lo.z = pkbf(w0b.x - __bfloat162float(t4), w0b.y - __bfloat162float(t5));
        lo.w = pkbf(w0b.z - __bfloat162float(t6), w0b.w - __bfloat162float(t7));
        sts128(sbase + 32768 + wr * 64 + wsw, hi);
        sts128(sbase + 36864 + wr * 64 + wsw, lo);
    }

    int ri = lane & 7, mat = lane >> 3;

    for (int it = 0; it < 128; it++) {
        int st = it & 1;
        unsigned stb = sbase + st * 40960u;
        cpa_wait0();
        __syncthreads();

        float4 wna, wnb;
        if (it < 127) {
            long ko = kbase + (it + 1) * 32;
            wna = *(const float4*)(wgp + (it + 1) * 32);
            wnb = *(const float4*)(wgp + (it + 1) * 32 + 4);
            unsigned nb = sbase + (st ^ 1) * 40960u;
#pragma unroll
            for (int j = 0; j < 4; j++) {
                int r = aq[j], c = ac[j];
                unsigned sw = (unsigned)(r * 64 + ((c ^ ((r >> 1) & 3)) << 4));
                cpa16(nb + sw, g_ahi + (long)r * 32768 + ko + c * 8);
                cpa16(nb + 16384 + sw, g_alo + (long)r * 32768 + ko + c * 8);
            }
            cpa_commit();
        }

        // ---- compute on stage st ----
#pragma unroll
        for (int k16 = 0; k16 < 2; k16++) {
            unsigned ah[4][4], al[4][4], bh[4][2], bl[4][2];
            // A frags
#pragma unroll
            for (int mi = 0; mi < 4; mi++) {
                int row = m_base + mi * 16 + ri + ((mat & 1) << 3);
                int c = k16 * 2 + (mat >> 1);
                unsigned ad = stb + row * 64 + ((c ^ ((row >> 1) & 3)) << 4);
                ldsm4(ah[mi][0], ah[mi][1], ah[mi][2], ah[mi][3], ad);
                ldsm4(al[mi][0], al[mi][1], al[mi][2], al[mi][3], ad + 16384);
            }
            // B frags
#pragma unroll
            for (int ng = 0; ng < 2; ng++) {
                int row = n_base + ng * 16 + ri + ((mat >> 1) << 3);
                int c = k16 * 2 + (mat & 1);
                unsigned bd = stb + 32768 + row * 64 + ((c ^ ((row >> 1) & 3)) << 4);
                unsigned r0, r1, r2, r3;
                ldsm4(r0, r1, r2, r3, bd);
                bh[2 * ng][0] = r0; bh[2 * ng][1] = r1;
                bh[2 * ng + 1][0] = r2; bh[2 * ng + 1][1] = r3;
                ldsm4(r0, r1, r2, r3, bd + 4096);
                bl[2 * ng][0] = r0; bl[2 * ng][1] = r1;
                bl[2 * ng + 1][0] = r2; bl[2 * ng + 1][1] = r3;
            }
#pragma unroll
            for (int mi = 0; mi < 4; mi++)
#pragma unroll
                for (int ni = 0; ni < 4; ni++) {
                    mma16816(acc[mi][ni], ah[mi], bh[ni]);
                    mma16816(acc[mi][ni], ah[mi], bl[ni]);
                    mma16816(acc[mi][ni], al[mi], bh[ni]);
                }
        }

        if (it < 127) {
            uint4 hi, lo;
            hi.x = pkbf(wna.x, wna.y); hi.y = pkbf(wna.z, wna.w);
            hi.z = pkbf(wnb.x, wnb.y); hi.w = pkbf(wnb.z, wnb.w);
            __nv_bfloat16 t0 = __float2bfloat16(wna.x), t1 = __float2bfloat16(wna.y);
            __nv_bfloat16 t2 = __float2bfloat16(wna.z), t3 = __float2bfloat16(wna.w);
            __nv_bfloat16 t4 = __float2bfloat16(wnb.x), t5 = __float2bfloat16(wnb.y);
            __nv_bfloat16 t6 = __float2bfloat16(wnb.z), t7 = __float2bfloat16(wnb.w);
            lo.x = pkbf(wna.x - __bfloat162float(t0), wna.y - __bfloat162float(t1));
            lo.y = pkbf(wna.z - __bfloat162float(t2), wna.w - __bfloat162float(t3));
            lo.z = pkbf(wnb.x - __bfloat162float(t4), wnb.y - __bfloat162float(t5));
            lo.w = pkbf(wnb.z - __bfloat162float(t6), wnb.w - __bfloat162float(t7));
            unsigned nb = sbase + (st ^ 1) * 40960u;
            sts128(nb + 32768 + wr * 64 + wsw, hi);
            sts128(nb + 36864 + wr * 64 + wsw, lo);
        }
    }

    // ---- epilogue: write split-K slab ----
    float* slab = g_fc1p + (long)sk * BATCH * 1024;
#pragma unroll
    for (int mi = 0; mi < 4; mi++)
#pragma unroll
        for (int ni = 0; ni < 4; ni++) {
            int m = m_base + mi * 16 + (lane >> 2);
            int n = n0 + n_base + ni * 8 + (lane & 3) * 2;
            *(float2*)&slab[(long)m * 1024 + n] =
                make_float2(acc[mi][ni][0], acc[mi][ni][1]);
            *(float2*)&slab[(long)(m + 8) * 1024 + n] =
                make_float2(acc[mi][ni][2], acc[mi][ni][3]);
        }
}

__global__ __launch_bounds__(256) void k_fc1_finish(const float* __restrict__ fc1b) {
    int i = blockIdx.x * 256 + threadIdx.x;
    int n = i & 1023;
    float s = 0.f;
#pragma unroll
    for (int q = 0; q < 8; q++) s += g_fc1p[(long)q * BATCH * 1024 + i];
    g_hr[i] = fmaxf(s + fc1b[n], 0.f);
}

// ======================= fc2 ====================================================
__global__ __launch_bounds__(256) void k_fc2(const float* __restrict__ w2,
                                             const float* __restrict__ b2,
                                             float* __restrict__ out) {
    __shared__ float red[10 * 256];
    int b = blockIdx.x, tid = threadIdx.x;
    float p[10];
#pragma unroll
    for (int n = 0; n < 10; n++) p[n] = 0.f;
    for (int j = tid; j < 1024; j += 256) {
        float hv = g_hr[b * 1024 + j];
#pragma unroll
        for (int n = 0; n < 10; n++) p[n] += hv * w2[n * 1024 + j];
    }
#pragma unroll
    for (int n = 0; n < 10; n++) red[n * 256 + tid] = p[n];
    __syncthreads();
    for (int s = 128; s > 0; s >>= 1) {
        if (tid < s) {
#pragma unroll
            for (int n = 0; n < 10; n++) red[n * 256 + tid] += red[n * 256 + tid + s];
        }
        __syncthreads();
    }
    if (tid < 10) out[b * 10 + tid] = red[tid * 256] + b2[tid];
}

// =================================================================================
extern "C" void kernel_launch(void* const* d_in, const int* in_sizes, int n_in,
                              void* d_out, int out_size) {
    const float* x    = (const float*)d_in[0];
    const int*   idx1 = (const int*)d_in[1];
    const int*   idx2 = (const int*)d_in[2];
    const float* w1a  = (const float*)d_in[3];
    const float* b1a  = (const float*)d_in[4];
    const float* w1b  = (const float*)d_in[5];
    const float* b1b  = (const float*)d_in[6];
    const float* w1p  = (const float*)d_in[7];
    const float* b1p  = (const float*)d_in[8];
    const float* w2a  = (const float*)d_in[9];
    const float* b2a  = (const float*)d_in[10];
    const float* w2b  = (const float*)d_in[11];
    const float* b2b  = (const float*)d_in[12];
    const float* w2p  = (const float*)d_in[13];
    const float* b2p  = (const float*)d_in[14];
    const float* fc1w = (const float*)d_in[15];
    const float* fc1b = (const float*)d_in[16];
    const float* fc2w = (const float*)d_in[17];
    const float* fc2b = (const float*)d_in[18];
    float* out = (float*)d_out;

    const int smem_conv2 = (64 * 256 + 576 * 16) * 4;
    const int smem_knn2  = (64 * 68 + 576 * 16) * 4;
    const int smem_fc1t  = 81920;
    cudaFuncSetAttribute(k_l2_conv, cudaFuncAttributeMaxDynamicSharedMemorySize, smem_conv2);
    cudaFuncSetAttribute(k_l2_knn,  cudaFuncAttributeMaxDynamicSharedMemorySize, smem_knn2);
    cudaFuncSetAttribute(k_fc1t,    cudaFuncAttributeMaxDynamicSharedMemorySize, smem_fc1t);

    k_repack<<<72, 256>>>(w1a, w1b, w2a, w2b);
    k_l1_conv<<<BATCH, 256>>>(x, b1a);
    k_l1_knn<<<BATCH, 256>>>(x, idx1, b1b);
    k_l1_pw<<<BATCH, 256>>>(w1p, b1p);
    k_l2_conv<<<dim3(BATCH, 2), 256, smem_conv2>>>(b2a);
    k_l2_knn<<<dim3(BATCH, 2), 256, smem_knn2>>>(idx2, b2b);
    k_l2_pw<<<BATCH, 256>>>(w2p, b2p);
    k_cvt_a<<<8192, 256>>>();
    k_fc1t<<<dim3(16, 1, 8), 256, smem_fc1t>>>(fc1w);
    k_fc1_finish<<<1024, 256>>>(fc1b);
    k_fc2<<<BATCH, 256>>>(fc2w, fc2b, out);
}

// round 6
// speedup vs baseline: 1.7339x; 1.0257x over previous
#include <cuda_runtime.h>
#include <cuda_bf16.h>

typedef unsigned long long ull;
constexpr int BATCH = 256;

// ---------------- scratch (device globals) ----------------
__device__ __align__(16) float g_out1[BATCH * 64 * 256];
__device__ __align__(16) float g_cat2[BATCH * 64 * 256];
__device__ __align__(16) float g_fc1p[8 * BATCH * 1024];
__device__ __align__(16) float g_r1a[1728];
__device__ __align__(16) float g_r1b[1728];
__device__ __align__(16) float g_r2a[18432];
__device__ __align__(16) float g_r2b[18432];
__device__ __align__(16) __nv_bfloat16 g_ahi[BATCH * 32768];
__device__ __align__(16) __nv_bfloat16 g_alo[BATCH * 32768];

// ---------------- f32x2 helpers ----------------
__device__ __forceinline__ ull pack2(float lo, float hi) {
    ull r;
    asm("mov.b64 %0, {%1, %2};" : "=l"(r) : "r"(__float_as_uint(lo)), "r"(__float_as_uint(hi)));
    return r;
}
__device__ __forceinline__ ull packd(float s) { return pack2(s, s); }
__device__ __forceinline__ void fma2(ull& d, ull a, ull b) {
    asm("fma.rn.f32x2 %0, %1, %2, %3;" : "=l"(d) : "l"(a), "l"(b), "l"(d));
}
__device__ __forceinline__ float2 unpk(ull v) {
    unsigned lo, hi;
    asm("mov.b64 {%0, %1}, %2;" : "=r"(lo), "=r"(hi) : "l"(v));
    float2 f; f.x = __uint_as_float(lo); f.y = __uint_as_float(hi);
    return f;
}

// ---------------- mma.sync helpers ----------------
__device__ __forceinline__ unsigned smem_u32(const void* p) {
    unsigned a;
    asm("{ .reg .u64 t; cvta.to.shared.u64 t, %1; cvt.u32.u64 %0, t; }" : "=r"(a) : "l"(p));
    return a;
}
__device__ __forceinline__ void ldsm4(unsigned& r0, unsigned& r1, unsigned& r2, unsigned& r3,
                                      unsigned addr) {
    asm volatile("ldmatrix.sync.aligned.m8n8.x4.shared.b16 {%0,%1,%2,%3}, [%4];"
                 : "=r"(r0), "=r"(r1), "=r"(r2), "=r"(r3) : "r"(addr));
}
__device__ __forceinline__ void mma16816(float* c, const unsigned* a, const unsigned* b) {
    asm volatile(
        "mma.sync.aligned.m16n8k16.row.col.f32.bf16.bf16.f32 "
        "{%0,%1,%2,%3},{%4,%5,%6,%7},{%8,%9},{%0,%1,%2,%3};"
        : "+f"(c[0]), "+f"(c[1]), "+f"(c[2]), "+f"(c[3])
        : "r"(a[0]), "r"(a[1]), "r"(a[2]), "r"(a[3]), "r"(b[0]), "r"(b[1]));
}
__device__ __forceinline__ void cpa16(unsigned dst, const void* src) {
    asm volatile("cp.async.cg.shared.global [%0], [%1], 16;" :: "r"(dst), "l"(src));
}
__device__ __forceinline__ void cpa_commit() { asm volatile("cp.async.commit_group;"); }
__device__ __forceinline__ void cpa_wait0() {
    asm volatile("cp.async.wait_group 0;" ::: "memory");
}
__device__ __forceinline__ void sts128(unsigned addr, uint4 v) {
    asm volatile("st.shared.v4.b32 [%0], {%1,%2,%3,%4};"
                 :: "r"(addr), "r"(v.x), "r"(v.y), "r"(v.z), "r"(v.w));
}
__device__ __forceinline__ unsigned pkbf(float a, float b) {
    __nv_bfloat16 ha = __float2bfloat16(a), hb = __float2bfloat16(b);
    return ((unsigned)__bfloat16_as_ushort(hb) << 16) | __bfloat16_as_ushort(ha);
}

// ---------------- weight repack ----------------
__global__ __launch_bounds__(256) void k_repack(const float* __restrict__ w1a,
                                                const float* __restrict__ w1b,
                                                const float* __restrict__ w2a,
                                                const float* __restrict__ w2b) {
    int i = blockIdx.x * 256 + threadIdx.x;
    if (i < 1728) {
        int oc = i / 108, rest = i % 108;
        g_r1a[rest * 16 + oc] = w1a[i];
        g_r1b[rest * 16 + oc] = w1b[i];
    }
    if (i < 18432) {
        int oc = i / 576, rest = i % 576;
        g_r2a[rest * 32 + oc] = w2a[i];
        g_r2b[rest * 32 + oc] = w2b[i];
    }
}

// ======================= Layer 1 FUSED: conv + knn + pw -> g_out1 ================
__global__ __launch_bounds__(256) void k_l1(const float* __restrict__ x,
                                            const int* __restrict__ idx,
                                            const float* __restrict__ b1a,
                                            const float* __restrict__ b1b,
                                            const float* __restrict__ wp,
                                            const float* __restrict__ bp) {
    __shared__ __align__(16) float xs[12 * 256];
    __shared__ __align__(16) float ss[12 * 64];
    __shared__ float sn[64];
    __shared__ __align__(16) float wsa[1728];
    __shared__ __align__(16) float wsb[1728];
    __shared__ __align__(16) float wsp[64 * 32];
    int b = blockIdx.x, tid = threadIdx.x;

    for (int i = tid; i < 12 * 256; i += 256) {
        int cu = i >> 8, t = i & 255;
        int h = t >> 4, w = t & 15;
        int c = cu >> 2, ii = (cu >> 1) & 1, jj = cu & 1;
        xs[i] = x[((b * 3 + c) * 32 + (2 * h + ii)) * 32 + 2 * w + jj];
    }
    for (int i = tid; i < 1728; i += 256) { wsa[i] = g_r1a[i]; wsb[i] = g_r1b[i]; }
    for (int i = tid; i < 64 * 32; i += 256) wsp[i] = wp[i];
    __syncthreads();
    // gather knn samples from xs
    for (int i = tid; i < 12 * 64; i += 256)
        ss[i] = xs[(i >> 6) * 256 + idx[i & 63]];
    __syncthreads();
    if (tid < 64) {
        float s = 0.f;
#pragma unroll
        for (int c = 0; c < 12; c++) { float v = ss[c * 64 + tid]; s += v * v; }
        sn[tid] = s;
    }
    __syncthreads();

    int t = tid, h = t >> 4, w = t & 15;

    // ---- conv branch ----
    ull acv[8];
#pragma unroll
    for (int o = 0; o < 8; o++) acv[o] = pack2(b1a[2 * o], b1a[2 * o + 1]);
    for (int c = 0; c < 12; c++) {
        float p[9];
#pragma unroll
        for (int dy = 0; dy < 3; dy++)
#pragma unroll
            for (int dx = 0; dx < 3; dx++) {
                int y = h + dy - 1, xq = w + dx - 1;
                p[dy * 3 + dx] = (y >= 0 && y < 16 && xq >= 0 && xq < 16)
                                     ? xs[c * 256 + y * 16 + xq] : 0.f;
            }
#pragma unroll
        for (int tap = 0; tap < 9; tap++) {
            ull s2 = packd(p[tap]);
            const longlong2* wv = (const longlong2*)&wsa[(c * 9 + tap) * 16];
#pragma unroll
            for (int q = 0; q < 4; q++) {
                longlong2 w4 = wv[q];
                fma2(acv[q * 2 + 0], s2, (ull)w4.x);
                fma2(acv[q * 2 + 1], s2, (ull)w4.y);
            }
        }
    }

    // ---- knn branch ----
    float xr[12]; float xn = 0.f;
#pragma unroll
    for (int c = 0; c < 12; c++) { float v = xs[c * 256 + t]; xr[c] = v; xn += v * v; }

    float bd[9]; int bi[9];
#pragma unroll
    for (int k = 0; k < 9; k++) { bd[k] = 3.0e38f; bi[k] = 0; }
    for (int n = 0; n < 64; n++) {
        float dot = 0.f;
#pragma unroll
        for (int c = 0; c < 12; c++) dot += xr[c] * ss[c * 64 + n];
        float d = xn + sn[n] - 2.f * dot;
        if (d < bd[8]) {
            bool placed = false;
#pragma unroll
            for (int j = 8; j > 0; --j) {
                if (!placed) {
                    if (d < bd[j - 1]) { bd[j] = bd[j - 1]; bi[j] = bi[j - 1]; }
                    else { bd[j] = d; bi[j] = n; placed = true; }
                }
            }
            if (!placed) { bd[0] = d; bi[0] = n; }
        }
    }

    ull akn[8];
#pragma unroll
    for (int o = 0; o < 8; o++) akn[o] = pack2(b1b[2 * o], b1b[2 * o + 1]);
#pragma unroll
    for (int c = 0; c < 12; c++) {
#pragma unroll
        for (int k = 0; k < 9; k++) {
            ull s2 = packd(ss[c * 64 + bi[k]]);
            const longlong2* wv = (const longlong2*)&wsb[(c * 9 + k) * 16];
#pragma unroll
            for (int q = 0; q < 4; q++) {
                longlong2 w4 = wv[q];
                fma2(akn[q * 2 + 0], s2, (ull)w4.x);
                fma2(akn[q * 2 + 1], s2, (ull)w4.y);
            }
        }
    }

    // ---- relu + pointwise (32 -> 64) ----
    ull xv[16];
#pragma unroll
    for (int o = 0; o < 8; o++) {
        float2 v = unpk(acv[o]);
        xv[o] = pack2(fmaxf(v.x, 0.f), fmaxf(v.y, 0.f));
        float2 u = unpk(akn[o]);
        xv[8 + o] = pack2(fmaxf(u.x, 0.f), fmaxf(u.y, 0.f));
    }
    for (int oc = 0; oc < 64; oc++) {
        ull a2 = 0ull;
        const longlong2* wv = (const longlong2*)&wsp[oc * 32];
#pragma unroll
        for (int q = 0; q < 8; q++) {
            longlong2 w4 = wv[q];
            fma2(a2, xv[q * 2 + 0], (ull)w4.x);
            fma2(a2, xv[q * 2 + 1], (ull)w4.y);
        }
        float2 v = unpk(a2);
        g_out1[(b * 64 + oc) * 256 + tid] = v.x + v.y + bp[oc];
    }
}

// ======================= Layer 2: 3x3 conv (64 -> 32), oc-split x2 ==============
__global__ __launch_bounds__(256) void k_l2_conv(const float* __restrict__ ba) {
    extern __shared__ __align__(16) float sm[];
    float* xs = sm;
    float* wsh = sm + 64 * 256;
    int b = blockIdx.x, oc0 = blockIdx.y * 16, tid = threadIdx.x;
    for (int i = tid; i < 64 * 256; i += 256) xs[i] = g_out1[b * 64 * 256 + i];
    for (int i = tid; i < 576 * 16; i += 256) {
        int row = i >> 4, o = i & 15;
        wsh[i] = g_r2a[row * 32 + oc0 + o];
    }
    __syncthreads();

    int t = tid, h = t >> 4, w = t & 15;
    ull acc[8];
#pragma unroll
    for (int o = 0; o < 8; o++) acc[o] = pack2(ba[oc0 + 2 * o], ba[oc0 + 2 * o + 1]);
    for (int c = 0; c < 64; c++) {
        float p[9];
#pragma unroll
        for (int dy = 0; dy < 3; dy++)
#pragma unroll
            for (int dx = 0; dx < 3; dx++) {
                int y = h + dy - 1, xq = w + dx - 1;
                p[dy * 3 + dx] = (y >= 0 && y < 16 && xq >= 0 && xq < 16)
                                     ? xs[c * 256 + y * 16 + xq] : 0.f;
            }
#pragma unroll
        for (int tap = 0; tap < 9; tap++) {
            ull s2 = packd(p[tap]);
            const longlong2* wv = (const longlong2*)&wsh[(c * 9 + tap) * 16];
#pragma unroll
            for (int q = 0; q < 4; q++) {
                longlong2 w4 = wv[q];
                fma2(acc[q * 2 + 0], s2, (ull)w4.x);
                fma2(acc[q * 2 + 1], s2, (ull)w4.y);
            }
        }
    }
#pragma unroll
    for (int o = 0; o < 8; o++) {
        float2 v = unpk(acc[o]);
        g_cat2[((b * 64 + oc0 + 2 * o) * 256) + t] = fmaxf(v.x, 0.f);
        g_cat2[((b * 64 + oc0 + 2 * o + 1) * 256) + t] = fmaxf(v.y, 0.f);
    }
}

// ======================= Layer 2: kNN branch, oc-split x2 =======================
__global__ __launch_bounds__(256) void k_l2_knn(const int* __restrict__ idx,
                                                const float* __restrict__ bb) {
    extern __shared__ __align__(16) float sm[];
    float* ss = sm;
    float* wsh = sm + 64 * 68;
    __shared__ float sn[64];
    int b = blockIdx.x, oc0 = blockIdx.y * 16, tid = threadIdx.x;

    for (int i = tid; i < 64 * 64; i += 256) {
        int n = i >> 6, c = i & 63;
        ss[n * 68 + c] = g_out1[(b * 64 + c) * 256 + idx[n]];
    }
    for (int i = tid; i < 576 * 16; i += 256) {
        int row = i >> 4, o = i & 15;
        wsh[i] = g_r2b[row * 32 + oc0 + o];
    }
    __syncthreads();
    if (tid < 64) {
        float s = 0.f;
        for (int c = 0; c < 64; c++) { float v = ss[tid * 68 + c]; s += v * v; }
        sn[tid] = s;
    }
    __syncthreads();

    int t = tid;
    ull xr2[32]; float xn = 0.f;
#pragma unroll
    for (int c2 = 0; c2 < 32; c2++) {
        float f0 = g_out1[(b * 64 + 2 * c2) * 256 + t];
        float f1 = g_out1[(b * 64 + 2 * c2 + 1) * 256 + t];
        xn += f0 * f0 + f1 * f1;
        xr2[c2] = pack2(f0, f1);
    }

    float bd[9]; int bi[9];
#pragma unroll
    for (int k = 0; k < 9; k++) { bd[k] = 3.0e38f; bi[k] = 0; }
    for (int n = 0; n < 64; n++) {
        const longlong2* sp = (const longlong2*)&ss[n * 68];
        ull d2 = 0ull;
#pragma unroll
        for (int j = 0; j < 16; j++) {
            longlong2 s4 = sp[j];
            fma2(d2, xr2[2 * j + 0], (ull)s4.x);
            fma2(d2, xr2[2 * j + 1], (ull)s4.y);
        }
        float2 dv = unpk(d2);
        float d = xn + sn[n] - 2.f * (dv.x + dv.y);
        if (d < bd[8]) {
            bool placed = false;
#pragma unroll
            for (int j = 8; j > 0; --j) {
                if (!placed) {
                    if (d < bd[j - 1]) { bd[j] = bd[j - 1]; bi[j] = bi[j - 1]; }
                    else { bd[j] = d; bi[j] = n; placed = true; }
                }
            }
            if (!placed) { bd[0] = d; bi[0] = n; }
        }
    }

    ull acc[8];
#pragma unroll
    for (int o = 0; o < 8; o++) acc[o] = pack2(bb[oc0 + 2 * o], bb[oc0 + 2 * o + 1]);
    for (int c = 0; c < 64; c++) {
        float sg[9];
#pragma unroll
        for (int k = 0; k < 9; k++) sg[k] = ss[bi[k] * 68 + c];
#pragma unroll
        for (int k = 0; k < 9; k++) {
            ull s2 = packd(sg[k]);
            const longlong2* wv = (const longlong2*)&wsh[(c * 9 + k) * 16];
#pragma unroll
            for (int q = 0; q < 4; q++) {
                longlong2 w4 = wv[q];
                fma2(acc[q * 2 + 0], s2, (ull)w4.x);
                fma2(acc[q * 2 + 1], s2, (ull)w4.y);
            }
        }
    }
#pragma unroll
    for (int o = 0; o < 8; o++) {
        float2 v = unpk(acc[o]);
        g_cat2[((b * 64 + 32 + oc0 + 2 * o) * 256) + t] = fmaxf(v.x, 0.f);
        g_cat2[((b * 64 + 33 + oc0 + 2 * o) * 256) + t] = fmaxf(v.y, 0.f);
    }
}

// ======== Layer 2: 1x1 conv (64->128) + shuffle/flatten + bf16 hi/lo split ======
__global__ __launch_bounds__(256) void k_l2_pw(const float* __restrict__ wp,
                                               const float* __restrict__ bp) {
    __shared__ __align__(16) float ws[128 * 64];
    int b = blockIdx.x, tid = threadIdx.x;
    for (int i = tid; i < 128 * 64; i += 256) ws[i] = wp[i];
    __syncthreads();
    ull xv[32];
#pragma unroll
    for (int c2 = 0; c2 < 32; c2++) {
        float f0 = g_cat2[(b * 64 + 2 * c2) * 256 + tid];
        float f1 = g_cat2[(b * 64 + 2 * c2 + 1) * 256 + tid];
        xv[c2] = pack2(f0, f1);
    }
    int h = tid >> 4, w = tid & 15;
    for (int oc = 0; oc < 128; oc++) {
        ull a2 = 0ull;
        const longlong2* wv = (const longlong2*)&ws[oc * 64];
#pragma unroll
        for (int q = 0; q < 16; q++) {
            longlong2 w4 = wv[q];
            fma2(a2, xv[q * 2 + 0], (ull)w4.x);
            fma2(a2, xv[q * 2 + 1], (ull)w4.y);
        }
        float2 v = unpk(a2);
        float acc = v.x + v.y + bp[oc];
        int cp = oc >> 2, ii = (oc >> 1) & 1, jj = oc & 1;
        long pos = (long)b * 32768 + cp * 1024 + (2 * h + ii) * 32 + 2 * w + jj;
        __nv_bfloat16 hi = __float2bfloat16(acc);
        g_ahi[pos] = hi;
        g_alo[pos] = __float2bfloat16(acc - __bfloat162float(hi));
    }
}

// ======================= fc1: bf16 split GEMM via mma.sync ======================
__global__ __launch_bounds__(256) void k_fc1t(const float* __restrict__ W) {
    extern __shared__ __align__(16) char smem[];
    unsigned sbase = smem_u32(smem);
    int tid = threadIdx.x, lane = tid & 31, warp = tid >> 5;
    int n0 = blockIdx.x * 64, sk = blockIdx.z;
    long kbase = (long)sk * 4096;

    int m_base = (warp & 3) * 64;
    int n_base = (warp >> 2) * 32;

    int aq[4], ac[4];
#pragma unroll
    for (int j = 0; j < 4; j++) { int q = tid + j * 256; aq[j] = q >> 2; ac[j] = q & 3; }
    int wr = tid >> 2, wc = tid & 3;
    unsigned wsw = (unsigned)((wc ^ ((wr >> 1) & 3)) << 4);

    float acc[4][4][4];
#pragma unroll
    for (int i = 0; i < 4; i++)
#pragma unroll
        for (int j = 0; j < 4; j++)
#pragma unroll
            for (int q = 0; q < 4; q++) acc[i][j][q] = 0.f;

    const float* wgp = W + (long)(n0 + wr) * 32768 + kbase + wc * 8;

    float4 w0a = *(const float4*)(wgp);
    float4 w0b = *(const float4*)(wgp + 4);
#pragma unroll
    for (int j = 0; j < 4; j++) {
        int r = aq[j], c = ac[j];
        unsigned sw = (unsigned)(r * 64 + ((c ^ ((r >> 1) & 3)) << 4));
        cpa16(sbase + sw, g_ahi + (long)r * 32768 + kbase + c * 8);
        cpa16(sbase + 16384 + sw, g_alo + (long)r * 32768 + kbase + c * 8);
    }
    cpa_commit();
    {
        uint4 hi, lo;
        hi.x = pkbf(w0a.x, w0a.y); hi.y = pkbf(w0a.z, w0a.w);
        hi.z = pkbf(w0b.x, w0b.y); hi.w = pkbf(w0b.z, w0b.w);
        __nv_bfloat16 t0 = __float2bfloat16(w0a.x), t1 = __float2bfloat16(w0a.y);
        __nv_bfloat16 t2 = __float2bfloat16(w0a.z), t3 = __float2bfloat16(w0a.w);
        __nv_bfloat16 t4 = __float2bfloat16(w0b.x), t5 = __float2bfloat16(w0b.y);
        __nv_bfloat16 t6 = __float2bfloat16(w0b.z), t7 = __float2bfloat16(w0b.w);
        lo.x = pkbf(w0a.x - __bfloat162float(t0), w0a.y - __bfloat162float(t1));
        lo.y = pkbf(w0a.z - __bfloat162float(t2), w0a.w - __bfloat162float(t3));
        lo.z = pkbf(w0b.x - __bfloat162float(t4), w0b.y - __bfloat162float(t5));
        lo.w = pkbf(w0b.z - __bfloat162float(t6), w0b.w - __bfloat162float(t7));
        sts128(sbase + 32768 + wr * 64 + wsw, hi);
        sts128(sbase + 36864 + wr * 64 + wsw, lo);
    }

    int ri = lane & 7, mat = lane >> 3;

    for (int it = 0; it < 128; it++) {
        int st = it & 1;
        unsigned stb = sbase + st * 40960u;
        cpa_wait0();
        __syncthreads();

        float4 wna, wnb;
        if (it < 127) {
            long ko = kbase + (it + 1) * 32;
            wna = *(const float4*)(wgp + (it + 1) * 32);
            wnb = *(const float4*)(wgp + (it + 1) * 32 + 4);
            unsigned nb = sbase + (st ^ 1) * 40960u;
#pragma unroll
            for (int j = 0; j < 4; j++) {
                int r = aq[j], c = ac[j];
                unsigned sw = (unsigned)(r * 64 + ((c ^ ((r >> 1) & 3)) << 4));
                cpa16(nb + sw, g_ahi + (long)r * 32768 + ko + c * 8);
                cpa16(nb + 16384 + sw, g_alo + (long)r * 32768 + ko + c * 8);
            }
            cpa_commit();
        }

#pragma unroll
        for (int k16 = 0; k16 < 2; k16++) {
            unsigned ah[4][4], al[4][4], bh[4][2], bl[4][2];
#pragma unroll
            for (int mi = 0; mi < 4; mi++) {
                int row = m_base + mi * 16 + ri + ((mat & 1) << 3);
                int c = k16 * 2 + (mat >> 1);
                unsigned ad = stb + row * 64 + ((c ^ ((row >> 1) & 3)) << 4);
                ldsm4(ah[mi][0], ah[mi][1], ah[mi][2], ah[mi][3], ad);
                ldsm4(al[mi][0], al[mi][1], al[mi][2], al[mi][3], ad + 16384);
            }
#pragma unroll
            for (int ng = 0; ng < 2; ng++) {
                int row = n_base + ng * 16 + ri + ((mat >> 1) << 3);
                int c = k16 * 2 + (mat & 1);
                unsigned bd = stb + 32768 + row * 64 + ((c ^ ((row >> 1) & 3)) << 4);
                unsigned r0, r1, r2, r3;
                ldsm4(r0, r1, r2, r3, bd);
                bh[2 * ng][0] = r0; bh[2 * ng][1] = r1;
                bh[2 * ng + 1][0] = r2; bh[2 * ng + 1][1] = r3;
                ldsm4(r0, r1, r2, r3, bd + 4096);
                bl[2 * ng][0] = r0; bl[2 * ng][1] = r1;
                bl[2 * ng + 1][0] = r2; bl[2 * ng + 1][1] = r3;
            }
#pragma unroll
            for (int mi = 0; mi < 4; mi++)
#pragma unroll
                for (int ni = 0; ni < 4; ni++) {
                    mma16816(acc[mi][ni], ah[mi], bh[ni]);
                    mma16816(acc[mi][ni], ah[mi], bl[ni]);
                    mma16816(acc[mi][ni], al[mi], bh[ni]);
                }
        }

        if (it < 127) {
            uint4 hi, lo;
            hi.x = pkbf(wna.x, wna.y); hi.y = pkbf(wna.z, wna.w);
            hi.z = pkbf(wnb.x, wnb.y); hi.w = pkbf(wnb.z, wnb.w);
            __nv_bfloat16 t0 = __float2bfloat16(wna.x), t1 = __float2bfloat16(wna.y);
            __nv_bfloat16 t2 = __float2bfloat16(wna.z), t3 = __float2bfloat16(wna.w);
            __nv_bfloat16 t4 = __float2bfloat16(wnb.x), t5 = __float2bfloat16(wnb.y);
            __nv_bfloat16 t6 = __float2bfloat16(wnb.z), t7 = __float2bfloat16(wnb.w);
            lo.x = pkbf(wna.x - __bfloat162float(t0), wna.y - __bfloat162float(t1));
            lo.y = pkbf(wna.z - __bfloat162float(t2), wna.w - __bfloat162float(t3));
            lo.z = pkbf(wnb.x - __bfloat162float(t4), wnb.y - __bfloat162float(t5));
            lo.w = pkbf(wnb.z - __bfloat162float(t6), wnb.w - __bfloat162float(t7));
            unsigned nb = sbase + (st ^ 1) * 40960u;
            sts128(nb + 32768 + wr * 64 + wsw, hi);
            sts128(nb + 36864 + wr * 64 + wsw, lo);
        }
    }

    float* slab = g_fc1p + (long)sk * BATCH * 1024;
#pragma unroll
    for (int mi = 0; mi < 4; mi++)
#pragma unroll
        for (int ni = 0; ni < 4; ni++) {
            int m = m_base + mi * 16 + (lane >> 2);
            int n = n0 + n_base + ni * 8 + (lane & 3) * 2;
            *(float2*)&slab[(long)m * 1024 + n] =
                make_float2(acc[mi][ni][0], acc[mi][ni][1]);
            *(float2*)&slab[(long)(m + 8) * 1024 + n] =
                make_float2(acc[mi][ni][2], acc[mi][ni][3]);
        }
}

// ======================= fc2 (fused slab-reduce + relu + fc2) ===================
__global__ __launch_bounds__(256) void k_fc2(const float* __restrict__ fc1b,
                                             const float* __restrict__ w2,
                                             const float* __restrict__ b2,
                                             float* __restrict__ out) {
    __shared__ __align__(16) float hs[1024];
    __shared__ float red[10 * 256];
    int b = blockIdx.x, tid = threadIdx.x;
    for (int j = tid; j < 1024; j += 256) {
        float s = 0.f;
#pragma unroll
        for (int q = 0; q < 8; q++) s += g_fc1p[(long)q * BATCH * 1024 + b * 1024 + j];
        hs[j] = fmaxf(s + fc1b[j], 0.f);
    }
    __syncthreads();
    float p[10];
#pragma unroll
    for (int n = 0; n < 10; n++) p[n] = 0.f;
    for (int j = tid; j < 1024; j += 256) {
        float hv = hs[j];
#pragma unroll
        for (int n = 0; n < 10; n++) p[n] += hv * w2[n * 1024 + j];
    }
#pragma unroll
    for (int n = 0; n < 10; n++) red[n * 256 + tid] = p[n];
    __syncthreads();
    for (int s = 128; s > 0; s >>= 1) {
        if (tid < s) {
#pragma unroll
            for (int n = 0; n < 10; n++) red[n * 256 + tid] += red[n * 256 + tid + s];
        }
        __syncthreads();
    }
    if (tid < 10) out[b * 10 + tid] = red[tid * 256] + b2[tid];
}

// =================================================================================
extern "C" void kernel_launch(void* const* d_in, const int* in_sizes, int n_in,
                              void* d_out, int out_size) {
    const float* x    = (const float*)d_in[0];
    const int*   idx1 = (const int*)d_in[1];
    const int*   idx2 = (const int*)d_in[2];
    const float* w1a  = (const float*)d_in[3];
    const float* b1a  = (const float*)d_in[4];
    const float* w1b  = (const float*)d_in[5];
    const float* b1b  = (const float*)d_in[6];
    const float* w1p  = (const float*)d_in[7];
    const float* b1p  = (const float*)d_in[8];
    const float* w2a  = (const float*)d_in[9];
    const float* b2a  = (const float*)d_in[10];
    const float* w2b  = (const float*)d_in[11];
    const float* b2b  = (const float*)d_in[12];
    const float* w2p  = (const float*)d_in[13];
    const float* b2p  = (const float*)d_in[14];
    const float* fc1w = (const float*)d_in[15];
    const float* fc1b = (const float*)d_in[16];
    const float* fc2w = (const float*)d_in[17];
    const float* fc2b = (const float*)d_in[18];
    float* out = (float*)d_out;

    const int smem_conv2 = (64 * 256 + 576 * 16) * 4;
    const int smem_knn2  = (64 * 68 + 576 * 16) * 4;
    const int smem_fc1t  = 81920;
    cudaFuncSetAttribute(k_l2_conv, cudaFuncAttributeMaxDynamicSharedMemorySize, smem_conv2);
    cudaFuncSetAttribute(k_l2_knn,  cudaFuncAttributeMaxDynamicSharedMemorySize, smem_knn2);
    cudaFuncSetAttribute(k_fc1t,    cudaFuncAttributeMaxDynamicSharedMemorySize, smem_fc1t);

    k_repack<<<72, 256>>>(w1a, w1b, w2a, w2b);
    k_l1<<<BATCH, 256>>>(x, idx1, b1a, b1b, w1p, b1p);
    k_l2_conv<<<dim3(BATCH, 2), 256, smem_conv2>>>(b2a);
    k_l2_knn<<<dim3(BATCH, 2), 256, smem_knn2>>>(idx2, b2b);
    k_l2_pw<<<BATCH, 256>>>(w2p, b2p);
    k_fc1t<<<dim3(16, 1, 8), 256, smem_fc1t>>>(fc1w);
    k_fc2<<<BATCH, 256>>>(fc1b, fc2w, fc2b, out);
}

// round 7
// speedup vs baseline: 2.1127x; 1.2185x over previous
#include <cuda_runtime.h>
#include <cuda_bf16.h>

typedef unsigned long long ull;
constexpr int BATCH = 256;

// ---------------- scratch (device globals) ----------------
__device__ __align__(16) float g_out1[BATCH * 64 * 256];
__device__ __align__(16) float g_cat2[BATCH * 64 * 256];
__device__ __align__(16) float g_fc1p[8 * BATCH * 1024];
__device__ __align__(16) float g_r1a[1728];
__device__ __align__(16) float g_r1b[1728];
__device__ __align__(16) float g_r2a[18432];
__device__ __align__(16) float g_r2b[18432];   // [k][c][oc] layout
__device__ __align__(16) __nv_bfloat16 g_ahi[BATCH * 32768];
__device__ __align__(16) __nv_bfloat16 g_alo[BATCH * 32768];

// ---------------- f32x2 helpers ----------------
__device__ __forceinline__ ull pack2(float lo, float hi) {
    ull r;
    asm("mov.b64 %0, {%1, %2};" : "=l"(r) : "r"(__float_as_uint(lo)), "r"(__float_as_uint(hi)));
    return r;
}
__device__ __forceinline__ ull packd(float s) { return pack2(s, s); }
__device__ __forceinline__ void fma2(ull& d, ull a, ull b) {
    asm("fma.rn.f32x2 %0, %1, %2, %3;" : "=l"(d) : "l"(a), "l"(b), "l"(d));
}
__device__ __forceinline__ float2 unpk(ull v) {
    unsigned lo, hi;
    asm("mov.b64 {%0, %1}, %2;" : "=r"(lo), "=r"(hi) : "l"(v));
    float2 f; f.x = __uint_as_float(lo); f.y = __uint_as_float(hi);
    return f;
}

// ---------------- mma.sync helpers ----------------
__device__ __forceinline__ unsigned smem_u32(const void* p) {
    unsigned a;
    asm("{ .reg .u64 t; cvta.to.shared.u64 t, %1; cvt.u32.u64 %0, t; }" : "=r"(a) : "l"(p));
    return a;
}
__device__ __forceinline__ void ldsm4(unsigned& r0, unsigned& r1, unsigned& r2, unsigned& r3,
                                      unsigned addr) {
    asm volatile("ldmatrix.sync.aligned.m8n8.x4.shared.b16 {%0,%1,%2,%3}, [%4];"
                 : "=r"(r0), "=r"(r1), "=r"(r2), "=r"(r3) : "r"(addr));
}
__device__ __forceinline__ void mma16816(float* c, const unsigned* a, const unsigned* b) {
    asm volatile(
        "mma.sync.aligned.m16n8k16.row.col.f32.bf16.bf16.f32 "
        "{%0,%1,%2,%3},{%4,%5,%6,%7},{%8,%9},{%0,%1,%2,%3};"
        : "+f"(c[0]), "+f"(c[1]), "+f"(c[2]), "+f"(c[3])
        : "r"(a[0]), "r"(a[1]), "r"(a[2]), "r"(a[3]), "r"(b[0]), "r"(b[1]));
}
__device__ __forceinline__ void cpa16(unsigned dst, const void* src) {
    asm volatile("cp.async.cg.shared.global [%0], [%1], 16;" :: "r"(dst), "l"(src));
}
__device__ __forceinline__ void cpa_commit() { asm volatile("cp.async.commit_group;"); }
__device__ __forceinline__ void cpa_wait0() {
    asm volatile("cp.async.wait_group 0;" ::: "memory");
}
__device__ __forceinline__ void sts128(unsigned addr, uint4 v) {
    asm volatile("st.shared.v4.b32 [%0], {%1,%2,%3,%4};"
                 :: "r"(addr), "r"(v.x), "r"(v.y), "r"(v.z), "r"(v.w));
}
__device__ __forceinline__ unsigned pkbf(float a, float b) {
    __nv_bfloat16 ha = __float2bfloat16(a), hb = __float2bfloat16(b);
    return ((unsigned)__bfloat16_as_ushort(hb) << 16) | __bfloat16_as_ushort(ha);
}

// ---------------- weight repack ----------------
__global__ __launch_bounds__(256) void k_repack(const float* __restrict__ w1a,
                                                const float* __restrict__ w1b,
                                                const float* __restrict__ w2a,
                                                const float* __restrict__ w2b) {
    int i = blockIdx.x * 256 + threadIdx.x;
    if (i < 1728) {
        int oc = i / 108, rest = i % 108;
        g_r1a[rest * 16 + oc] = w1a[i];
        g_r1b[rest * 16 + oc] = w1b[i];
    }
    if (i < 18432) {
        int oc = i / 576, rest = i % 576;
        g_r2a[rest * 32 + oc] = w2a[i];
        int c = rest / 9, k = rest % 9;
        g_r2b[(k * 64 + c) * 32 + oc] = w2b[i];   // [k][c][oc]
    }
}

// ======================= Layer 1 FUSED: conv + knn + pw -> g_out1 ================
__global__ __launch_bounds__(256) void k_l1(const float* __restrict__ x,
                                            const int* __restrict__ idx,
                                            const float* __restrict__ b1a,
                                            const float* __restrict__ b1b,
                                            const float* __restrict__ wp,
                                            const float* __restrict__ bp) {
    __shared__ __align__(16) float xs[12 * 256];
    __shared__ __align__(16) float ss[12 * 64];
    __shared__ float sn[64];
    __shared__ __align__(16) float wsa[1728];
    __shared__ __align__(16) float wsb[1728];
    __shared__ __align__(16) float wsp[64 * 32];
    int b = blockIdx.x, tid = threadIdx.x;

    for (int i = tid; i < 12 * 256; i += 256) {
        int cu = i >> 8, t = i & 255;
        int h = t >> 4, w = t & 15;
        int c = cu >> 2, ii = (cu >> 1) & 1, jj = cu & 1;
        xs[i] = x[((b * 3 + c) * 32 + (2 * h + ii)) * 32 + 2 * w + jj];
    }
    for (int i = tid; i < 1728; i += 256) { wsa[i] = g_r1a[i]; wsb[i] = g_r1b[i]; }
    for (int i = tid; i < 64 * 32; i += 256) wsp[i] = wp[i];
    __syncthreads();
    for (int i = tid; i < 12 * 64; i += 256)
        ss[i] = xs[(i >> 6) * 256 + idx[i & 63]];
    __syncthreads();
    if (tid < 64) {
        float s = 0.f;
#pragma unroll
        for (int c = 0; c < 12; c++) { float v = ss[c * 64 + tid]; s += v * v; }
        sn[tid] = s;
    }
    __syncthreads();

    int t = tid, h = t >> 4, w = t & 15;

    ull acv[8];
#pragma unroll
    for (int o = 0; o < 8; o++) acv[o] = pack2(b1a[2 * o], b1a[2 * o + 1]);
    for (int c = 0; c < 12; c++) {
        float p[9];
#pragma unroll
        for (int dy = 0; dy < 3; dy++)
#pragma unroll
            for (int dx = 0; dx < 3; dx++) {
                int y = h + dy - 1, xq = w + dx - 1;
                p[dy * 3 + dx] = (y >= 0 && y < 16 && xq >= 0 && xq < 16)
                                     ? xs[c * 256 + y * 16 + xq] : 0.f;
            }
#pragma unroll
        for (int tap = 0; tap < 9; tap++) {
            ull s2 = packd(p[tap]);
            const longlong2* wv = (const longlong2*)&wsa[(c * 9 + tap) * 16];
#pragma unroll
            for (int q = 0; q < 4; q++) {
                longlong2 w4 = wv[q];
                fma2(acv[q * 2 + 0], s2, (ull)w4.x);
                fma2(acv[q * 2 + 1], s2, (ull)w4.y);
            }
        }
    }

    float xr[12]; float xn = 0.f;
#pragma unroll
    for (int c = 0; c < 12; c++) { float v = xs[c * 256 + t]; xr[c] = v; xn += v * v; }

    float bd[9]; int bi[9];
#pragma unroll
    for (int k = 0; k < 9; k++) { bd[k] = 3.0e38f; bi[k] = 0; }
    for (int n = 0; n < 64; n++) {
        float dot = 0.f;
#pragma unroll
        for (int c = 0; c < 12; c++) dot += xr[c] * ss[c * 64 + n];
        float d = xn + sn[n] - 2.f * dot;
        if (d < bd[8]) {
            bool placed = false;
#pragma unroll
            for (int j = 8; j > 0; --j) {
                if (!placed) {
                    if (d < bd[j - 1]) { bd[j] = bd[j - 1]; bi[j] = bi[j - 1]; }
                    else { bd[j] = d; bi[j] = n; placed = true; }
                }
            }
            if (!placed) { bd[0] = d; bi[0] = n; }
        }
    }

    ull akn[8];
#pragma unroll
    for (int o = 0; o < 8; o++) akn[o] = pack2(b1b[2 * o], b1b[2 * o + 1]);
#pragma unroll
    for (int c = 0; c < 12; c++) {
#pragma unroll
        for (int k = 0; k < 9; k++) {
            ull s2 = packd(ss[c * 64 + bi[k]]);
            const longlong2* wv = (const longlong2*)&wsb[(c * 9 + k) * 16];
#pragma unroll
            for (int q = 0; q < 4; q++) {
                longlong2 w4 = wv[q];
                fma2(akn[q * 2 + 0], s2, (ull)w4.x);
                fma2(akn[q * 2 + 1], s2, (ull)w4.y);
            }
        }
    }

    ull xv[16];
#pragma unroll
    for (int o = 0; o < 8; o++) {
        float2 v = unpk(acv[o]);
        xv[o] = pack2(fmaxf(v.x, 0.f), fmaxf(v.y, 0.f));
        float2 u = unpk(akn[o]);
        xv[8 + o] = pack2(fmaxf(u.x, 0.f), fmaxf(u.y, 0.f));
    }
    for (int oc = 0; oc < 64; oc++) {
        ull a2 = 0ull;
        const longlong2* wv = (const longlong2*)&wsp[oc * 32];
#pragma unroll
        for (int q = 0; q < 8; q++) {
            longlong2 w4 = wv[q];
            fma2(a2, xv[q * 2 + 0], (ull)w4.x);
            fma2(a2, xv[q * 2 + 1], (ull)w4.y);
        }
        float2 v = unpk(a2);
        g_out1[(b * 64 + oc) * 256 + tid] = v.x + v.y + bp[oc];
    }
}

// ======================= Layer 2: 3x3 conv (64 -> 32), oc-split x2 ==============
__global__ __launch_bounds__(256) void k_l2_conv(const float* __restrict__ ba) {
    extern __shared__ __align__(16) float sm[];
    float* xs = sm;
    float* wsh = sm + 64 * 256;
    int b = blockIdx.x, oc0 = blockIdx.y * 16, tid = threadIdx.x;
    for (int i = tid; i < 64 * 256; i += 256) xs[i] = g_out1[b * 64 * 256 + i];
    for (int i = tid; i < 576 * 16; i += 256) {
        int row = i >> 4, o = i & 15;
        wsh[i] = g_r2a[row * 32 + oc0 + o];
    }
    __syncthreads();

    int t = tid, h = t >> 4, w = t & 15;
    ull acc[8];
#pragma unroll
    for (int o = 0; o < 8; o++) acc[o] = pack2(ba[oc0 + 2 * o], ba[oc0 + 2 * o + 1]);
    for (int c = 0; c < 64; c++) {
        float p[9];
#pragma unroll
        for (int dy = 0; dy < 3; dy++)
#pragma unroll
            for (int dx = 0; dx < 3; dx++) {
                int y = h + dy - 1, xq = w + dx - 1;
                p[dy * 3 + dx] = (y >= 0 && y < 16 && xq >= 0 && xq < 16)
                                     ? xs[c * 256 + y * 16 + xq] : 0.f;
            }
#pragma unroll
        for (int tap = 0; tap < 9; tap++) {
            ull s2 = packd(p[tap]);
            const longlong2* wv = (const longlong2*)&wsh[(c * 9 + tap) * 16];
#pragma unroll
            for (int q = 0; q < 4; q++) {
                longlong2 w4 = wv[q];
                fma2(acc[q * 2 + 0], s2, (ull)w4.x);
                fma2(acc[q * 2 + 1], s2, (ull)w4.y);
            }
        }
    }
#pragma unroll
    for (int o = 0; o < 8; o++) {
        float2 v = unpk(acc[o]);
        g_cat2[((b * 64 + oc0 + 2 * o) * 256) + t] = fmaxf(v.x, 0.f);
        g_cat2[((b * 64 + oc0 + 2 * o + 1) * 256) + t] = fmaxf(v.y, 0.f);
    }
}

// ======================= Layer 2: kNN branch — M-table restructure ==============
// One block per image, 288 threads. smem: ss[64n][66], M[9k*64n][33], sn[64].
__global__ __launch_bounds__(288) void k_l2_knn(const int* __restrict__ idx,
                                                const float* __restrict__ bb) {
    extern __shared__ __align__(16) float sm[];
    float* ss = sm;              // [n][c], row stride 66 (4224 floats)
    float* Mt = sm + 4224;       // [(k*64+n)][o], row stride 33 (19008 floats)
    float* sn = Mt + 19008;      // 64
    int b = blockIdx.x, tid = threadIdx.x, lane = tid & 31, wid = tid >> 5;

    for (int i = tid; i < 4096; i += 288) {
        int n = i & 63, c = i >> 6;
        ss[n * 66 + c] = g_out1[(b * 64 + c) * 256 + idx[n]];
    }
    __syncthreads();
    if (tid < 64) {
        float s = 0.f;
#pragma unroll 16
        for (int c = 0; c < 64; c++) { float v = ss[tid * 66 + c]; s += v * v; }
        sn[tid] = s;
    }

    // ---- M-GEMM: warp wid computes M[k=wid][n in {lane, lane+32}][0..31] ----
    {
        int k = wid;
        ull a0[16], a1[16];
#pragma unroll
        for (int j = 0; j < 16; j++) { a0[j] = 0ull; a1[j] = 0ull; }
        const longlong2* wrow = (const longlong2*)(g_r2b + (k * 64) * 32);
        int n0 = lane, n1 = lane + 32;
        for (int c = 0; c < 64; c++) {
            ull s0 = packd(ss[n0 * 66 + c]);
            ull s1 = packd(ss[n1 * 66 + c]);
#pragma unroll
            for (int q = 0; q < 8; q++) {
                longlong2 w4 = wrow[c * 8 + q];   // warp-uniform -> L1 broadcast
                fma2(a0[q * 2 + 0], s0, (ull)w4.x);
                fma2(a0[q * 2 + 1], s0, (ull)w4.y);
                fma2(a1[q * 2 + 0], s1, (ull)w4.x);
                fma2(a1[q * 2 + 1], s1, (ull)w4.y);
            }
        }
        float* m0 = &Mt[(k * 64 + n0) * 33];
        float* m1 = &Mt[(k * 64 + n1) * 33];
#pragma unroll
        for (int j = 0; j < 16; j++) {
            float2 v0 = unpk(a0[j]); m0[2 * j] = v0.x; m0[2 * j + 1] = v0.y;
            float2 v1 = unpk(a1[j]); m1[2 * j] = v1.x; m1[2 * j + 1] = v1.y;
        }
    }
    __syncthreads();

    if (tid < 256) {
        int t = tid;
        ull xr2[32]; float xn = 0.f;
#pragma unroll
        for (int c2 = 0; c2 < 32; c2++) {
            float f0 = g_out1[(b * 64 + 2 * c2) * 256 + t];
            float f1 = g_out1[(b * 64 + 2 * c2 + 1) * 256 + t];
            xn += f0 * f0 + f1 * f1;
            xr2[c2] = pack2(f0, f1);
        }

        float bd[9]; int bi[9];
#pragma unroll
        for (int k = 0; k < 9; k++) { bd[k] = 3.0e38f; bi[k] = 0; }
        for (int n = 0; n < 64; n++) {
            const ull* sp = (const ull*)&ss[n * 66];
            ull d2 = 0ull;
#pragma unroll
            for (int j = 0; j < 32; j++) fma2(d2, xr2[j], sp[j]);
            float2 dv = unpk(d2);
            float d = xn + sn[n] - 2.f * (dv.x + dv.y);
            if (d < bd[8]) {
                bool placed = false;
#pragma unroll
                for (int j = 8; j > 0; --j) {
                    if (!placed) {
                        if (d < bd[j - 1]) { bd[j] = bd[j - 1]; bi[j] = bi[j - 1]; }
                        else { bd[j] = d; bi[j] = n; placed = true; }
                    }
                }
                if (!placed) { bd[0] = d; bi[0] = n; }
            }
        }

        float acc[32];
#pragma unroll
        for (int o = 0; o < 32; o++) acc[o] = bb[o];
#pragma unroll
        for (int k = 0; k < 9; k++) {
            const float* mrow = &Mt[(k * 64 + bi[k]) * 33];
#pragma unroll
            for (int o = 0; o < 32; o++) acc[o] += mrow[o];
        }
#pragma unroll
        for (int o = 0; o < 32; o++)
            g_cat2[((b * 64 + 32 + o) * 256) + t] = fmaxf(acc[o], 0.f);
    }
}

// ======== Layer 2: 1x1 conv (64->128) + shuffle/flatten + bf16 hi/lo split ======
__global__ __launch_bounds__(256) void k_l2_pw(const float* __restrict__ wp,
                                               const float* __restrict__ bp) {
    __shared__ __align__(16) float ws[128 * 64];
    int b = blockIdx.x, tid = threadIdx.x;
    for (int i = tid; i < 128 * 64; i += 256) ws[i] = wp[i];
    __syncthreads();
    ull xv[32];
#pragma unroll
    for (int c2 = 0; c2 < 32; c2++) {
        float f0 = g_cat2[(b * 64 + 2 * c2) * 256 + tid];
        float f1 = g_cat2[(b * 64 + 2 * c2 + 1) * 256 + tid];
        xv[c2] = pack2(f0, f1);
    }
    int h = tid >> 4, w = tid & 15;
    for (int oc = 0; oc < 128; oc++) {
        ull a2 = 0ull;
        const longlong2* wv = (const longlong2*)&ws[oc * 64];
#pragma unroll
        for (int q = 0; q < 16; q++) {
            longlong2 w4 = wv[q];
            fma2(a2, xv[q * 2 + 0], (ull)w4.x);
            fma2(a2, xv[q * 2 + 1], (ull)w4.y);
        }
        float2 v = unpk(a2);
        float acc = v.x + v.y + bp[oc];
        int cp = oc >> 2, ii = (oc >> 1) & 1, jj = oc & 1;
        long pos = (long)b * 32768 + cp * 1024 + (2 * h + ii) * 32 + 2 * w + jj;
        __nv_bfloat16 hi = __float2bfloat16(acc);
        g_ahi[pos] = hi;
        g_alo[pos] = __float2bfloat16(acc - __bfloat162float(hi));
    }
}

// ======================= fc1: bf16 split GEMM via mma.sync ======================
__global__ __launch_bounds__(256) void k_fc1t(const float* __restrict__ W) {
    extern __shared__ __align__(16) char smem[];
    unsigned sbase = smem_u32(smem);
    int tid = threadIdx.x, lane = tid & 31, warp = tid >> 5;
    int n0 = blockIdx.x * 64, sk = blockIdx.z;
    long kbase = (long)sk * 4096;

    int m_base = (warp & 3) * 64;
    int n_base = (warp >> 2) * 32;

    int aq[4], ac[4];
#pragma unroll
    for (int j = 0; j < 4; j++) { int q = tid + j * 256; aq[j] = q >> 2; ac[j] = q & 3; }
    int wr = tid >> 2, wc = tid & 3;
    unsigned wsw = (unsigned)((wc ^ ((wr >> 1) & 3)) << 4);

    float acc[4][4][4];
#pragma unroll
    for (int i = 0; i < 4; i++)
#pragma unroll
        for (int j = 0; j < 4; j++)
#pragma unroll
            for (int q = 0; q < 4; q++) acc[i][j][q] = 0.f;

    const float* wgp = W + (long)(n0 + wr) * 32768 + kbase + wc * 8;

    float4 w0a = *(const float4*)(wgp);
    float4 w0b = *(const float4*)(wgp + 4);
#pragma unroll
    for (int j = 0; j < 4; j++) {
        int r = aq[j], c = ac[j];
        unsigned sw = (unsigned)(r * 64 + ((c ^ ((r >> 1) & 3)) << 4));
        cpa16(sbase + sw, g_ahi + (long)r * 32768 + kbase + c * 8);
        cpa16(sbase + 16384 + sw, g_alo + (long)r * 32768 + kbase + c * 8);
    }
    cpa_commit();
    {
        uint4 hi, lo;
        hi.x = pkbf(w0a.x, w0a.y); hi.y = pkbf(w0a.z, w0a.w);
        hi.z = pkbf(w0b.x, w0b.y); hi.w = pkbf(w0b.z, w0b.w);
        __nv_bfloat16 t0 = __float2bfloat16(w0a.x), t1 = __float2bfloat16(w0a.y);
        __nv_bfloat16 t2 = __float2bfloat16(w0a.z), t3 = __float2bfloat16(w0a.w);
        __nv_bfloat16 t4 = __float2bfloat16(w0b.x), t5 = __float2bfloat16(w0b.y);
        __nv_bfloat16 t6 = __float2bfloat16(w0b.z), t7 = __float2bfloat16(w0b.w);
        lo.x = pkbf(w0a.x - __bfloat162float(t0), w0a.y - __bfloat162float(t1));
        lo.y = pkbf(w0a.z - __bfloat162float(t2), w0a.w - __bfloat162float(t3));
        lo.z = pkbf(w0b.x - __bfloat162float(t4), w0b.y - __bfloat162float(t5));
        lo.w = pkbf(w0b.z - __bfloat162float(t6), w0b.w - __bfloat162float(t7));
        sts128(sbase + 32768 + wr * 64 + wsw, hi);
        sts128(sbase + 36864 + wr * 64 + wsw, lo);
    }

    int ri = lane & 7, mat = lane >> 3;

    for (int it = 0; it < 128; it++) {
        int st = it & 1;
        unsigned stb = sbase + st * 40960u;
        cpa_wait0();
        __syncthreads();

        float4 wna, wnb;
        if (it < 127) {
            long ko = kbase + (it + 1) * 32;
            wna = *(const float4*)(wgp + (it + 1) * 32);
            wnb = *(const float4*)(wgp + (it + 1) * 32 + 4);
            unsigned nb = sbase + (st ^ 1) * 40960u;
#pragma unroll
            for (int j = 0; j < 4; j++) {
                int r = aq[j], c = ac[j];
                unsigned sw = (unsigned)(r * 64 + ((c ^ ((r >> 1) & 3)) << 4));
                cpa16(nb + sw, g_ahi + (long)r * 32768 + ko + c * 8);
                cpa16(nb + 16384 + sw, g_alo + (long)r * 32768 + ko + c * 8);
            }
            cpa_commit();
        }

#pragma unroll
        for (int k16 = 0; k16 < 2; k16++) {
            unsigned ah[4][4], al[4][4], bh[4][2], bl[4][2];
#pragma unroll
            for (int mi = 0; mi < 4; mi++) {
                int row = m_base + mi * 16 + ri + ((mat & 1) << 3);
                int c = k16 * 2 + (mat >> 1);
                unsigned ad = stb + row * 64 + ((c ^ ((row >> 1) & 3)) << 4);
                ldsm4(ah[mi][0], ah[mi][1], ah[mi][2], ah[mi][3], ad);
                ldsm4(al[mi][0], al[mi][1], al[mi][2], al[mi][3], ad + 16384);
            }
#pragma unroll
            for (int ng = 0; ng < 2; ng++) {
                int row = n_base + ng * 16 + ri + ((mat >> 1) << 3);
                int c = k16 * 2 + (mat & 1);
                unsigned bd = stb + 32768 + row * 64 + ((c ^ ((row >> 1) & 3)) << 4);
                unsigned r0, r1, r2, r3;
                ldsm4(r0, r1, r2, r3, bd);
                bh[2 * ng][0] = r0; bh[2 * ng][1] = r1;
                bh[2 * ng + 1][0] = r2; bh[2 * ng + 1][1] = r3;
                ldsm4(r0, r1, r2, r3, bd + 4096);
                bl[2 * ng][0] = r0; bl[2 * ng][1] = r1;
                bl[2 * ng + 1][0] = r2; bl[2 * ng + 1][1] = r3;
            }
#pragma unroll
            for (int mi = 0; mi < 4; mi++)
#pragma unroll
                for (int ni = 0; ni < 4; ni++) {
                    mma16816(acc[mi][ni], ah[mi], bh[ni]);
                    mma16816(acc[mi][ni], ah[mi], bl[ni]);
                    mma16816(acc[mi][ni], al[mi], bh[ni]);
                }
        }

        if (it < 127) {
            uint4 hi, lo;
            hi.x = pkbf(wna.x, wna.y); hi.y = pkbf(wna.z, wna.w);
            hi.z = pkbf(wnb.x, wnb.y); hi.w = pkbf(wnb.z, wnb.w);
            __nv_bfloat16 t0 = __float2bfloat16(wna.x), t1 = __float2bfloat16(wna.y);
            __nv_bfloat16 t2 = __float2bfloat16(wna.z), t3 = __float2bfloat16(wna.w);
            __nv_bfloat16 t4 = __float2bfloat16(wnb.x), t5 = __float2bfloat16(wnb.y);
            __nv_bfloat16 t6 = __float2bfloat16(wnb.z), t7 = __float2bfloat16(wnb.w);
            lo.x = pkbf(wna.x - __bfloat162float(t0), wna.y - __bfloat162float(t1));
            lo.y = pkbf(wna.z - __bfloat162float(t2), wna.w - __bfloat162float(t3));
            lo.z = pkbf(wnb.x - __bfloat162float(t4), wnb.y - __bfloat162float(t5));
            lo.w = pkbf(wnb.z - __bfloat162float(t6), wnb.w - __bfloat162float(t7));
            unsigned nb = sbase + (st ^ 1) * 40960u;
            sts128(nb + 32768 + wr * 64 + wsw, hi);
            sts128(nb + 36864 + wr * 64 + wsw, lo);
        }
    }

    float* slab = g_fc1p + (long)sk * BATCH * 1024;
#pragma unroll
    for (int mi = 0; mi < 4; mi++)
#pragma unroll
        for (int ni = 0; ni < 4; ni++) {
            int m = m_base + mi * 16 + (lane >> 2);
            int n = n0 + n_base + ni * 8 + (lane & 3) * 2;
            *(float2*)&slab[(long)m * 1024 + n] =
                make_float2(acc[mi][ni][0], acc[mi][ni][1]);
            *(float2*)&slab[(long)(m + 8) * 1024 + n] =
                make_float2(acc[mi][ni][2], acc[mi][ni][3]);
        }
}

// ======================= fc2 (fused slab-reduce + relu + fc2) ===================
__global__ __launch_bounds__(256) void k_fc2(const float* __restrict__ fc1b,
                                             const float* __restrict__ w2,
                                             const float* __restrict__ b2,
                                             float* __restrict__ out) {
    __shared__ __align__(16) float hs[1024];
    __shared__ float red[10 * 256];
    int b = blockIdx.x, tid = threadIdx.x;
    for (int j = tid; j < 1024; j += 256) {
        float s = 0.f;
#pragma unroll
        for (int q = 0; q < 8; q++) s += g_fc1p[(long)q * BATCH * 1024 + b * 1024 + j];
        hs[j] = fmaxf(s + fc1b[j], 0.f);
    }
    __syncthreads();
    float p[10];
#pragma unroll
    for (int n = 0; n < 10; n++) p[n] = 0.f;
    for (int j = tid; j < 1024; j += 256) {
        float hv = hs[j];
#pragma unroll
        for (int n = 0; n < 10; n++) p[n] += hv * w2[n * 1024 + j];
    }
#pragma unroll
    for (int n = 0; n < 10; n++) red[n * 256 + tid] = p[n];
    __syncthreads();
    for (int s = 128; s > 0; s >>= 1) {
        if (tid < s) {
#pragma unroll
            for (int n = 0; n < 10; n++) red[n * 256 + tid] += red[n * 256 + tid + s];
        }
        __syncthreads();
    }
    if (tid < 10) out[b * 10 + tid] = red[tid * 256] + b2[tid];
}

// =================================================================================
extern "C" void kernel_launch(void* const* d_in, const int* in_sizes, int n_in,
                              void* d_out, int out_size) {
    const float* x    = (const float*)d_in[0];
    const int*   idx1 = (const int*)d_in[1];
    const int*   idx2 = (const int*)d_in[2];
    const float* w1a  = (const float*)d_in[3];
    const float* b1a  = (const float*)d_in[4];
    const float* w1b  = (const float*)d_in[5];
    const float* b1b  = (const float*)d_in[6];
    const float* w1p  = (const float*)d_in[7];
    const float* b1p  = (const float*)d_in[8];
    const float* w2a  = (const float*)d_in[9];
    const float* b2a  = (const float*)d_in[10];
    const float* w2b  = (const float*)d_in[11];
    const float* b2b  = (const float*)d_in[12];
    const float* w2p  = (const float*)d_in[13];
    const float* b2p  = (const float*)d_in[14];
    const float* fc1w = (const float*)d_in[15];
    const float* fc1b = (const float*)d_in[16];
    const float* fc2w = (const float*)d_in[17];
    const float* fc2b = (const float*)d_in[18];
    float* out = (float*)d_out;

    const int smem_conv2 = (64 * 256 + 576 * 16) * 4;          // 102400
    const int smem_knn2  = (4224 + 19008 + 64) * 4;            //  93184
    const int smem_fc1t  = 81920;
    cudaFuncSetAttribute(k_l2_conv, cudaFuncAttributeMaxDynamicSharedMemorySize, smem_conv2);
    cudaFuncSetAttribute(k_l2_knn,  cudaFuncAttributeMaxDynamicSharedMemorySize, smem_knn2);
    cudaFuncSetAttribute(k_fc1t,    cudaFuncAttributeMaxDynamicSharedMemorySize, smem_fc1t);

    k_repack<<<72, 256>>>(w1a, w1b, w2a, w2b);
    k_l1<<<BATCH, 256>>>(x, idx1, b1a, b1b, w1p, b1p);
    k_l2_conv<<<dim3(BATCH, 2), 256, smem_conv2>>>(b2a);
    k_l2_knn<<<BATCH, 288, smem_knn2>>>(idx2, b2b);
    k_l2_pw<<<BATCH, 256>>>(w2p, b2p);
    k_fc1t<<<dim3(16, 1, 8), 256, smem_fc1t>>>(fc1w);
    k_fc2<<<BATCH, 256>>>(fc1b, fc2w, fc2b, out);
}

// round 8
// speedup vs baseline: 2.2359x; 1.0583x over previous
#include <cuda_runtime.h>
#include <cuda_bf16.h>

typedef unsigned long long ull;
constexpr int BATCH = 256;

// ---------------- scratch (device globals) ----------------
__device__ __align__(16) float g_out1[BATCH * 64 * 256];
__device__ __align__(16) float g_cat2[BATCH * 64 * 256];
__device__ __align__(16) float g_fc1p[16 * BATCH * 1024];
__device__ __align__(16) float g_r1a[1728];
__device__ __align__(16) float g_r1b[1728];
__device__ __align__(16) float g_r2a[18432];
__device__ __align__(16) float g_r2b[18432];   // [k][c][oc] layout
__device__ __align__(16) __nv_bfloat16 g_ahi[BATCH * 32768];
__device__ __align__(16) __nv_bfloat16 g_alo[BATCH * 32768];

// ---------------- f32x2 helpers ----------------
__device__ __forceinline__ ull pack2(float lo, float hi) {
    ull r;
    asm("mov.b64 %0, {%1, %2};" : "=l"(r) : "r"(__float_as_uint(lo)), "r"(__float_as_uint(hi)));
    return r;
}
__device__ __forceinline__ ull packd(float s) { return pack2(s, s); }
__device__ __forceinline__ void fma2(ull& d, ull a, ull b) {
    asm("fma.rn.f32x2 %0, %1, %2, %3;" : "=l"(d) : "l"(a), "l"(b), "l"(d));
}
__device__ __forceinline__ float2 unpk(ull v) {
    unsigned lo, hi;
    asm("mov.b64 {%0, %1}, %2;" : "=r"(lo), "=r"(hi) : "l"(v));
    float2 f; f.x = __uint_as_float(lo); f.y = __uint_as_float(hi);
    return f;
}

// ---------------- mma.sync helpers ----------------
__device__ __forceinline__ unsigned smem_u32(const void* p) {
    unsigned a;
    asm("{ .reg .u64 t; cvta.to.shared.u64 t, %1; cvt.u32.u64 %0, t; }" : "=r"(a) : "l"(p));
    return a;
}
__device__ __forceinline__ void ldsm4(unsigned& r0, unsigned& r1, unsigned& r2, unsigned& r3,
                                      unsigned addr) {
    asm volatile("ldmatrix.sync.aligned.m8n8.x4.shared.b16 {%0,%1,%2,%3}, [%4];"
                 : "=r"(r0), "=r"(r1), "=r"(r2), "=r"(r3) : "r"(addr));
}
__device__ __forceinline__ void mma16816(float* c, const unsigned* a, const unsigned* b) {
    asm volatile(
        "mma.sync.aligned.m16n8k16.row.col.f32.bf16.bf16.f32 "
        "{%0,%1,%2,%3},{%4,%5,%6,%7},{%8,%9},{%0,%1,%2,%3};"
        : "+f"(c[0]), "+f"(c[1]), "+f"(c[2]), "+f"(c[3])
        : "r"(a[0]), "r"(a[1]), "r"(a[2]), "r"(a[3]), "r"(b[0]), "r"(b[1]));
}
__device__ __forceinline__ void cpa16(unsigned dst, const void* src) {
    asm volatile("cp.async.cg.shared.global [%0], [%1], 16;" :: "r"(dst), "l"(src));
}
__device__ __forceinline__ void cpa_commit() { asm volatile("cp.async.commit_group;"); }
__device__ __forceinline__ void cpa_wait0() {
    asm volatile("cp.async.wait_group 0;" ::: "memory");
}
__device__ __forceinline__ void sts128(unsigned addr, uint4 v) {
    asm volatile("st.shared.v4.b32 [%0], {%1,%2,%3,%4};"
                 :: "r"(addr), "r"(v.x), "r"(v.y), "r"(v.z), "r"(v.w));
}
__device__ __forceinline__ unsigned pkbf(float a, float b) {
    __nv_bfloat16 ha = __float2bfloat16(a), hb = __float2bfloat16(b);
    return ((unsigned)__bfloat16_as_ushort(hb) << 16) | __bfloat16_as_ushort(ha);
}
// split 8 fp32 -> hi/lo bf16 planes (lo plane at +8192 bytes)
__device__ __forceinline__ void wsplit_store(unsigned hi_base, int row, int c,
                                             float4 a, float4 b) {
    unsigned sw = (unsigned)(row * 64 + ((c ^ ((row >> 1) & 3)) << 4));
    uint4 hi, lo;
    hi.x = pkbf(a.x, a.y); hi.y = pkbf(a.z, a.w);
    hi.z = pkbf(b.x, b.y); hi.w = pkbf(b.z, b.w);
    __nv_bfloat16 t0 = __float2bfloat16(a.x), t1 = __float2bfloat16(a.y);
    __nv_bfloat16 t2 = __float2bfloat16(a.z), t3 = __float2bfloat16(a.w);
    __nv_bfloat16 t4 = __float2bfloat16(b.x), t5 = __float2bfloat16(b.y);
    __nv_bfloat16 t6 = __float2bfloat16(b.z), t7 = __float2bfloat16(b.w);
    lo.x = pkbf(a.x - __bfloat162float(t0), a.y - __bfloat162float(t1));
    lo.y = pkbf(a.z - __bfloat162float(t2), a.w - __bfloat162float(t3));
    lo.z = pkbf(b.x - __bfloat162float(t4), b.y - __bfloat162float(t5));
    lo.w = pkbf(b.z - __bfloat162float(t6), b.w - __bfloat162float(t7));
    sts128(hi_base + sw, hi);
    sts128(hi_base + 8192 + sw, lo);
}

// ---------------- weight repack ----------------
__global__ __launch_bounds__(256) void k_repack(const float* __restrict__ w1a,
                                                const float* __restrict__ w1b,
                                                const float* __restrict__ w2a,
                                                const float* __restrict__ w2b) {
    int i = blockIdx.x * 256 + threadIdx.x;
    if (i < 1728) {
        int oc = i / 108, rest = i % 108;
        g_r1a[rest * 16 + oc] = w1a[i];
        g_r1b[rest * 16 + oc] = w1b[i];
    }
    if (i < 18432) {
        int oc = i / 576, rest = i % 576;
        g_r2a[rest * 32 + oc] = w2a[i];
        int c = rest / 9, k = rest % 9;
        g_r2b[(k * 64 + c) * 32 + oc] = w2b[i];   // [k][c][oc]
    }
}

// ======================= Layer 1 FUSED: conv + knn + pw -> g_out1 ================
__global__ __launch_bounds__(256) void k_l1(const float* __restrict__ x,
                                            const int* __restrict__ idx,
                                            const float* __restrict__ b1a,
                                            const float* __restrict__ b1b,
                                            const float* __restrict__ wp,
                                            const float* __restrict__ bp) {
    __shared__ __align__(16) float xs[12 * 256];
    __shared__ __align__(16) float ss[12 * 64];
    __shared__ float sn[64];
    __shared__ __align__(16) float wsa[1728];
    __shared__ __align__(16) float wsb[1728];
    __shared__ __align__(16) float wsp[64 * 32];
    int b = blockIdx.x, tid = threadIdx.x;

    for (int i = tid; i < 12 * 256; i += 256) {
        int cu = i >> 8, t = i & 255;
        int h = t >> 4, w = t & 15;
        int c = cu >> 2, ii = (cu >> 1) & 1, jj = cu & 1;
        xs[i] = x[((b * 3 + c) * 32 + (2 * h + ii)) * 32 + 2 * w + jj];
    }
    for (int i = tid; i < 1728; i += 256) { wsa[i] = g_r1a[i]; wsb[i] = g_r1b[i]; }
    for (int i = tid; i < 64 * 32; i += 256) wsp[i] = wp[i];
    __syncthreads();
    for (int i = tid; i < 12 * 64; i += 256)
        ss[i] = xs[(i >> 6) * 256 + idx[i & 63]];
    __syncthreads();
    if (tid < 64) {
        float s = 0.f;
#pragma unroll
        for (int c = 0; c < 12; c++) { float v = ss[c * 64 + tid]; s += v * v; }
        sn[tid] = s;
    }
    __syncthreads();

    int t = tid, h = t >> 4, w = t & 15;

    ull acv[8];
#pragma unroll
    for (int o = 0; o < 8; o++) acv[o] = pack2(b1a[2 * o], b1a[2 * o + 1]);
    for (int c = 0; c < 12; c++) {
        float p[9];
#pragma unroll
        for (int dy = 0; dy < 3; dy++)
#pragma unroll
            for (int dx = 0; dx < 3; dx++) {
                int y = h + dy - 1, xq = w + dx - 1;
                p[dy * 3 + dx] = (y >= 0 && y < 16 && xq >= 0 && xq < 16)
                                     ? xs[c * 256 + y * 16 + xq] : 0.f;
            }
#pragma unroll
        for (int tap = 0; tap < 9; tap++) {
            ull s2 = packd(p[tap]);
            const longlong2* wv = (const longlong2*)&wsa[(c * 9 + tap) * 16];
#pragma unroll
            for (int q = 0; q < 4; q++) {
                longlong2 w4 = wv[q];
                fma2(acv[q * 2 + 0], s2, (ull)w4.x);
                fma2(acv[q * 2 + 1], s2, (ull)w4.y);
            }
        }
    }

    float xr[12]; float xn = 0.f;
#pragma unroll
    for (int c = 0; c < 12; c++) { float v = xs[c * 256 + t]; xr[c] = v; xn += v * v; }

    float bd[9]; int bi[9];
#pragma unroll
    for (int k = 0; k < 9; k++) { bd[k] = 3.0e38f; bi[k] = 0; }
    for (int n = 0; n < 64; n++) {
        float dot = 0.f;
#pragma unroll
        for (int c = 0; c < 12; c++) dot += xr[c] * ss[c * 64 + n];
        float d = xn + sn[n] - 2.f * dot;
        if (d < bd[8]) {
            bool placed = false;
#pragma unroll
            for (int j = 8; j > 0; --j) {
                if (!placed) {
                    if (d < bd[j - 1]) { bd[j] = bd[j - 1]; bi[j] = bi[j - 1]; }
                    else { bd[j] = d; bi[j] = n; placed = true; }
                }
            }
            if (!placed) { bd[0] = d; bi[0] = n; }
        }
    }

    ull akn[8];
#pragma unroll
    for (int o = 0; o < 8; o++) akn[o] = pack2(b1b[2 * o], b1b[2 * o + 1]);
#pragma unroll
    for (int c = 0; c < 12; c++) {
#pragma unroll
        for (int k = 0; k < 9; k++) {
            ull s2 = packd(ss[c * 64 + bi[k]]);
            const longlong2* wv = (const longlong2*)&wsb[(c * 9 + k) * 16];
#pragma unroll
            for (int q = 0; q < 4; q++) {
                longlong2 w4 = wv[q];
                fma2(akn[q * 2 + 0], s2, (ull)w4.x);
                fma2(akn[q * 2 + 1], s2, (ull)w4.y);
            }
        }
    }

    ull xv[16];
#pragma unroll
    for (int o = 0; o < 8; o++) {
        float2 v = unpk(acv[o]);
        xv[o] = pack2(fmaxf(v.x, 0.f), fmaxf(v.y, 0.f));
        float2 u = unpk(akn[o]);
        xv[8 + o] = pack2(fmaxf(u.x, 0.f), fmaxf(u.y, 0.f));
    }
    for (int oc = 0; oc < 64; oc++) {
        ull a2 = 0ull;
        const longlong2* wv = (const longlong2*)&wsp[oc * 32];
#pragma unroll
        for (int q = 0; q < 8; q++) {
            longlong2 w4 = wv[q];
            fma2(a2, xv[q * 2 + 0], (ull)w4.x);
            fma2(a2, xv[q * 2 + 1], (ull)w4.y);
        }
        float2 v = unpk(a2);
        g_out1[(b * 64 + oc) * 256 + tid] = v.x + v.y + bp[oc];
    }
}

// ======================= Layer 2: 3x3 conv (64 -> 32), oc-split x2 ==============
__global__ __launch_bounds__(256) void k_l2_conv(const float* __restrict__ ba) {
    extern __shared__ __align__(16) float sm[];
    float* xs = sm;
    float* wsh = sm + 64 * 256;
    int b = blockIdx.x, oc0 = blockIdx.y * 16, tid = threadIdx.x;
    for (int i = tid; i < 64 * 256; i += 256) xs[i] = g_out1[b * 64 * 256 + i];
    for (int i = tid; i < 576 * 16; i += 256) {
        int row = i >> 4, o = i & 15;
        wsh[i] = g_r2a[row * 32 + oc0 + o];
    }
    __syncthreads();

    int t = tid, h = t >> 4, w = t & 15;
    ull acc[8];
#pragma unroll
    for (int o = 0; o < 8; o++) acc[o] = pack2(ba[oc0 + 2 * o], ba[oc0 + 2 * o + 1]);
    for (int c = 0; c < 64; c++) {
        float p[9];
#pragma unroll
        for (int dy = 0; dy < 3; dy++)
#pragma unroll
            for (int dx = 0; dx < 3; dx++) {
                int y = h + dy - 1, xq = w + dx - 1;
                p[dy * 3 + dx] = (y >= 0 && y < 16 && xq >= 0 && xq < 16)
                                     ? xs[c * 256 + y * 16 + xq] : 0.f;
            }
#pragma unroll
        for (int tap = 0; tap < 9; tap++) {
            ull s2 = packd(p[tap]);
            const longlong2* wv = (const longlong2*)&wsh[(c * 9 + tap) * 16];
#pragma unroll
            for (int q = 0; q < 4; q++) {
                longlong2 w4 = wv[q];
                fma2(acc[q * 2 + 0], s2, (ull)w4.x);
                fma2(acc[q * 2 + 1], s2, (ull)w4.y);
            }
        }
    }
#pragma unroll
    for (int o = 0; o < 8; o++) {
        float2 v = unpk(acc[o]);
        g_cat2[((b * 64 + oc0 + 2 * o) * 256) + t] = fmaxf(v.x, 0.f);
        g_cat2[((b * 64 + oc0 + 2 * o + 1) * 256) + t] = fmaxf(v.y, 0.f);
    }
}

// ======================= Layer 2: kNN branch — M-table restructure ==============
__global__ __launch_bounds__(288, 2) void k_l2_knn(const int* __restrict__ idx,
                                                   const float* __restrict__ bb) {
    extern __shared__ __align__(16) float sm[];
    float* ss = sm;              // [n][c], row stride 66
    float* Mt = sm + 4224;       // [(k*64+n)][o], row stride 33
    float* sn = Mt + 19008;      // 64
    int b = blockIdx.x, tid = threadIdx.x, lane = tid & 31, wid = tid >> 5;

    for (int i = tid; i < 4096; i += 288) {
        int n = i & 63, c = i >> 6;
        ss[n * 66 + c] = g_out1[(b * 64 + c) * 256 + idx[n]];
    }
    __syncthreads();
    if (tid < 64) {
        float s = 0.f;
#pragma unroll 16
        for (int c = 0; c < 64; c++) { float v = ss[tid * 66 + c]; s += v * v; }
        sn[tid] = s;
    }

    // ---- M-GEMM: warp wid computes M[k=wid][n in {lane, lane+32}][0..31] ----
    {
        int k = wid;
        ull a0[16], a1[16];
#pragma unroll
        for (int j = 0; j < 16; j++) { a0[j] = 0ull; a1[j] = 0ull; }
        const longlong2* wrow = (const longlong2*)(g_r2b + (k * 64) * 32);
        int n0 = lane, n1 = lane + 32;
        for (int c = 0; c < 64; c++) {
            ull s0 = packd(ss[n0 * 66 + c]);
            ull s1 = packd(ss[n1 * 66 + c]);
#pragma unroll
            for (int q = 0; q < 8; q++) {
                longlong2 w4 = wrow[c * 8 + q];
                fma2(a0[q * 2 + 0], s0, (ull)w4.x);
                fma2(a0[q * 2 + 1], s0, (ull)w4.y);
                fma2(a1[q * 2 + 0], s1, (ull)w4.x);
                fma2(a1[q * 2 + 1], s1, (ull)w4.y);
            }
        }
        float* m0 = &Mt[(k * 64 + n0) * 33];
        float* m1 = &Mt[(k * 64 + n1) * 33];
#pragma unroll
        for (int j = 0; j < 16; j++) {
            float2 v0 = unpk(a0[j]); m0[2 * j] = v0.x; m0[2 * j + 1] = v0.y;
            float2 v1 = unpk(a1[j]); m1[2 * j] = v1.x; m1[2 * j + 1] = v1.y;
        }
    }
    __syncthreads();

    if (tid < 256) {
        int t = tid;
        ull xr2[32]; float xn = 0.f;
#pragma unroll
        for (int c2 = 0; c2 < 32; c2++) {
            float f0 = g_out1[(b * 64 + 2 * c2) * 256 + t];
            float f1 = g_out1[(b * 64 + 2 * c2 + 1) * 256 + t];
            xn += f0 * f0 + f1 * f1;
            xr2[c2] = pack2(f0, f1);
        }

        float bd[9]; int bi[9];
#pragma unroll
        for (int k = 0; k < 9; k++) { bd[k] = 3.0e38f; bi[k] = 0; }
        for (int n = 0; n < 64; n++) {
            const ull* sp = (const ull*)&ss[n * 66];
            ull d2 = 0ull;
#pragma unroll
            for (int j = 0; j < 32; j++) fma2(d2, xr2[j], sp[j]);
            float2 dv = unpk(d2);
            float d = xn + sn[n] - 2.f * (dv.x + dv.y);
            if (d < bd[8]) {
                bool placed = false;
#pragma unroll
                for (int j = 8; j > 0; --j) {
                    if (!placed) {
                        if (d < bd[j - 1]) { bd[j] = bd[j - 1]; bi[j] = bi[j - 1]; }
                        else { bd[j] = d; bi[j] = n; placed = true; }
                    }
                }
                if (!placed) { bd[0] = d; bi[0] = n; }
            }
        }

#pragma unroll
        for (int half = 0; half < 2; half++) {
            float acc[16];
#pragma unroll
            for (int o = 0; o < 16; o++) acc[o] = bb[half * 16 + o];
#pragma unroll
            for (int k = 0; k < 9; k++) {
                const float* mrow = &Mt[(k * 64 + bi[k]) * 33 + half * 16];
#pragma unroll
                for (int o = 0; o < 16; o++) acc[o] += mrow[o];
            }
#pragma unroll
            for (int o = 0; o < 16; o++)
                g_cat2[((b * 64 + 32 + half * 16 + o) * 256) + t] = fmaxf(acc[o], 0.f);
        }
    }
}

// ======== Layer 2: 1x1 conv (64->128) + shuffle/flatten + bf16 hi/lo split ======
__global__ __launch_bounds__(256) void k_l2_pw(const float* __restrict__ wp,
                                               const float* __restrict__ bp) {
    __shared__ __align__(16) float ws[128 * 64];
    int b = blockIdx.x, tid = threadIdx.x;
    for (int i = tid; i < 128 * 64; i += 256) ws[i] = wp[i];
    __syncthreads();
    ull xv[32];
#pragma unroll
    for (int c2 = 0; c2 < 32; c2++) {
        float f0 = g_cat2[(b * 64 + 2 * c2) * 256 + tid];
        float f1 = g_cat2[(b * 64 + 2 * c2 + 1) * 256 + tid];
        xv[c2] = pack2(f0, f1);
    }
    int h = tid >> 4, w = tid & 15;
    for (int oc = 0; oc < 128; oc++) {
        ull a2 = 0ull;
        const longlong2* wv = (const longlong2*)&ws[oc * 64];
#pragma unroll
        for (int q = 0; q < 16; q++) {
            longlong2 w4 = wv[q];
            fma2(a2, xv[q * 2 + 0], (ull)w4.x);
            fma2(a2, xv[q * 2 + 1], (ull)w4.y);
        }
        float2 v = unpk(a2);
        float acc = v.x + v.y + bp[oc];
        int cp = oc >> 2, ii = (oc >> 1) & 1, jj = oc & 1;
        long pos = (long)b * 32768 + cp * 1024 + (2 * h + ii) * 32 + 2 * w + jj;
        __nv_bfloat16 hi = __float2bfloat16(acc);
        g_ahi[pos] = hi;
        g_alo[pos] = __float2bfloat16(acc - __bfloat162float(hi));
    }
}

// ======================= fc1: bf16 split GEMM via mma.sync ======================
// C[256,1024] = A @ W^T;  AhWh + AhWl + AlWh, fp32 acc.
// Grid (8 n-tiles, 1, 16 splitk). CTA: M=256, N=128, kc=32, 2-stage pipeline.
// Stage: Ah 16K | Al 16K | Wh 8K | Wl 8K = 48K; x2 = 96K.
__global__ __launch_bounds__(256) void k_fc1t(const float* __restrict__ W) {
    extern __shared__ __align__(16) char smem[];
    unsigned sbase = smem_u32(smem);
    int tid = threadIdx.x, lane = tid & 31, warp = tid >> 5;
    int n0 = blockIdx.x * 128, sk = blockIdx.z;
    long kbase = (long)sk * 2048;

    int m_base = (warp & 3) * 64;
    int n_base = (warp >> 2) * 64;

    int aq[4], ac[4];
#pragma unroll
    for (int j = 0; j < 4; j++) { int q = tid + j * 256; aq[j] = q >> 2; ac[j] = q & 3; }
    int wr[2], wc[2];
#pragma unroll
    for (int j = 0; j < 2; j++) { int q = tid + j * 256; wr[j] = q >> 2; wc[j] = q & 3; }

    float acc[4][8][4];
#pragma unroll
    for (int i = 0; i < 4; i++)
#pragma unroll
        for (int j = 0; j < 8; j++)
#pragma unroll
            for (int q = 0; q < 4; q++) acc[i][j][q] = 0.f;

    const float* wgp0 = W + (long)(n0 + wr[0]) * 32768 + kbase + wc[0] * 8;
    const float* wgp1 = W + (long)(n0 + wr[1]) * 32768 + kbase + wc[1] * 8;

    // ---- prologue: stage 0 ----
    float4 w0[2][2];
    w0[0][0] = *(const float4*)(wgp0); w0[0][1] = *(const float4*)(wgp0 + 4);
    w0[1][0] = *(const float4*)(wgp1); w0[1][1] = *(const float4*)(wgp1 + 4);
#pragma unroll
    for (int j = 0; j < 4; j++) {
        int r = aq[j], c = ac[j];
        unsigned sw = (unsigned)(r * 64 + ((c ^ ((r >> 1) & 3)) << 4));
        cpa16(sbase + sw, g_ahi + (long)r * 32768 + kbase + c * 8);
        cpa16(sbase + 16384 + sw, g_alo + (long)r * 32768 + kbase + c * 8);
    }
    cpa_commit();
    wsplit_store(sbase + 32768, wr[0], wc[0], w0[0][0], w0[0][1]);
    wsplit_store(sbase + 32768, wr[1], wc[1], w0[1][0], w0[1][1]);

    int ri = lane & 7, mat = lane >> 3;

    for (int it = 0; it < 64; it++) {
        int st = it & 1;
        unsigned stb = sbase + st * 49152u;
        cpa_wait0();
        __syncthreads();

        float4 wn[2][2];
        if (it < 63) {
            long ko = kbase + (it + 1) * 32;
            wn[0][0] = *(const float4*)(wgp0 + (it + 1) * 32);
            wn[0][1] = *(const float4*)(wgp0 + (it + 1) * 32 + 4);
            wn[1][0] = *(const float4*)(wgp1 + (it + 1) * 32);
            wn[1][1] = *(const float4*)(wgp1 + (it + 1) * 32 + 4);
            unsigned nb = sbase + (st ^ 1) * 49152u;
#pragma unroll
            for (int j = 0; j < 4; j++) {
                int r = aq[j], c = ac[j];
                unsigned sw = (unsigned)(r * 64 + ((c ^ ((r >> 1) & 3)) << 4));
                cpa16(nb + sw, g_ahi + (long)r * 32768 + ko + c * 8);
                cpa16(nb + 16384 + sw, g_alo + (long)r * 32768 + ko + c * 8);
            }
            cpa_commit();
        }

#pragma unroll
        for (int k16 = 0; k16 < 2; k16++) {
            unsigned af[4][4], bh[8][2], bl[8][2];
            // B frags (hi+lo)
#pragma unroll
            for (int ng = 0; ng < 4; ng++) {
                int row = n_base + ng * 16 + ri + ((mat >> 1) << 3);
                int c = k16 * 2 + (mat & 1);
                unsigned bd = stb + 32768 + row * 64 + ((c ^ ((row >> 1) & 3)) << 4);
                unsigned r0, r1, r2, r3;
                ldsm4(r0, r1, r2, r3, bd);
                bh[2 * ng][0] = r0; bh[2 * ng][1] = r1;
                bh[2 * ng + 1][0] = r2; bh[2 * ng + 1][1] = r3;
                ldsm4(r0, r1, r2, r3, bd + 8192);
                bl[2 * ng][0] = r0; bl[2 * ng][1] = r1;
                bl[2 * ng + 1][0] = r2; bl[2 * ng + 1][1] = r3;
            }
            // A-hi frags, two MMA terms
#pragma unroll
            for (int mi = 0; mi < 4; mi++) {
                int row = m_base + mi * 16 + ri + ((mat & 1) << 3);
                int c = k16 * 2 + (mat >> 1);
                unsigned ad = stb + row * 64 + ((c ^ ((row >> 1) & 3)) << 4);
                ldsm4(af[mi][0], af[mi][1], af[mi][2], af[mi][3], ad);
            }
#pragma unroll
            for (int mi = 0; mi < 4; mi++)
#pragma unroll
                for (int ni = 0; ni < 8; ni++) {
                    mma16816(acc[mi][ni], af[mi], bh[ni]);
                    mma16816(acc[mi][ni], af[mi], bl[ni]);
                }
            // A-lo frags (reuse regs), third term
#pragma unroll
            for (int mi = 0; mi < 4; mi++) {
                int row = m_base + mi * 16 + ri + ((mat & 1) << 3);
                int c = k16 * 2 + (mat >> 1);
                unsigned ad = stb + 16384 + row * 64 + ((c ^ ((row >> 1) & 3)) << 4);
                ldsm4(af[mi][0], af[mi][1], af[mi][2], af[mi][3], ad);
            }
#pragma unroll
            for (int mi = 0; mi < 4; mi++)
#pragma unroll
                for (int ni = 0; ni < 8; ni++)
                    mma16816(acc[mi][ni], af[mi], bh[ni]);
        }

        if (it < 63) {
            unsigned nb = sbase + (st ^ 1) * 49152u;
            wsplit_store(nb + 32768, wr[0], wc[0], wn[0][0], wn[0][1]);
            wsplit_store(nb + 32768, wr[1], wc[1], wn[1][0], wn[1][1]);
        }
    }

    float* slab = g_fc1p + (long)sk * BATCH * 1024;
#pragma unroll
    for (int mi = 0; mi < 4; mi++)
#pragma unroll
        for (int ni = 0; ni < 8; ni++) {
            int m = m_base + mi * 16 + (lane >> 2);
            int n = n0 + n_base + ni * 8 + (lane & 3) * 2;
            *(float2*)&slab[(long)m * 1024 + n] =
                make_float2(acc[mi][ni][0], acc[mi][ni][1]);
            *(float2*)&slab[(long)(m + 8) * 1024 + n] =
                make_float2(acc[mi][ni][2], acc[mi][ni][3]);
        }
}

// ======================= fc2 (fused slab-reduce + relu + fc2) ===================
__global__ __launch_bounds__(256) void k_fc2(const float* __restrict__ fc1b,
                                             const float* __restrict__ w2,
                                             const float* __restrict__ b2,
                                             float* __restrict__ out) {
    __shared__ __align__(16) float hs[1024];
    __shared__ float red[10 * 256];
    int b = blockIdx.x, tid = threadIdx.x;
    for (int j = tid; j < 1024; j += 256) {
        float s = 0.f;
#pragma unroll
        for (int q = 0; q < 16; q++) s += g_fc1p[(long)q * BATCH * 1024 + b * 1024 + j];
        hs[j] = fmaxf(s + fc1b[j], 0.f);
    }
    __syncthreads();
    float p[10];
#pragma unroll
    for (int n = 0; n < 10; n++) p[n] = 0.f;
    for (int j = tid; j < 1024; j += 256) {
        float hv = hs[j];
#pragma unroll
        for (int n = 0; n < 10; n++) p[n] += hv * w2[n * 1024 + j];
    }
#pragma unroll
    for (int n = 0; n < 10; n++) red[n * 256 + tid] = p[n];
    __syncthreads();
    for (int s = 128; s > 0; s >>= 1) {
        if (tid < s) {
#pragma unroll
            for (int n = 0; n < 10; n++) red[n * 256 + tid] += red[n * 256 + tid + s];
        }
        __syncthreads();
    }
    if (tid < 10) out[b * 10 + tid] = red[tid * 256] + b2[tid];
}

// =================================================================================
extern "C" void kernel_launch(void* const* d_in, const int* in_sizes, int n_in,
                              void* d_out, int out_size) {
    const float* x    = (const float*)d_in[0];
    const int*   idx1 = (const int*)d_in[1];
    const int*   idx2 = (const int*)d_in[2];
    const float* w1a  = (const float*)d_in[3];
    const float* b1a  = (const float*)d_in[4];
    const float* w1b  = (const float*)d_in[5];
    const float* b1b  = (const float*)d_in[6];
    const float* w1p  = (const float*)d_in[7];
    const float* b1p  = (const float*)d_in[8];
    const float* w2a  = (const float*)d_in[9];
    const float* b2a  = (const float*)d_in[10];
    const float* w2b  = (const float*)d_in[11];
    const float* b2b  = (const float*)d_in[12];
    const float* w2p  = (const float*)d_in[13];
    const float* b2p  = (const float*)d_in[14];
    const float* fc1w = (const float*)d_in[15];
    const float* fc1b = (const float*)d_in[16];
    const float* fc2w = (const float*)d_in[17];
    const float* fc2b = (const float*)d_in[18];
    float* out = (float*)d_out;

    const int smem_conv2 = (64 * 256 + 576 * 16) * 4;          // 102400
    const int smem_knn2  = (4224 + 19008 + 64) * 4;            //  93184
    const int smem_fc1t  = 98304;
    cudaFuncSetAttribute(k_l2_conv, cudaFuncAttributeMaxDynamicSharedMemorySize, smem_conv2);
    cudaFuncSetAttribute(k_l2_knn,  cudaFuncAttributeMaxDynamicSharedMemorySize, smem_knn2);
    cudaFuncSetAttribute(k_fc1t,    cudaFuncAttributeMaxDynamicSharedMemorySize, smem_fc1t);

    k_repack<<<72, 256>>>(w1a, w1b, w2a, w2b);
    k_l1<<<BATCH, 256>>>(x, idx1, b1a, b1b, w1p, b1p);
    k_l2_conv<<<dim3(BATCH, 2), 256, smem_conv2>>>(b2a);
    k_l2_knn<<<BATCH, 288, smem_knn2>>>(idx2, b2b);
    k_l2_pw<<<BATCH, 256>>>(w2p, b2p);
    k_fc1t<<<dim3(8, 1, 16), 256, smem_fc1t>>>(fc1w);
    k_fc2<<<BATCH, 256>>>(fc1b, fc2w, fc2b, out);
}

// round 9
// speedup vs baseline: 2.2666x; 1.0138x over previous
#include <cuda_runtime.h>
#include <cuda_bf16.h>

typedef unsigned long long ull;
constexpr int BATCH = 256;

// ---------------- scratch (device globals) ----------------
__device__ __align__(16) float g_out1[BATCH * 64 * 256];
__device__ __align__(16) float g_cat2[BATCH * 64 * 256];
__device__ __align__(16) float g_fc1p[16 * BATCH * 1024];
__device__ __align__(16) float g_r1a[1728];
__device__ __align__(16) float g_r1b[1728];
__device__ __align__(16) float g_r2a[18432];
__device__ __align__(16) float g_r2b[18432];   // [k][c][oc] layout
__device__ __align__(16) __nv_bfloat16 g_ahi[BATCH * 32768];
__device__ __align__(16) __nv_bfloat16 g_alo[BATCH * 32768];

// ---------------- f32x2 helpers ----------------
__device__ __forceinline__ ull pack2(float lo, float hi) {
    ull r;
    asm("mov.b64 %0, {%1, %2};" : "=l"(r) : "r"(__float_as_uint(lo)), "r"(__float_as_uint(hi)));
    return r;
}
__device__ __forceinline__ ull packd(float s) { return pack2(s, s); }
__device__ __forceinline__ void fma2(ull& d, ull a, ull b) {
    asm("fma.rn.f32x2 %0, %1, %2, %3;" : "=l"(d) : "l"(a), "l"(b), "l"(d));
}
__device__ __forceinline__ float2 unpk(ull v) {
    unsigned lo, hi;
    asm("mov.b64 {%0, %1}, %2;" : "=r"(lo), "=r"(hi) : "l"(v));
    float2 f; f.x = __uint_as_float(lo); f.y = __uint_as_float(hi);
    return f;
}

// ---------------- mma.sync helpers ----------------
__device__ __forceinline__ unsigned smem_u32(const void* p) {
    unsigned a;
    asm("{ .reg .u64 t; cvta.to.shared.u64 t, %1; cvt.u32.u64 %0, t; }" : "=r"(a) : "l"(p));
    return a;
}
__device__ __forceinline__ void ldsm4(unsigned& r0, unsigned& r1, unsigned& r2, unsigned& r3,
                                      unsigned addr) {
    asm volatile("ldmatrix.sync.aligned.m8n8.x4.shared.b16 {%0,%1,%2,%3}, [%4];"
                 : "=r"(r0), "=r"(r1), "=r"(r2), "=r"(r3) : "r"(addr));
}
__device__ __forceinline__ void mma16816(float* c, const unsigned* a, const unsigned* b) {
    asm volatile(
        "mma.sync.aligned.m16n8k16.row.col.f32.bf16.bf16.f32 "
        "{%0,%1,%2,%3},{%4,%5,%6,%7},{%8,%9},{%0,%1,%2,%3};"
        : "+f"(c[0]), "+f"(c[1]), "+f"(c[2]), "+f"(c[3])
        : "r"(a[0]), "r"(a[1]), "r"(a[2]), "r"(a[3]), "r"(b[0]), "r"(b[1]));
}
__device__ __forceinline__ void cpa16(unsigned dst, const void* src) {
    asm volatile("cp.async.cg.shared.global [%0], [%1], 16;" :: "r"(dst), "l"(src));
}
__device__ __forceinline__ void cpa_commit() { asm volatile("cp.async.commit_group;"); }
__device__ __forceinline__ void cpa_wait0() {
    asm volatile("cp.async.wait_group 0;" ::: "memory");
}
__device__ __forceinline__ void sts128(unsigned addr, uint4 v) {
    asm volatile("st.shared.v4.b32 [%0], {%1,%2,%3,%4};"
                 :: "r"(addr), "r"(v.x), "r"(v.y), "r"(v.z), "r"(v.w));
}
__device__ __forceinline__ unsigned pkbf(float a, float b) {
    __nv_bfloat16 ha = __float2bfloat16(a), hb = __float2bfloat16(b);
    return ((unsigned)__bfloat16_as_ushort(hb) << 16) | __bfloat16_as_ushort(ha);
}
__device__ __forceinline__ void wsplit_store(unsigned hi_base, int row, int c,
                                             float4 a, float4 b) {
    unsigned sw = (unsigned)(row * 64 + ((c ^ ((row >> 1) & 3)) << 4));
    uint4 hi, lo;
    hi.x = pkbf(a.x, a.y); hi.y = pkbf(a.z, a.w);
    hi.z = pkbf(b.x, b.y); hi.w = pkbf(b.z, b.w);
    __nv_bfloat16 t0 = __float2bfloat16(a.x), t1 = __float2bfloat16(a.y);
    __nv_bfloat16 t2 = __float2bfloat16(a.z), t3 = __float2bfloat16(a.w);
    __nv_bfloat16 t4 = __float2bfloat16(b.x), t5 = __float2bfloat16(b.y);
    __nv_bfloat16 t6 = __float2bfloat16(b.z), t7 = __float2bfloat16(b.w);
    lo.x = pkbf(a.x - __bfloat162float(t0), a.y - __bfloat162float(t1));
    lo.y = pkbf(a.z - __bfloat162float(t2), a.w - __bfloat162float(t3));
    lo.z = pkbf(b.x - __bfloat162float(t4), b.y - __bfloat162float(t5));
    lo.w = pkbf(b.z - __bfloat162float(t6), b.w - __bfloat162float(t7));
    sts128(hi_base + sw, hi);
    sts128(hi_base + 8192 + sw, lo);
}

// ---------------- weight repack ----------------
__global__ __launch_bounds__(256) void k_repack(const float* __restrict__ w1a,
                                                const float* __restrict__ w1b,
                                                const float* __restrict__ w2a,
                                                const float* __restrict__ w2b) {
    int i = blockIdx.x * 256 + threadIdx.x;
    if (i < 1728) {
        int oc = i / 108, rest = i % 108;
        g_r1a[rest * 16 + oc] = w1a[i];
        g_r1b[rest * 16 + oc] = w1b[i];
    }
    if (i < 18432) {
        int oc = i / 576, rest = i % 576;
        g_r2a[rest * 32 + oc] = w2a[i];
        int c = rest / 9, k = rest % 9;
        g_r2b[(k * 64 + c) * 32 + oc] = w2b[i];
    }
}

// ======================= Layer 1 FUSED, pixel-split x2 ==========================
__global__ __launch_bounds__(128) void k_l1(const float* __restrict__ x,
                                            const int* __restrict__ idx,
                                            const float* __restrict__ b1a,
                                            const float* __restrict__ b1b,
                                            const float* __restrict__ wp,
                                            const float* __restrict__ bp) {
    __shared__ __align__(16) float xs[12 * 256];
    __shared__ __align__(16) float ss[12 * 64];
    __shared__ float sn[64];
    __shared__ __align__(16) float wsa[1728];
    __shared__ __align__(16) float wsb[1728];
    __shared__ __align__(16) float wsp[64 * 32];
    int b = blockIdx.x, tid = threadIdx.x;
    int p = blockIdx.y * 128 + tid;    // this block's pixel

    for (int i = tid; i < 12 * 256; i += 128) {
        int cu = i >> 8, t = i & 255;
        int h = t >> 4, w = t & 15;
        int c = cu >> 2, ii = (cu >> 1) & 1, jj = cu & 1;
        xs[i] = x[((b * 3 + c) * 32 + (2 * h + ii)) * 32 + 2 * w + jj];
    }
    for (int i = tid; i < 1728; i += 128) { wsa[i] = g_r1a[i]; wsb[i] = g_r1b[i]; }
    for (int i = tid; i < 64 * 32; i += 128) wsp[i] = wp[i];
    __syncthreads();
    for (int i = tid; i < 12 * 64; i += 128)
        ss[i] = xs[(i >> 6) * 256 + idx[i & 63]];
    __syncthreads();
    if (tid < 64) {
        float s = 0.f;
#pragma unroll
        for (int c = 0; c < 12; c++) { float v = ss[c * 64 + tid]; s += v * v; }
        sn[tid] = s;
    }
    __syncthreads();

    int h = p >> 4, w = p & 15;

    ull acv[8];
#pragma unroll
    for (int o = 0; o < 8; o++) acv[o] = pack2(b1a[2 * o], b1a[2 * o + 1]);
    for (int c = 0; c < 12; c++) {
        float pp[9];
#pragma unroll
        for (int dy = 0; dy < 3; dy++)
#pragma unroll
            for (int dx = 0; dx < 3; dx++) {
                int y = h + dy - 1, xq = w + dx - 1;
                pp[dy * 3 + dx] = (y >= 0 && y < 16 && xq >= 0 && xq < 16)
                                      ? xs[c * 256 + y * 16 + xq] : 0.f;
            }
#pragma unroll
        for (int tap = 0; tap < 9; tap++) {
            ull s2 = packd(pp[tap]);
            const longlong2* wv = (const longlong2*)&wsa[(c * 9 + tap) * 16];
#pragma unroll
            for (int q = 0; q < 4; q++) {
                longlong2 w4 = wv[q];
                fma2(acv[q * 2 + 0], s2, (ull)w4.x);
                fma2(acv[q * 2 + 1], s2, (ull)w4.y);
            }
        }
    }

    float xr[12]; float xn = 0.f;
#pragma unroll
    for (int c = 0; c < 12; c++) { float v = xs[c * 256 + p]; xr[c] = v; xn += v * v; }

    float bd[9]; int bi[9];
#pragma unroll
    for (int k = 0; k < 9; k++) { bd[k] = 3.0e38f; bi[k] = 0; }
    for (int n = 0; n < 64; n++) {
        float dot = 0.f;
#pragma unroll
        for (int c = 0; c < 12; c++) dot += xr[c] * ss[c * 64 + n];
        float d = xn + sn[n] - 2.f * dot;
        if (d < bd[8]) {
            bool placed = false;
#pragma unroll
            for (int j = 8; j > 0; --j) {
                if (!placed) {
                    if (d < bd[j - 1]) { bd[j] = bd[j - 1]; bi[j] = bi[j - 1]; }
                    else { bd[j] = d; bi[j] = n; placed = true; }
                }
            }
            if (!placed) { bd[0] = d; bi[0] = n; }
        }
    }

    ull akn[8];
#pragma unroll
    for (int o = 0; o < 8; o++) akn[o] = pack2(b1b[2 * o], b1b[2 * o + 1]);
#pragma unroll
    for (int c = 0; c < 12; c++) {
#pragma unroll
        for (int k = 0; k < 9; k++) {
            ull s2 = packd(ss[c * 64 + bi[k]]);
            const longlong2* wv = (const longlong2*)&wsb[(c * 9 + k) * 16];
#pragma unroll
            for (int q = 0; q < 4; q++) {
                longlong2 w4 = wv[q];
                fma2(akn[q * 2 + 0], s2, (ull)w4.x);
                fma2(akn[q * 2 + 1], s2, (ull)w4.y);
            }
        }
    }

    ull xv[16];
#pragma unroll
    for (int o = 0; o < 8; o++) {
        float2 v = unpk(acv[o]);
        xv[o] = pack2(fmaxf(v.x, 0.f), fmaxf(v.y, 0.f));
        float2 u = unpk(akn[o]);
        xv[8 + o] = pack2(fmaxf(u.x, 0.f), fmaxf(u.y, 0.f));
    }
    for (int oc = 0; oc < 64; oc++) {
        ull a2 = 0ull;
        const longlong2* wv = (const longlong2*)&wsp[oc * 32];
#pragma unroll
        for (int q = 0; q < 8; q++) {
            longlong2 w4 = wv[q];
            fma2(a2, xv[q * 2 + 0], (ull)w4.x);
            fma2(a2, xv[q * 2 + 1], (ull)w4.y);
        }
        float2 v = unpk(a2);
        g_out1[(b * 64 + oc) * 256 + p] = v.x + v.y + bp[oc];
    }
}

// ============ Layer 2 MERGED: y<2 -> conv oc-half, y==2 -> kNN branch ===========
__global__ __launch_bounds__(288, 2) void k_l2(const int* __restrict__ idx,
                                               const float* __restrict__ ba,
                                               const float* __restrict__ bb) {
    extern __shared__ __align__(16) float sm[];
    int b = blockIdx.x, sel = blockIdx.y, tid = threadIdx.x;

    if (sel < 2) {
        // ---------------- conv branch ----------------
        float* xs = sm;                 // 64*256
        float* wsh = sm + 64 * 256;     // 576*16
        int oc0 = sel * 16;
        for (int i = tid; i < 64 * 256; i += 288) xs[i] = g_out1[b * 64 * 256 + i];
        for (int i = tid; i < 576 * 16; i += 288) {
            int row = i >> 4, o = i & 15;
            wsh[i] = g_r2a[row * 32 + oc0 + o];
        }
        __syncthreads();
        if (tid < 256) {
            int t = tid, h = t >> 4, w = t & 15;
            ull acc[8];
#pragma unroll
            for (int o = 0; o < 8; o++) acc[o] = pack2(ba[oc0 + 2 * o], ba[oc0 + 2 * o + 1]);
            for (int c = 0; c < 64; c++) {
                float p[9];
#pragma unroll
                for (int dy = 0; dy < 3; dy++)
#pragma unroll
                    for (int dx = 0; dx < 3; dx++) {
                        int y = h + dy - 1, xq = w + dx - 1;
                        p[dy * 3 + dx] = (y >= 0 && y < 16 && xq >= 0 && xq < 16)
                                             ? xs[c * 256 + y * 16 + xq] : 0.f;
                    }
#pragma unroll
                for (int tap = 0; tap < 9; tap++) {
                    ull s2 = packd(p[tap]);
                    const longlong2* wv = (const longlong2*)&wsh[(c * 9 + tap) * 16];
#pragma unroll
                    for (int q = 0; q < 4; q++) {
                        longlong2 w4 = wv[q];
                        fma2(acc[q * 2 + 0], s2, (ull)w4.x);
                        fma2(acc[q * 2 + 1], s2, (ull)w4.y);
                    }
                }
            }
#pragma unroll
            for (int o = 0; o < 8; o++) {
                float2 v = unpk(acc[o]);
                g_cat2[((b * 64 + oc0 + 2 * o) * 256) + t] = fmaxf(v.x, 0.f);
                g_cat2[((b * 64 + oc0 + 2 * o + 1) * 256) + t] = fmaxf(v.y, 0.f);
            }
        }
        return;
    }

    // ---------------- kNN branch ----------------
    float* ss = sm;              // [n][c], stride 66
    float* Mt = sm + 4224;       // [(k*64+n)][o], stride 33
    float* sn = Mt + 19008;      // 64
    int lane = tid & 31, wid = tid >> 5;

    for (int i = tid; i < 4096; i += 288) {
        int n = i & 63, c = i >> 6;
        ss[n * 66 + c] = g_out1[(b * 64 + c) * 256 + idx[n]];
    }
    __syncthreads();
    if (tid < 64) {
        float s = 0.f;
#pragma unroll 16
        for (int c = 0; c < 64; c++) { float v = ss[tid * 66 + c]; s += v * v; }
        sn[tid] = s;
    }

    {
        int k = wid;
        ull a0[16], a1[16];
#pragma unroll
        for (int j = 0; j < 16; j++) { a0[j] = 0ull; a1[j] = 0ull; }
        const longlong2* wrow = (const longlong2*)(g_r2b + (k * 64) * 32);
        int n0 = lane, n1 = lane + 32;
        for (int c = 0; c < 64; c++) {
            ull s0 = packd(ss[n0 * 66 + c]);
            ull s1 = packd(ss[n1 * 66 + c]);
#pragma unroll
            for (int q = 0; q < 8; q++) {
                longlong2 w4 = wrow[c * 8 + q];
                fma2(a0[q * 2 + 0], s0, (ull)w4.x);
                fma2(a0[q * 2 + 1], s0, (ull)w4.y);
                fma2(a1[q * 2 + 0], s1, (ull)w4.x);
                fma2(a1[q * 2 + 1], s1, (ull)w4.y);
            }
        }
        float* m0 = &Mt[(k * 64 + n0) * 33];
        float* m1 = &Mt[(k * 64 + n1) * 33];
#pragma unroll
        for (int j = 0; j < 16; j++) {
            float2 v0 = unpk(a0[j]); m0[2 * j] = v0.x; m0[2 * j + 1] = v0.y;
            float2 v1 = unpk(a1[j]); m1[2 * j] = v1.x; m1[2 * j + 1] = v1.y;
        }
    }
    __syncthreads();

    if (tid < 256) {
        int t = tid;
        ull xr2[32]; float xn = 0.f;
#pragma unroll
        for (int c2 = 0; c2 < 32; c2++) {
            float f0 = g_out1[(b * 64 + 2 * c2) * 256 + t];
            float f1 = g_out1[(b * 64 + 2 * c2 + 1) * 256 + t];
            xn += f0 * f0 + f1 * f1;
            xr2[c2] = pack2(f0, f1);
        }

        float bd[9]; int bi[9];
#pragma unroll
        for (int k = 0; k < 9; k++) { bd[k] = 3.0e38f; bi[k] = 0; }
        for (int n = 0; n < 64; n++) {
            const ull* sp = (const ull*)&ss[n * 66];
            ull d2 = 0ull;
#pragma unroll
            for (int j = 0; j < 32; j++) fma2(d2, xr2[j], sp[j]);
            float2 dv = unpk(d2);
            float d = xn + sn[n] - 2.f * (dv.x + dv.y);
            if (d < bd[8]) {
                bool placed = false;
#pragma unroll
                for (int j = 8; j > 0; --j) {
                    if (!placed) {
                        if (d < bd[j - 1]) { bd[j] = bd[j - 1]; bi[j] = bi[j - 1]; }
                        else { bd[j] = d; bi[j] = n; placed = true; }
                    }
                }
                if (!placed) { bd[0] = d; bi[0] = n; }
            }
        }

#pragma unroll
        for (int half = 0; half < 2; half++) {
            float acc[16];
#pragma unroll
            for (int o = 0; o < 16; o++) acc[o] = bb[half * 16 + o];
#pragma unroll
            for (int k = 0; k < 9; k++) {
                const float* mrow = &Mt[(k * 64 + bi[k]) * 33 + half * 16];
#pragma unroll
                for (int o = 0; o < 16; o++) acc[o] += mrow[o];
            }
#pragma unroll
            for (int o = 0; o < 16; o++)
                g_cat2[((b * 64 + 32 + half * 16 + o) * 256) + t] = fmaxf(acc[o], 0.f);
        }
    }
}

// ======== Layer 2: 1x1 conv (64->128) + shuffle/flatten + bf16 hi/lo split ======
__global__ __launch_bounds__(256) void k_l2_pw(const float* __restrict__ wp,
                                               const float* __restrict__ bp) {
    __shared__ __align__(16) float ws[128 * 64];
    int b = blockIdx.x, tid = threadIdx.x;
    for (int i = tid; i < 128 * 64; i += 256) ws[i] = wp[i];
    __syncthreads();
    ull xv[32];
#pragma unroll
    for (int c2 = 0; c2 < 32; c2++) {
        float f0 = g_cat2[(b * 64 + 2 * c2) * 256 + tid];
        float f1 = g_cat2[(b * 64 + 2 * c2 + 1) * 256 + tid];
        xv[c2] = pack2(f0, f1);
    }
    int h = tid >> 4, w = tid & 15;
    for (int oc = 0; oc < 128; oc++) {
        ull a2 = 0ull;
        const longlong2* wv = (const longlong2*)&ws[oc * 64];
#pragma unroll
        for (int q = 0; q < 16; q++) {
            longlong2 w4 = wv[q];
            fma2(a2, xv[q * 2 + 0], (ull)w4.x);
            fma2(a2, xv[q * 2 + 1], (ull)w4.y);
        }
        float2 v = unpk(a2);
        float acc = v.x + v.y + bp[oc];
        int cp = oc >> 2, ii = (oc >> 1) & 1, jj = oc & 1;
        long pos = (long)b * 32768 + cp * 1024 + (2 * h + ii) * 32 + 2 * w + jj;
        __nv_bfloat16 hi = __float2bfloat16(acc);
        g_ahi[pos] = hi;
        g_alo[pos] = __float2bfloat16(acc - __bfloat162float(hi));
    }
}

// ======================= fc1: bf16 split GEMM via mma.sync ======================
__global__ __launch_bounds__(256) void k_fc1t(const float* __restrict__ W) {
    extern __shared__ __align__(16) char smem[];
    unsigned sbase = smem_u32(smem);
    int tid = threadIdx.x, lane = tid & 31, warp = tid >> 5;
    int n0 = blockIdx.x * 128, sk = blockIdx.z;
    long kbase = (long)sk * 2048;

    int m_base = (warp & 3) * 64;
    int n_base = (warp >> 2) * 64;

    int aq[4], ac[4];
#pragma unroll
    for (int j = 0; j < 4; j++) { int q = tid + j * 256; aq[j] = q >> 2; ac[j] = q & 3; }
    int wr[2], wc[2];
#pragma unroll
    for (int j = 0; j < 2; j++) { int q = tid + j * 256; wr[j] = q >> 2; wc[j] = q & 3; }

    float acc[4][8][4];
#pragma unroll
    for (int i = 0; i < 4; i++)
#pragma unroll
        for (int j = 0; j < 8; j++)
#pragma unroll
            for (int q = 0; q < 4; q++) acc[i][j][q] = 0.f;

    const float* wgp0 = W + (long)(n0 + wr[0]) * 32768 + kbase + wc[0] * 8;
    const float* wgp1 = W + (long)(n0 + wr[1]) * 32768 + kbase + wc[1] * 8;

    float4 w0[2][2];
    w0[0][0] = *(const float4*)(wgp0); w0[0][1] = *(const float4*)(wgp0 + 4);
    w0[1][0] = *(const float4*)(wgp1); w0[1][1] = *(const float4*)(wgp1 + 4);
#pragma unroll
    for (int j = 0; j < 4; j++) {
        int r = aq[j], c = ac[j];
        unsigned sw = (unsigned)(r * 64 + ((c ^ ((r >> 1) & 3)) << 4));
        cpa16(sbase + sw, g_ahi + (long)r * 32768 + kbase + c * 8);
        cpa16(sbase + 16384 + sw, g_alo + (long)r * 32768 + kbase + c * 8);
    }
    cpa_commit();
    wsplit_store(sbase + 32768, wr[0], wc[0], w0[0][0], w0[0][1]);
    wsplit_store(sbase + 32768, wr[1], wc[1], w0[1][0], w0[1][1]);

    int ri = lane & 7, mat = lane >> 3;

    for (int it = 0; it < 64; it++) {
        int st = it & 1;
        unsigned stb = sbase + st * 49152u;
        cpa_wait0();
        __syncthreads();

        float4 wn[2][2];
        if (it < 63) {
            long ko = kbase + (it + 1) * 32;
            wn[0][0] = *(const float4*)(wgp0 + (it + 1) * 32);
            wn[0][1] = *(const float4*)(wgp0 + (it + 1) * 32 + 4);
            wn[1][0] = *(const float4*)(wgp1 + (it + 1) * 32);
            wn[1][1] = *(const float4*)(wgp1 + (it + 1) * 32 + 4);
            unsigned nb = sbase + (st ^ 1) * 49152u;
#pragma unroll
            for (int j = 0; j < 4; j++) {
                int r = aq[j], c = ac[j];
                unsigned sw = (unsigned)(r * 64 + ((c ^ ((r >> 1) & 3)) << 4));
                cpa16(nb + sw, g_ahi + (long)r * 32768 + ko + c * 8);
                cpa16(nb + 16384 + sw, g_alo + (long)r * 32768 + ko + c * 8);
            }
            cpa_commit();
        }

#pragma unroll
        for (int k16 = 0; k16 < 2; k16++) {
            unsigned af[4][4], bh[8][2], bl[8][2];
#pragma unroll
            for (int ng = 0; ng < 4; ng++) {
                int row = n_base + ng * 16 + ri + ((mat >> 1) << 3);
                int c = k16 * 2 + (mat & 1);
                unsigned bd = stb + 32768 + row * 64 + ((c ^ ((row >> 1) & 3)) << 4);
                unsigned r0, r1, r2, r3;
                ldsm4(r0, r1, r2, r3, bd);
                bh[2 * ng][0] = r0; bh[2 * ng][1] = r1;
                bh[2 * ng + 1][0] = r2; bh[2 * ng + 1][1] = r3;
                ldsm4(r0, r1, r2, r3, bd + 8192);
                bl[2 * ng][0] = r0; bl[2 * ng][1] = r1;
                bl[2 * ng + 1][0] = r2; bl[2 * ng + 1][1] = r3;
            }
#pragma unroll
            for (int mi = 0; mi < 4; mi++) {
                int row = m_base + mi * 16 + ri + ((mat & 1) << 3);
                int c = k16 * 2 + (mat >> 1);
                unsigned ad = stb + row * 64 + ((c ^ ((row >> 1) & 3)) << 4);
                ldsm4(af[mi][0], af[mi][1], af[mi][2], af[mi][3], ad);
            }
#pragma unroll
            for (int mi = 0; mi < 4; mi++)
#pragma unroll
                for (int ni = 0; ni < 8; ni++) {
                    mma16816(acc[mi][ni], af[mi], bh[ni]);
                    mma16816(acc[mi][ni], af[mi], bl[ni]);
                }
#pragma unroll
            for (int mi = 0; mi < 4; mi++) {
                int row = m_base + mi * 16 + ri + ((mat & 1) << 3);
                int c = k16 * 2 + (mat >> 1);
                unsigned ad = stb + 16384 + row * 64 + ((c ^ ((row >> 1) & 3)) << 4);
                ldsm4(af[mi][0], af[mi][1], af[mi][2], af[mi][3], ad);
            }
#pragma unroll
            for (int mi = 0; mi < 4; mi++)
#pragma unroll
                for (int ni = 0; ni < 8; ni++)
                    mma16816(acc[mi][ni], af[mi], bh[ni]);
        }

        if (it < 63) {
            unsigned nb = sbase + (st ^ 1) * 49152u;
            wsplit_store(nb + 32768, wr[0], wc[0], wn[0][0], wn[0][1]);
            wsplit_store(nb + 32768, wr[1], wc[1], wn[1][0], wn[1][1]);
        }
    }

    float* slab = g_fc1p + (long)sk * BATCH * 1024;
#pragma unroll
    for (int mi = 0; mi < 4; mi++)
#pragma unroll
        for (int ni = 0; ni < 8; ni++) {
            int m = m_base + mi * 16 + (lane >> 2);
            int n = n0 + n_base + ni * 8 + (lane & 3) * 2;
            *(float2*)&slab[(long)m * 1024 + n] =
                make_float2(acc[mi][ni][0], acc[mi][ni][1]);
            *(float2*)&slab[(long)(m + 8) * 1024 + n] =
                make_float2(acc[mi][ni][2], acc[mi][ni][3]);
        }
}

// ======================= fc2 (fused slab-reduce + relu + fc2) ===================
__global__ __launch_bounds__(256) void k_fc2(const float* __restrict__ fc1b,
                                             const float* __restrict__ w2,
                                             const float* __restrict__ b2,
                                             float* __restrict__ out) {
    __shared__ __align__(16) float hs[1024];
    __shared__ float red[10 * 256];
    int b = blockIdx.x, tid = threadIdx.x;
    for (int j = tid; j < 1024; j += 256) {
        float s = 0.f;
#pragma unroll
        for (int q = 0; q < 16; q++) s += g_fc1p[(long)q * BATCH * 1024 + b * 1024 + j];
        hs[j] = fmaxf(s + fc1b[j], 0.f);
    }
    __syncthreads();
    float p[10];
#pragma unroll
    for (int n = 0; n < 10; n++) p[n] = 0.f;
    for (int j = tid; j < 1024; j += 256) {
        float hv = hs[j];
#pragma unroll
        for (int n = 0; n < 10; n++) p[n] += hv * w2[n * 1024 + j];
    }
#pragma unroll
    for (int n = 0; n < 10; n++) red[n * 256 + tid] = p[n];
    __syncthreads();
    for (int s = 128; s > 0; s >>= 1) {
        if (tid < s) {
#pragma unroll
            for (int n = 0; n < 10; n++) red[n * 256 + tid] += red[n * 256 + tid + s];
        }
        __syncthreads();
    }
    if (tid < 10) out[b * 10 + tid] = red[tid * 256] + b2[tid];
}

// =================================================================================
extern "C" void kernel_launch(void* const* d_in, const int* in_sizes, int n_in,
                              void* d_out, int out_size) {
    const float* x    = (const float*)d_in[0];
    const int*   idx1 = (const int*)d_in[1];
    const int*   idx2 = (const int*)d_in[2];
    const float* w1a  = (const float*)d_in[3];
    const float* b1a  = (const float*)d_in[4];
    const float* w1b  = (const float*)d_in[5];
    const float* b1b  = (const float*)d_in[6];
    const float* w1p  = (const float*)d_in[7];
    const float* b1p  = (const float*)d_in[8];
    const float* w2a  = (const float*)d_in[9];
    const float* b2a  = (const float*)d_in[10];
    const float* w2b  = (const float*)d_in[11];
    const float* b2b  = (const float*)d_in[12];
    const float* w2p  = (const float*)d_in[13];
    const float* b2p  = (const float*)d_in[14];
    const float* fc1w = (const float*)d_in[15];
    const float* fc1b = (const float*)d_in[16];
    const float* fc2w = (const float*)d_in[17];
    const float* fc2b = (const float*)d_in[18];
    float* out = (float*)d_out;

    const int smem_l2   = (64 * 256 + 576 * 16) * 4;           // 102400 (covers knn 93184)
    const int smem_fc1t = 98304;
    cudaFuncSetAttribute(k_l2,   cudaFuncAttributeMaxDynamicSharedMemorySize, smem_l2);
    cudaFuncSetAttribute(k_fc1t, cudaFuncAttributeMaxDynamicSharedMemorySize, smem_fc1t);

    k_repack<<<72, 256>>>(w1a, w1b, w2a, w2b);
    k_l1<<<dim3(BATCH, 2), 128>>>(x, idx1, b1a, b1b, w1p, b1p);
    k_l2<<<dim3(BATCH, 3), 288, smem_l2>>>(idx2, b2a, b2b);
    k_l2_pw<<<BATCH, 256>>>(w2p, b2p);
    k_fc1t<<<dim3(8, 1, 16), 256, smem_fc1t>>>(fc1w);
    k_fc2<<<BATCH, 256>>>(fc1b, fc2w, fc2b, out);
}

// round 10
// speedup vs baseline: 2.3530x; 1.0381x over previous
#include <cuda_runtime.h>
#include <cuda_bf16.h>

typedef unsigned long long ull;
constexpr int BATCH = 256;

// ---------------- scratch (device globals) ----------------
__device__ __align__(16) float g_out1[BATCH * 64 * 256];
__device__ __align__(16) float g_cat2[BATCH * 64 * 256];
__device__ __align__(16) float g_fc1p[16 * BATCH * 1024];
__device__ __align__(16) float g_r1a[1728];
__device__ __align__(16) float g_r1b[1728];
__device__ __align__(16) float g_r2a[18432];
__device__ __align__(16) float g_r2b[18432];   // [k][c][oc] layout
__device__ __align__(16) __nv_bfloat16 g_ahi[BATCH * 32768];
__device__ __align__(16) __nv_bfloat16 g_alo[BATCH * 32768];

// ---------------- f32x2 helpers ----------------
__device__ __forceinline__ ull pack2(float lo, float hi) {
    ull r;
    asm("mov.b64 %0, {%1, %2};" : "=l"(r) : "r"(__float_as_uint(lo)), "r"(__float_as_uint(hi)));
    return r;
}
__device__ __forceinline__ ull packd(float s) { return pack2(s, s); }
__device__ __forceinline__ void fma2(ull& d, ull a, ull b) {
    asm("fma.rn.f32x2 %0, %1, %2, %3;" : "=l"(d) : "l"(a), "l"(b), "l"(d));
}
__device__ __forceinline__ float2 unpk(ull v) {
    unsigned lo, hi;
    asm("mov.b64 {%0, %1}, %2;" : "=r"(lo), "=r"(hi) : "l"(v));
    float2 f; f.x = __uint_as_float(lo); f.y = __uint_as_float(hi);
    return f;
}

// ---------------- mma.sync helpers ----------------
__device__ __forceinline__ unsigned smem_u32(const void* p) {
    unsigned a;
    asm("{ .reg .u64 t; cvta.to.shared.u64 t, %1; cvt.u32.u64 %0, t; }" : "=r"(a) : "l"(p));
    return a;
}
__device__ __forceinline__ void ldsm4(unsigned& r0, unsigned& r1, unsigned& r2, unsigned& r3,
                                      unsigned addr) {
    asm volatile("ldmatrix.sync.aligned.m8n8.x4.shared.b16 {%0,%1,%2,%3}, [%4];"
                 : "=r"(r0), "=r"(r1), "=r"(r2), "=r"(r3) : "r"(addr));
}
__device__ __forceinline__ void mma16816(float* c, const unsigned* a, const unsigned* b) {
    asm volatile(
        "mma.sync.aligned.m16n8k16.row.col.f32.bf16.bf16.f32 "
        "{%0,%1,%2,%3},{%4,%5,%6,%7},{%8,%9},{%0,%1,%2,%3};"
        : "+f"(c[0]), "+f"(c[1]), "+f"(c[2]), "+f"(c[3])
        : "r"(a[0]), "r"(a[1]), "r"(a[2]), "r"(a[3]), "r"(b[0]), "r"(b[1]));
}
__device__ __forceinline__ void cpa16(unsigned dst, const void* src) {
    asm volatile("cp.async.cg.shared.global [%0], [%1], 16;" :: "r"(dst), "l"(src));
}
__device__ __forceinline__ void cpa_commit() { asm volatile("cp.async.commit_group;"); }
__device__ __forceinline__ void cpa_wait0() {
    asm volatile("cp.async.wait_group 0;" ::: "memory");
}
__device__ __forceinline__ void sts128(unsigned addr, uint4 v) {
    asm volatile("st.shared.v4.b32 [%0], {%1,%2,%3,%4};"
                 :: "r"(addr), "r"(v.x), "r"(v.y), "r"(v.z), "r"(v.w));
}
__device__ __forceinline__ unsigned pkbf(float a, float b) {
    __nv_bfloat16 ha = __float2bfloat16(a), hb = __float2bfloat16(b);
    return ((unsigned)__bfloat16_as_ushort(hb) << 16) | __bfloat16_as_ushort(ha);
}
__device__ __forceinline__ void wsplit_store(unsigned hi_base, int row, int c,
                                             float4 a, float4 b) {
    unsigned sw = (unsigned)(row * 64 + ((c ^ ((row >> 1) & 3)) << 4));
    uint4 hi, lo;
    hi.x = pkbf(a.x, a.y); hi.y = pkbf(a.z, a.w);
    hi.z = pkbf(b.x, b.y); hi.w = pkbf(b.z, b.w);
    __nv_bfloat16 t0 = __float2bfloat16(a.x), t1 = __float2bfloat16(a.y);
    __nv_bfloat16 t2 = __float2bfloat16(a.z), t3 = __float2bfloat16(a.w);
    __nv_bfloat16 t4 = __float2bfloat16(b.x), t5 = __float2bfloat16(b.y);
    __nv_bfloat16 t6 = __float2bfloat16(b.z), t7 = __float2bfloat16(b.w);
    lo.x = pkbf(a.x - __bfloat162float(t0), a.y - __bfloat162float(t1));
    lo.y = pkbf(a.z - __bfloat162float(t2), a.w - __bfloat162float(t3));
    lo.z = pkbf(b.x - __bfloat162float(t4), b.y - __bfloat162float(t5));
    lo.w = pkbf(b.z - __bfloat162float(t6), b.w - __bfloat162float(t7));
    sts128(hi_base + sw, hi);
    sts128(hi_base + 8192 + sw, lo);
}

// ---------------- weight repack ----------------
__global__ __launch_bounds__(256) void k_repack(const float* __restrict__ w1a,
                                                const float* __restrict__ w1b,
                                                const float* __restrict__ w2a,
                                                const float* __restrict__ w2b) {
    int i = blockIdx.x * 256 + threadIdx.x;
    if (i < 1728) {
        int oc = i / 108, rest = i % 108;
        g_r1a[rest * 16 + oc] = w1a[i];
        g_r1b[rest * 16 + oc] = w1b[i];
    }
    if (i < 18432) {
        int oc = i / 576, rest = i % 576;
        g_r2a[rest * 32 + oc] = w2a[i];
        int c = rest / 9, k = rest % 9;
        g_r2b[(k * 64 + c) * 32 + oc] = w2b[i];
    }
}

// ======================= Layer 1 FUSED, pixel-split x2 ==========================
__global__ __launch_bounds__(128) void k_l1(const float* __restrict__ x,
                                            const int* __restrict__ idx,
                                            const float* __restrict__ b1a,
                                            const float* __restrict__ b1b,
                                            const float* __restrict__ wp,
                                            const float* __restrict__ bp) {
    __shared__ __align__(16) float xs[12 * 256];
    __shared__ __align__(16) float ss[12 * 64];
    __shared__ float sn[64];
    __shared__ __align__(16) float wsa[1728];
    __shared__ __align__(16) float wsb[1728];
    __shared__ __align__(16) float wsp[64 * 32];
    int b = blockIdx.x, tid = threadIdx.x;
    int p = blockIdx.y * 128 + tid;

    for (int i = tid; i < 12 * 256; i += 128) {
        int cu = i >> 8, t = i & 255;
        int h = t >> 4, w = t & 15;
        int c = cu >> 2, ii = (cu >> 1) & 1, jj = cu & 1;
        xs[i] = x[((b * 3 + c) * 32 + (2 * h + ii)) * 32 + 2 * w + jj];
    }
    for (int i = tid; i < 1728; i += 128) { wsa[i] = g_r1a[i]; wsb[i] = g_r1b[i]; }
    for (int i = tid; i < 64 * 32; i += 128) wsp[i] = wp[i];
    __syncthreads();
    for (int i = tid; i < 12 * 64; i += 128)
        ss[i] = xs[(i >> 6) * 256 + idx[i & 63]];
    __syncthreads();
    if (tid < 64) {
        float s = 0.f;
#pragma unroll
        for (int c = 0; c < 12; c++) { float v = ss[c * 64 + tid]; s += v * v; }
        sn[tid] = s;
    }
    __syncthreads();

    int h = p >> 4, w = p & 15;

    ull acv[8];
#pragma unroll
    for (int o = 0; o < 8; o++) acv[o] = pack2(b1a[2 * o], b1a[2 * o + 1]);
    for (int c = 0; c < 12; c++) {
        float pp[9];
#pragma unroll
        for (int dy = 0; dy < 3; dy++)
#pragma unroll
            for (int dx = 0; dx < 3; dx++) {
                int y = h + dy - 1, xq = w + dx - 1;
                pp[dy * 3 + dx] = (y >= 0 && y < 16 && xq >= 0 && xq < 16)
                                      ? xs[c * 256 + y * 16 + xq] : 0.f;
            }
#pragma unroll
        for (int tap = 0; tap < 9; tap++) {
            ull s2 = packd(pp[tap]);
            const longlong2* wv = (const longlong2*)&wsa[(c * 9 + tap) * 16];
#pragma unroll
            for (int q = 0; q < 4; q++) {
                longlong2 w4 = wv[q];
                fma2(acv[q * 2 + 0], s2, (ull)w4.x);
                fma2(acv[q * 2 + 1], s2, (ull)w4.y);
            }
        }
    }

    float xr[12]; float xn = 0.f;
#pragma unroll
    for (int c = 0; c < 12; c++) { float v = xs[c * 256 + p]; xr[c] = v; xn += v * v; }

    float bd[9]; int bi[9];
#pragma unroll
    for (int k = 0; k < 9; k++) { bd[k] = 3.0e38f; bi[k] = 0; }
    for (int n = 0; n < 64; n++) {
        float dot = 0.f;
#pragma unroll
        for (int c = 0; c < 12; c++) dot += xr[c] * ss[c * 64 + n];
        float d = xn + sn[n] - 2.f * dot;
        if (d < bd[8]) {
            bool placed = false;
#pragma unroll
            for (int j = 8; j > 0; --j) {
                if (!placed) {
                    if (d < bd[j - 1]) { bd[j] = bd[j - 1]; bi[j] = bi[j - 1]; }
                    else { bd[j] = d; bi[j] = n; placed = true; }
                }
            }
            if (!placed) { bd[0] = d; bi[0] = n; }
        }
    }

    ull akn[8];
#pragma unroll
    for (int o = 0; o < 8; o++) akn[o] = pack2(b1b[2 * o], b1b[2 * o + 1]);
#pragma unroll
    for (int c = 0; c < 12; c++) {
#pragma unroll
        for (int k = 0; k < 9; k++) {
            ull s2 = packd(ss[c * 64 + bi[k]]);
            const longlong2* wv = (const longlong2*)&wsb[(c * 9 + k) * 16];
#pragma unroll
            for (int q = 0; q < 4; q++) {
                longlong2 w4 = wv[q];
                fma2(akn[q * 2 + 0], s2, (ull)w4.x);
                fma2(akn[q * 2 + 1], s2, (ull)w4.y);
            }
        }
    }

    ull xv[16];
#pragma unroll
    for (int o = 0; o < 8; o++) {
        float2 v = unpk(acv[o]);
        xv[o] = pack2(fmaxf(v.x, 0.f), fmaxf(v.y, 0.f));
        float2 u = unpk(akn[o]);
        xv[8 + o] = pack2(fmaxf(u.x, 0.f), fmaxf(u.y, 0.f));
    }
    for (int oc = 0; oc < 64; oc++) {
        ull a2 = 0ull;
        const longlong2* wv = (const longlong2*)&wsp[oc * 32];
#pragma unroll
        for (int q = 0; q < 8; q++) {
            longlong2 w4 = wv[q];
            fma2(a2, xv[q * 2 + 0], (ull)w4.x);
            fma2(a2, xv[q * 2 + 1], (ull)w4.y);
        }
        float2 v = unpk(a2);
        g_out1[(b * 64 + oc) * 256 + p] = v.x + v.y + bp[oc];
    }
}

// ============ Layer 2 MERGED: y<2 -> conv oc-half, y==2 -> kNN branch ===========
__global__ __launch_bounds__(288, 2) void k_l2(const int* __restrict__ idx,
                                               const float* __restrict__ ba,
                                               const float* __restrict__ bb) {
    extern __shared__ __align__(16) float sm[];
    int b = blockIdx.x, sel = blockIdx.y, tid = threadIdx.x;

    if (sel < 2) {
        float* xs = sm;
        float* wsh = sm + 64 * 256;
        int oc0 = sel * 16;
        for (int i = tid; i < 64 * 256; i += 288) xs[i] = g_out1[b * 64 * 256 + i];
        for (int i = tid; i < 576 * 16; i += 288) {
            int row = i >> 4, o = i & 15;
            wsh[i] = g_r2a[row * 32 + oc0 + o];
        }
        __syncthreads();
        if (tid < 256) {
            int t = tid, h = t >> 4, w = t & 15;
            ull acc[8];
#pragma unroll
            for (int o = 0; o < 8; o++) acc[o] = pack2(ba[oc0 + 2 * o], ba[oc0 + 2 * o + 1]);
            for (int c = 0; c < 64; c++) {
                float p[9];
#pragma unroll
                for (int dy = 0; dy < 3; dy++)
#pragma unroll
                    for (int dx = 0; dx < 3; dx++) {
                        int y = h + dy - 1, xq = w + dx - 1;
                        p[dy * 3 + dx] = (y >= 0 && y < 16 && xq >= 0 && xq < 16)
                                             ? xs[c * 256 + y * 16 + xq] : 0.f;
                    }
#pragma unroll
                for (int tap = 0; tap < 9; tap++) {
                    ull s2 = packd(p[tap]);
                    const longlong2* wv = (const longlong2*)&wsh[(c * 9 + tap) * 16];
#pragma unroll
                    for (int q = 0; q < 4; q++) {
                        longlong2 w4 = wv[q];
                        fma2(acc[q * 2 + 0], s2, (ull)w4.x);
                        fma2(acc[q * 2 + 1], s2, (ull)w4.y);
                    }
                }
            }
#pragma unroll
            for (int o = 0; o < 8; o++) {
                float2 v = unpk(acc[o]);
                g_cat2[((b * 64 + oc0 + 2 * o) * 256) + t] = fmaxf(v.x, 0.f);
                g_cat2[((b * 64 + oc0 + 2 * o + 1) * 256) + t] = fmaxf(v.y, 0.f);
            }
        }
        return;
    }

    float* ss = sm;              // [n][c], stride 66
    float* Mt = sm + 4224;       // [(k*64+n)][o], stride 33
    float* sn = Mt + 19008;      // 64
    int lane = tid & 31, wid = tid >> 5;

    for (int i = tid; i < 4096; i += 288) {
        int n = i & 63, c = i >> 6;
        ss[n * 66 + c] = g_out1[(b * 64 + c) * 256 + idx[n]];
    }
    __syncthreads();
    if (tid < 64) {
        float s = 0.f;
#pragma unroll 16
        for (int c = 0; c < 64; c++) { float v = ss[tid * 66 + c]; s += v * v; }
        sn[tid] = s;
    }

    {
        int k = wid;
        ull a0[16], a1[16];
#pragma unroll
        for (int j = 0; j < 16; j++) { a0[j] = 0ull; a1[j] = 0ull; }
        const longlong2* wrow = (const longlong2*)(g_r2b + (k * 64) * 32);
        int n0 = lane, n1 = lane + 32;
        for (int c = 0; c < 64; c++) {
            ull s0 = packd(ss[n0 * 66 + c]);
            ull s1 = packd(ss[n1 * 66 + c]);
#pragma unroll
            for (int q = 0; q < 8; q++) {
                longlong2 w4 = wrow[c * 8 + q];
                fma2(a0[q * 2 + 0], s0, (ull)w4.x);
                fma2(a0[q * 2 + 1], s0, (ull)w4.y);
                fma2(a1[q * 2 + 0], s1, (ull)w4.x);
                fma2(a1[q * 2 + 1], s1, (ull)w4.y);
            }
        }
        float* m0 = &Mt[(k * 64 + n0) * 33];
        float* m1 = &Mt[(k * 64 + n1) * 33];
#pragma unroll
        for (int j = 0; j < 16; j++) {
            float2 v0 = unpk(a0[j]); m0[2 * j] = v0.x; m0[2 * j + 1] = v0.y;
            float2 v1 = unpk(a1[j]); m1[2 * j] = v1.x; m1[2 * j + 1] = v1.y;
        }
    }
    __syncthreads();

    if (tid < 256) {
        int t = tid;
        ull xr2[32]; float xn = 0.f;
#pragma unroll
        for (int c2 = 0; c2 < 32; c2++) {
            float f0 = g_out1[(b * 64 + 2 * c2) * 256 + t];
            float f1 = g_out1[(b * 64 + 2 * c2 + 1) * 256 + t];
            xn += f0 * f0 + f1 * f1;
            xr2[c2] = pack2(f0, f1);
        }

        float bd[9]; int bi[9];
#pragma unroll
        for (int k = 0; k < 9; k++) { bd[k] = 3.0e38f; bi[k] = 0; }
        for (int n = 0; n < 64; n++) {
            const ull* sp = (const ull*)&ss[n * 66];
            ull d2 = 0ull;
#pragma unroll
            for (int j = 0; j < 32; j++) fma2(d2, xr2[j], sp[j]);
            float2 dv = unpk(d2);
            float d = xn + sn[n] - 2.f * (dv.x + dv.y);
            if (d < bd[8]) {
                bool placed = false;
#pragma unroll
                for (int j = 8; j > 0; --j) {
                    if (!placed) {
                        if (d < bd[j - 1]) { bd[j] = bd[j - 1]; bi[j] = bi[j - 1]; }
                        else { bd[j] = d; bi[j] = n; placed = true; }
                    }
                }
                if (!placed) { bd[0] = d; bi[0] = n; }
            }
        }

#pragma unroll
        for (int half = 0; half < 2; half++) {
            float acc[16];
#pragma unroll
            for (int o = 0; o < 16; o++) acc[o] = bb[half * 16 + o];
#pragma unroll
            for (int k = 0; k < 9; k++) {
                const float* mrow = &Mt[(k * 64 + bi[k]) * 33 + half * 16];
#pragma unroll
                for (int o = 0; o < 16; o++) acc[o] += mrow[o];
            }
#pragma unroll
            for (int o = 0; o < 16; o++)
                g_cat2[((b * 64 + 32 + half * 16 + o) * 256) + t] = fmaxf(acc[o], 0.f);
        }
    }
}

// ======== Layer 2: 1x1 conv (64->128) + shuffle/flatten + bf16 hi/lo split ======
__global__ __launch_bounds__(256) void k_l2_pw(const float* __restrict__ wp,
                                               const float* __restrict__ bp) {
    __shared__ __align__(16) float ws[128 * 64];
    int b = blockIdx.x, tid = threadIdx.x;
    for (int i = tid; i < 128 * 64; i += 256) ws[i] = wp[i];
    __syncthreads();
    ull xv[32];
#pragma unroll
    for (int c2 = 0; c2 < 32; c2++) {
        float f0 = g_cat2[(b * 64 + 2 * c2) * 256 + tid];
        float f1 = g_cat2[(b * 64 + 2 * c2 + 1) * 256 + tid];
        xv[c2] = pack2(f0, f1);
    }
    int h = tid >> 4, w = tid & 15;
    for (int oc = 0; oc < 128; oc++) {
        ull a2 = 0ull;
        const longlong2* wv = (const longlong2*)&ws[oc * 64];
#pragma unroll
        for (int q = 0; q < 16; q++) {
            longlong2 w4 = wv[q];
            fma2(a2, xv[q * 2 + 0], (ull)w4.x);
            fma2(a2, xv[q * 2 + 1], (ull)w4.y);
        }
        float2 v = unpk(a2);
        float acc = v.x + v.y + bp[oc];
        int cp = oc >> 2, ii = (oc >> 1) & 1, jj = oc & 1;
        long pos = (long)b * 32768 + cp * 1024 + (2 * h + ii) * 32 + 2 * w + jj;
        __nv_bfloat16 hi = __float2bfloat16(acc);
        g_ahi[pos] = hi;
        g_alo[pos] = __float2bfloat16(acc - __bfloat162float(hi));
    }
}

// ======================= fc1: bf16 split GEMM via mma.sync ======================
// 512 threads, 16 warps (4m x 4n), warp tile 64x32. CTA tile M=256 N=128 kc=32.
// Stage: Ah 16K | Al 16K | Wh 8K | Wl 8K = 48K; x2 = 96K.
__global__ __launch_bounds__(512) void k_fc1t(const float* __restrict__ W) {
    extern __shared__ __align__(16) char smem[];
    unsigned sbase = smem_u32(smem);
    int tid = threadIdx.x, lane = tid & 31, warp = tid >> 5;
    int n0 = blockIdx.x * 128, sk = blockIdx.z;
    long kbase = (long)sk * 2048;

    int m_base = (warp & 3) * 64;
    int n_base = (warp >> 2) * 32;

    // A fill: 2 chunks/thread (1024 chunks: row=q>>2, col=q&3)
    int aq[2], ac[2];
#pragma unroll
    for (int j = 0; j < 2; j++) { int q = tid + j * 512; aq[j] = q >> 2; ac[j] = q & 3; }
    // W fill: 1 chunk-pair/thread (512: row=tid>>2, col=tid&3 of 8 floats)
    int wr = tid >> 2, wc = tid & 3;

    float acc[4][4][4];
#pragma unroll
    for (int i = 0; i < 4; i++)
#pragma unroll
        for (int j = 0; j < 4; j++)
#pragma unroll
            for (int q = 0; q < 4; q++) acc[i][j][q] = 0.f;

    const float* wgp = W + (long)(n0 + wr) * 32768 + kbase + wc * 8;

    // ---- prologue ----
    float4 w0a = *(const float4*)(wgp);
    float4 w0b = *(const float4*)(wgp + 4);
#pragma unroll
    for (int j = 0; j < 2; j++) {
        int r = aq[j], c = ac[j];
        unsigned sw = (unsigned)(r * 64 + ((c ^ ((r >> 1) & 3)) << 4));
        cpa16(sbase + sw, g_ahi + (long)r * 32768 + kbase + c * 8);
        cpa16(sbase + 16384 + sw, g_alo + (long)r * 32768 + kbase + c * 8);
    }
    cpa_commit();
    wsplit_store(sbase + 32768, wr, wc, w0a, w0b);

    int ri = lane & 7, mat = lane >> 3;

    for (int it = 0; it < 64; it++) {
        int st = it & 1;
        unsigned stb = sbase + st * 49152u;
        cpa_wait0();
        __syncthreads();

        float4 wna, wnb;
        if (it < 63) {
            long ko = kbase + (it + 1) * 32;
            wna = *(const float4*)(wgp + (it + 1) * 32);
            wnb = *(const float4*)(wgp + (it + 1) * 32 + 4);
            unsigned nb = sbase + (st ^ 1) * 49152u;
#pragma unroll
            for (int j = 0; j < 2; j++) {
                int r = aq[j], c = ac[j];
                unsigned sw = (unsigned)(r * 64 + ((c ^ ((r >> 1) & 3)) << 4));
                cpa16(nb + sw, g_ahi + (long)r * 32768 + ko + c * 8);
                cpa16(nb + 16384 + sw, g_alo + (long)r * 32768 + ko + c * 8);
            }
            cpa_commit();
        }

#pragma unroll
        for (int k16 = 0; k16 < 2; k16++) {
            unsigned af[4][4], bh[4][2], bl[4][2];
            // B frags (hi+lo): 2 ldsm4 pairs covering n_base..n_base+31
#pragma unroll
            for (int ng = 0; ng < 2; ng++) {
                int row = n_base + ng * 16 + ri + ((mat >> 1) << 3);
                int c = k16 * 2 + (mat & 1);
                unsigned bd = stb + 32768 + row * 64 + ((c ^ ((row >> 1) & 3)) << 4);
                unsigned r0, r1, r2, r3;
                ldsm4(r0, r1, r2, r3, bd);
                bh[2 * ng][0] = r0; bh[2 * ng][1] = r1;
                bh[2 * ng + 1][0] = r2; bh[2 * ng + 1][1] = r3;
                ldsm4(r0, r1, r2, r3, bd + 8192);
                bl[2 * ng][0] = r0; bl[2 * ng][1] = r1;
                bl[2 * ng + 1][0] = r2; bl[2 * ng + 1][1] = r3;
            }
            // A-hi frags, terms 1+2
#pragma unroll
            for (int mi = 0; mi < 4; mi++) {
                int row = m_base + mi * 16 + ri + ((mat & 1) << 3);
                int c = k16 * 2 + (mat >> 1);
                unsigned ad = stb + row * 64 + ((c ^ ((row >> 1) & 3)) << 4);
                ldsm4(af[mi][0], af[mi][1], af[mi][2], af[mi][3], ad);
            }
#pragma unroll
            for (int mi = 0; mi < 4; mi++)
#pragma unroll
                for (int ni = 0; ni < 4; ni++) {
                    mma16816(acc[mi][ni], af[mi], bh[ni]);
                    mma16816(acc[mi][ni], af[mi], bl[ni]);
                }
            // A-lo frags (reuse regs), term 3
#pragma unroll
            for (int mi = 0; mi < 4; mi++) {
                int row = m_base + mi * 16 + ri + ((mat & 1) << 3);
                int c = k16 * 2 + (mat >> 1);
                unsigned ad = stb + 16384 + row * 64 + ((c ^ ((row >> 1) & 3)) << 4);
                ldsm4(af[mi][0], af[mi][1], af[mi][2], af[mi][3], ad);
            }
#pragma unroll
            for (int mi = 0; mi < 4; mi++)
#pragma unroll
                for (int ni = 0; ni < 4; ni++)
                    mma16816(acc[mi][ni], af[mi], bh[ni]);
        }

        if (it < 63) {
            unsigned nb = sbase + (st ^ 1) * 49152u;
            wsplit_store(nb + 32768, wr, wc, wna, wnb);
        }
    }

    float* slab = g_fc1p + (long)sk * BATCH * 1024;
#pragma unroll
    for (int mi = 0; mi < 4; mi++)
#pragma unroll
        for (int ni = 0; ni < 4; ni++) {
            int m = m_base + mi * 16 + (lane >> 2);
            int n = n0 + n_base + ni * 8 + (lane & 3) * 2;
            *(float2*)&slab[(long)m * 1024 + n] =
                make_float2(acc[mi][ni][0], acc[mi][ni][1]);
            *(float2*)&slab[(long)(m + 8) * 1024 + n] =
                make_float2(acc[mi][ni][2], acc[mi][ni][3]);
        }
}

// ======================= fc2 (fused slab-reduce + relu + fc2) ===================
__global__ __launch_bounds__(256) void k_fc2(const float* __restrict__ fc1b,
                                             const float* __restrict__ w2,
                                             const float* __restrict__ b2,
                                             float* __restrict__ out) {
    __shared__ __align__(16) float hs[1024];
    __shared__ float red[10 * 256];
    int b = blockIdx.x, tid = threadIdx.x;
    for (int j = tid; j < 1024; j += 256) {
        float s = 0.f;
#pragma unroll
        for (int q = 0; q < 16; q++) s += g_fc1p[(long)q * BATCH * 1024 + b * 1024 + j];
        hs[j] = fmaxf(s + fc1b[j], 0.f);
    }
    __syncthreads();
    float p[10];
#pragma unroll
    for (int n = 0; n < 10; n++) p[n] = 0.f;
    for (int j = tid; j < 1024; j += 256) {
        float hv = hs[j];
#pragma unroll
        for (int n = 0; n < 10; n++) p[n] += hv * w2[n * 1024 + j];
    }
#pragma unroll
    for (int n = 0; n < 10; n++) red[n * 256 + tid] = p[n];
    __syncthreads();
    for (int s = 128; s > 0; s >>= 1) {
        if (tid < s) {
#pragma unroll
            for (int n = 0; n < 10; n++) red[n * 256 + tid] += red[n * 256 + tid + s];
        }
        __syncthreads();
    }
    if (tid < 10) out[b * 10 + tid] = red[tid * 256] + b2[tid];
}

// =================================================================================
extern "C" void kernel_launch(void* const* d_in, const int* in_sizes, int n_in,
                              void* d_out, int out_size) {
    const float* x    = (const float*)d_in[0];
    const int*   idx1 = (const int*)d_in[1];
    const int*   idx2 = (const int*)d_in[2];
    const float* w1a  = (const float*)d_in[3];
    const float* b1a  = (const float*)d_in[4];
    const float* w1b  = (const float*)d_in[5];
    const float* b1b  = (const float*)d_in[6];
    const float* w1p  = (const float*)d_in[7];
    const float* b1p  = (const float*)d_in[8];
    const float* w2a  = (const float*)d_in[9];
    const float* b2a  = (const float*)d_in[10];
    const float* w2b  = (const float*)d_in[11];
    const float* b2b  = (const float*)d_in[12];
    const float* w2p  = (const float*)d_in[13];
    const float* b2p  = (const float*)d_in[14];
    const float* fc1w = (const float*)d_in[15];
    const float* fc1b = (const float*)d_in[16];
    const float* fc2w = (const float*)d_in[17];
    const float* fc2b = (const float*)d_in[18];
    float* out = (float*)d_out;

    const int smem_l2   = (64 * 256 + 576 * 16) * 4;
    const int smem_fc1t = 98304;
    cudaFuncSetAttribute(k_l2,   cudaFuncAttributeMaxDynamicSharedMemorySize, smem_l2);
    cudaFuncSetAttribute(k_fc1t, cudaFuncAttributeMaxDynamicSharedMemorySize, smem_fc1t);

    k_repack<<<72, 256>>>(w1a, w1b, w2a, w2b);
    k_l1<<<dim3(BATCH, 2), 128>>>(x, idx1, b1a, b1b, w1p, b1p);
    k_l2<<<dim3(BATCH, 3), 288, smem_l2>>>(idx2, b2a, b2b);
    k_l2_pw<<<BATCH, 256>>>(w2p, b2p);
    k_fc1t<<<dim3(8, 1, 16), 512, smem_fc1t>>>(fc1w);
    k_fc2<<<BATCH, 256>>>(fc1b, fc2w, fc2b, out);
}

// round 11
// speedup vs baseline: 2.4298x; 1.0326x over previous
#include <cuda_runtime.h>
#include <cuda_bf16.h>

typedef unsigned long long ull;
constexpr int BATCH = 256;

// ---------------- scratch (device globals) ----------------
__device__ __align__(16) float g_out1[BATCH * 64 * 256];
__device__ __align__(16) float g_fc1p[16 * BATCH * 1024];
__device__ __align__(16) float g_r1a[1728];
__device__ __align__(16) float g_r1b[1728];
__device__ __align__(16) float g_r2a[18432];
__device__ __align__(16) float g_r2b[18432];   // [k][c][oc]
__device__ __align__(16) __nv_bfloat16 g_c2h[BATCH * 16384];  // cat2 hi, [t][c]
__device__ __align__(16) __nv_bfloat16 g_c2l[BATCH * 16384];  // cat2 lo
__device__ __align__(16) __nv_bfloat16 g_wph[8192];           // w2p hi [oc][c]
__device__ __align__(16) __nv_bfloat16 g_wpl[8192];
__device__ __align__(16) __nv_bfloat16 g_ahi[BATCH * 32768];
__device__ __align__(16) __nv_bfloat16 g_alo[BATCH * 32768];

// ---------------- f32x2 helpers ----------------
__device__ __forceinline__ ull pack2(float lo, float hi) {
    ull r;
    asm("mov.b64 %0, {%1, %2};" : "=l"(r) : "r"(__float_as_uint(lo)), "r"(__float_as_uint(hi)));
    return r;
}
__device__ __forceinline__ ull packd(float s) { return pack2(s, s); }
__device__ __forceinline__ void fma2(ull& d, ull a, ull b) {
    asm("fma.rn.f32x2 %0, %1, %2, %3;" : "=l"(d) : "l"(a), "l"(b), "l"(d));
}
__device__ __forceinline__ float2 unpk(ull v) {
    unsigned lo, hi;
    asm("mov.b64 {%0, %1}, %2;" : "=r"(lo), "=r"(hi) : "l"(v));
    float2 f; f.x = __uint_as_float(lo); f.y = __uint_as_float(hi);
    return f;
}

// ---------------- mma.sync helpers ----------------
__device__ __forceinline__ unsigned smem_u32(const void* p) {
    unsigned a;
    asm("{ .reg .u64 t; cvta.to.shared.u64 t, %1; cvt.u32.u64 %0, t; }" : "=r"(a) : "l"(p));
    return a;
}
__device__ __forceinline__ void ldsm4(unsigned& r0, unsigned& r1, unsigned& r2, unsigned& r3,
                                      unsigned addr) {
    asm volatile("ldmatrix.sync.aligned.m8n8.x4.shared.b16 {%0,%1,%2,%3}, [%4];"
                 : "=r"(r0), "=r"(r1), "=r"(r2), "=r"(r3) : "r"(addr));
}
__device__ __forceinline__ void mma16816(float* c, const unsigned* a, const unsigned* b) {
    asm volatile(
        "mma.sync.aligned.m16n8k16.row.col.f32.bf16.bf16.f32 "
        "{%0,%1,%2,%3},{%4,%5,%6,%7},{%8,%9},{%0,%1,%2,%3};"
        : "+f"(c[0]), "+f"(c[1]), "+f"(c[2]), "+f"(c[3])
        : "r"(a[0]), "r"(a[1]), "r"(a[2]), "r"(a[3]), "r"(b[0]), "r"(b[1]));
}
__device__ __forceinline__ void cpa16(unsigned dst, const void* src) {
    asm volatile("cp.async.cg.shared.global [%0], [%1], 16;" :: "r"(dst), "l"(src));
}
__device__ __forceinline__ void cpa_commit() { asm volatile("cp.async.commit_group;"); }
__device__ __forceinline__ void cpa_wait0() {
    asm volatile("cp.async.wait_group 0;" ::: "memory");
}
__device__ __forceinline__ void cpa_wait1() {
    asm volatile("cp.async.wait_group 1;" ::: "memory");
}
__device__ __forceinline__ void sts128(unsigned addr, uint4 v) {
    asm volatile("st.shared.v4.b32 [%0], {%1,%2,%3,%4};"
                 :: "r"(addr), "r"(v.x), "r"(v.y), "r"(v.z), "r"(v.w));
}
__device__ __forceinline__ unsigned pkbf(float a, float b) {
    __nv_bfloat16 ha = __float2bfloat16(a), hb = __float2bfloat16(b);
    return ((unsigned)__bfloat16_as_ushort(hb) << 16) | __bfloat16_as_ushort(ha);
}
__device__ __forceinline__ void wsplit_store(unsigned hi_base, int row, int c,
                                             float4 a, float4 b) {
    unsigned sw = (unsigned)(row * 64 + ((c ^ ((row >> 1) & 3)) << 4));
    uint4 hi, lo;
    hi.x = pkbf(a.x, a.y); hi.y = pkbf(a.z, a.w);
    hi.z = pkbf(b.x, b.y); hi.w = pkbf(b.z, b.w);
    __nv_bfloat16 t0 = __float2bfloat16(a.x), t1 = __float2bfloat16(a.y);
    __nv_bfloat16 t2 = __float2bfloat16(a.z), t3 = __float2bfloat16(a.w);
    __nv_bfloat16 t4 = __float2bfloat16(b.x), t5 = __float2bfloat16(b.y);
    __nv_bfloat16 t6 = __float2bfloat16(b.z), t7 = __float2bfloat16(b.w);
    lo.x = pkbf(a.x - __bfloat162float(t0), a.y - __bfloat162float(t1));
    lo.y = pkbf(a.z - __bfloat162float(t2), a.w - __bfloat162float(t3));
    lo.z = pkbf(b.x - __bfloat162float(t4), b.y - __bfloat162float(t5));
    lo.w = pkbf(b.z - __bfloat162float(t6), b.w - __bfloat162float(t7));
    sts128(hi_base + sw, hi);
    sts128(hi_base + 8192 + sw, lo);
}
// relu'd pair -> bf16 hi/lo packed words into cat2 planes
__device__ __forceinline__ void c2_store(long base, float r0, float r1) {
    __nv_bfloat16 h0 = __float2bfloat16(r0), h1 = __float2bfloat16(r1);
    *(unsigned*)&g_c2h[base] = pkbf(r0, r1);
    *(unsigned*)&g_c2l[base] = pkbf(r0 - __bfloat162float(h0), r1 - __bfloat162float(h1));
}

// ---------------- weight repack ----------------
__global__ __launch_bounds__(256) void k_repack(const float* __restrict__ w1a,
                                                const float* __restrict__ w1b,
                                                const float* __restrict__ w2a,
                                                const float* __restrict__ w2b,
                                                const float* __restrict__ w2p) {
    int i = blockIdx.x * 256 + threadIdx.x;
    if (i < 1728) {
        int oc = i / 108, rest = i % 108;
        g_r1a[rest * 16 + oc] = w1a[i];
        g_r1b[rest * 16 + oc] = w1b[i];
    }
    if (i < 8192) {
        float v = w2p[i];
        __nv_bfloat16 h = __float2bfloat16(v);
        g_wph[i] = h;
        g_wpl[i] = __float2bfloat16(v - __bfloat162float(h));
    }
    if (i < 18432) {
        int oc = i / 576, rest = i % 576;
        g_r2a[rest * 32 + oc] = w2a[i];
        int c = rest / 9, k = rest % 9;
        g_r2b[(k * 64 + c) * 32 + oc] = w2b[i];
    }
}

// ======================= Layer 1 FUSED, pixel-split x2 ==========================
__global__ __launch_bounds__(128) void k_l1(const float* __restrict__ x,
                                            const int* __restrict__ idx,
                                            const float* __restrict__ b1a,
                                            const float* __restrict__ b1b,
                                            const float* __restrict__ wp,
                                            const float* __restrict__ bp) {
    __shared__ __align__(16) float xs[12 * 256];
    __shared__ __align__(16) float ss[12 * 64];
    __shared__ float sn[64];
    __shared__ __align__(16) float wsa[1728];
    __shared__ __align__(16) float wsb[1728];
    __shared__ __align__(16) float wsp[64 * 32];
    int b = blockIdx.x, tid = threadIdx.x;
    int p = blockIdx.y * 128 + tid;

    for (int i = tid; i < 12 * 256; i += 128) {
        int cu = i >> 8, t = i & 255;
        int h = t >> 4, w = t & 15;
        int c = cu >> 2, ii = (cu >> 1) & 1, jj = cu & 1;
        xs[i] = x[((b * 3 + c) * 32 + (2 * h + ii)) * 32 + 2 * w + jj];
    }
    for (int i = tid; i < 1728; i += 128) { wsa[i] = g_r1a[i]; wsb[i] = g_r1b[i]; }
    for (int i = tid; i < 64 * 32; i += 128) wsp[i] = wp[i];
    __syncthreads();
    for (int i = tid; i < 12 * 64; i += 128)
        ss[i] = xs[(i >> 6) * 256 + idx[i & 63]];
    __syncthreads();
    if (tid < 64) {
        float s = 0.f;
#pragma unroll
        for (int c = 0; c < 12; c++) { float v = ss[c * 64 + tid]; s += v * v; }
        sn[tid] = s;
    }
    __syncthreads();

    int h = p >> 4, w = p & 15;

    ull acv[8];
#pragma unroll
    for (int o = 0; o < 8; o++) acv[o] = pack2(b1a[2 * o], b1a[2 * o + 1]);
    for (int c = 0; c < 12; c++) {
        float pp[9];
#pragma unroll
        for (int dy = 0; dy < 3; dy++)
#pragma unroll
            for (int dx = 0; dx < 3; dx++) {
                int y = h + dy - 1, xq = w + dx - 1;
                pp[dy * 3 + dx] = (y >= 0 && y < 16 && xq >= 0 && xq < 16)
                                      ? xs[c * 256 + y * 16 + xq] : 0.f;
            }
#pragma unroll
        for (int tap = 0; tap < 9; tap++) {
            ull s2 = packd(pp[tap]);
            const longlong2* wv = (const longlong2*)&wsa[(c * 9 + tap) * 16];
#pragma unroll
            for (int q = 0; q < 4; q++) {
                longlong2 w4 = wv[q];
                fma2(acv[q * 2 + 0], s2, (ull)w4.x);
                fma2(acv[q * 2 + 1], s2, (ull)w4.y);
            }
        }
    }

    float xr[12]; float xn = 0.f;
#pragma unroll
    for (int c = 0; c < 12; c++) { float v = xs[c * 256 + p]; xr[c] = v; xn += v * v; }

    float bd[9]; int bi[9];
#pragma unroll
    for (int k = 0; k < 9; k++) { bd[k] = 3.0e38f; bi[k] = 0; }
    for (int n = 0; n < 64; n++) {
        float dot = 0.f;
#pragma unroll
        for (int c = 0; c < 12; c++) dot += xr[c] * ss[c * 64 + n];
        float d = xn + sn[n] - 2.f * dot;
        if (d < bd[8]) {
            bool placed = false;
#pragma unroll
            for (int j = 8; j > 0; --j) {
                if (!placed) {
                    if (d < bd[j - 1]) { bd[j] = bd[j - 1]; bi[j] = bi[j - 1]; }
                    else { bd[j] = d; bi[j] = n; placed = true; }
                }
            }
            if (!placed) { bd[0] = d; bi[0] = n; }
        }
    }

    ull akn[8];
#pragma unroll
    for (int o = 0; o < 8; o++) akn[o] = pack2(b1b[2 * o], b1b[2 * o + 1]);
#pragma unroll
    for (int c = 0; c < 12; c++) {
#pragma unroll
        for (int k = 0; k < 9; k++) {
            ull s2 = packd(ss[c * 64 + bi[k]]);
            const longlong2* wv = (const longlong2*)&wsb[(c * 9 + k) * 16];
#pragma unroll
            for (int q = 0; q < 4; q++) {
                longlong2 w4 = wv[q];
                fma2(akn[q * 2 + 0], s2, (ull)w4.x);
                fma2(akn[q * 2 + 1], s2, (ull)w4.y);
            }
        }
    }

    ull xv[16];
#pragma unroll
    for (int o = 0; o < 8; o++) {
        float2 v = unpk(acv[o]);
        xv[o] = pack2(fmaxf(v.x, 0.f), fmaxf(v.y, 0.f));
        float2 u = unpk(akn[o]);
        xv[8 + o] = pack2(fmaxf(u.x, 0.f), fmaxf(u.y, 0.f));
    }
    for (int oc = 0; oc < 64; oc++) {
        ull a2 = 0ull;
        const longlong2* wv = (const longlong2*)&wsp[oc * 32];
#pragma unroll
        for (int q = 0; q < 8; q++) {
            longlong2 w4 = wv[q];
            fma2(a2, xv[q * 2 + 0], (ull)w4.x);
            fma2(a2, xv[q * 2 + 1], (ull)w4.y);
        }
        float2 v = unpk(a2);
        g_out1[(b * 64 + oc) * 256 + p] = v.x + v.y + bp[oc];
    }
}

// ============ Layer 2 MERGED: y<2 -> conv oc-half, y==2 -> kNN branch ===========
// Outputs cat2 as bf16 hi/lo planes in [t][c] layout for the tensor-core pw.
__global__ __launch_bounds__(288, 2) void k_l2(const int* __restrict__ idx,
                                               const float* __restrict__ ba,
                                               const float* __restrict__ bb) {
    extern __shared__ __align__(16) float sm[];
    int b = blockIdx.x, sel = blockIdx.y, tid = threadIdx.x;

    if (sel < 2) {
        float* xs = sm;
        float* wsh = sm + 64 * 256;
        int oc0 = sel * 16;
        for (int i = tid; i < 64 * 256; i += 288) xs[i] = g_out1[b * 64 * 256 + i];
        for (int i = tid; i < 576 * 16; i += 288) {
            int row = i >> 4, o = i & 15;
            wsh[i] = g_r2a[row * 32 + oc0 + o];
        }
        __syncthreads();
        if (tid < 256) {
            int t = tid, h = t >> 4, w = t & 15;
            ull acc[8];
#pragma unroll
            for (int o = 0; o < 8; o++) acc[o] = pack2(ba[oc0 + 2 * o], ba[oc0 + 2 * o + 1]);
            for (int c = 0; c < 64; c++) {
                float p[9];
#pragma unroll
                for (int dy = 0; dy < 3; dy++)
#pragma unroll
                    for (int dx = 0; dx < 3; dx++) {
                        int y = h + dy - 1, xq = w + dx - 1;
                        p[dy * 3 + dx] = (y >= 0 && y < 16 && xq >= 0 && xq < 16)
                                             ? xs[c * 256 + y * 16 + xq] : 0.f;
                    }
#pragma unroll
                for (int tap = 0; tap < 9; tap++) {
                    ull s2 = packd(p[tap]);
                    const longlong2* wv = (const longlong2*)&wsh[(c * 9 + tap) * 16];
#pragma unroll
                    for (int q = 0; q < 4; q++) {
                        longlong2 w4 = wv[q];
                        fma2(acc[q * 2 + 0], s2, (ull)w4.x);
                        fma2(acc[q * 2 + 1], s2, (ull)w4.y);
                    }
                }
            }
#pragma unroll
            for (int o = 0; o < 8; o++) {
                float2 v = unpk(acc[o]);
                c2_store((long)b * 16384 + t * 64 + oc0 + 2 * o,
                         fmaxf(v.x, 0.f), fmaxf(v.y, 0.f));
            }
        }
        return;
    }

    float* ss = sm;              // [n][c], stride 66
    float* Mt = sm + 4224;       // [(k*64+n)][o], stride 33
    float* sn = Mt + 19008;      // 64
    int lane = tid & 31, wid = tid >> 5;

    for (int i = tid; i < 4096; i += 288) {
        int n = i & 63, c = i >> 6;
        ss[n * 66 + c] = g_out1[(b * 64 + c) * 256 + idx[n]];
    }
    __syncthreads();
    if (tid < 64) {
        float s = 0.f;
#pragma unroll 16
        for (int c = 0; c < 64; c++) { float v = ss[tid * 66 + c]; s += v * v; }
        sn[tid] = s;
    }

    {
        int k = wid;
        ull a0[16], a1[16];
#pragma unroll
        for (int j = 0; j < 16; j++) { a0[j] = 0ull; a1[j] = 0ull; }
        const longlong2* wrow = (const longlong2*)(g_r2b + (k * 64) * 32);
        int n0 = lane, n1 = lane + 32;
        for (int c = 0; c < 64; c++) {
            ull s0 = packd(ss[n0 * 66 + c]);
            ull s1 = packd(ss[n1 * 66 + c]);
#pragma unroll
            for (int q = 0; q < 8; q++) {
                longlong2 w4 = wrow[c * 8 + q];
                fma2(a0[q * 2 + 0], s0, (ull)w4.x);
                fma2(a0[q * 2 + 1], s0, (ull)w4.y);
                fma2(a1[q * 2 + 0], s1, (ull)w4.x);
                fma2(a1[q * 2 + 1], s1, (ull)w4.y);
            }
        }
        float* m0 = &Mt[(k * 64 + n0) * 33];
        float* m1 = &Mt[(k * 64 + n1) * 33];
#pragma unroll
        for (int j = 0; j < 16; j++) {
            float2 v0 = unpk(a0[j]); m0[2 * j] = v0.x; m0[2 * j + 1] = v0.y;
            float2 v1 = unpk(a1[j]); m1[2 * j] = v1.x; m1[2 * j + 1] = v1.y;
        }
    }
    __syncthreads();

    if (tid < 256) {
        int t = tid;
        ull xr2[32]; float xn = 0.f;
#pragma unroll
        for (int c2 = 0; c2 < 32; c2++) {
            float f0 = g_out1[(b * 64 + 2 * c2) * 256 + t];
            float f1 = g_out1[(b * 64 + 2 * c2 + 1) * 256 + t];
            xn += f0 * f0 + f1 * f1;
            xr2[c2] = pack2(f0, f1);
        }

        float bd[9]; int bi[9];
#pragma unroll
        for (int k = 0; k < 9; k++) { bd[k] = 3.0e38f; bi[k] = 0; }
        for (int n = 0; n < 64; n++) {
            const ull* sp = (const ull*)&ss[n * 66];
            ull d2 = 0ull;
#pragma unroll
            for (int j = 0; j < 32; j++) fma2(d2, xr2[j], sp[j]);
            float2 dv = unpk(d2);
            float d = xn + sn[n] - 2.f * (dv.x + dv.y);
            if (d < bd[8]) {
                bool placed = false;
#pragma unroll
                for (int j = 8; j > 0; --j) {
                    if (!placed) {
                        if (d < bd[j - 1]) { bd[j] = bd[j - 1]; bi[j] = bi[j - 1]; }
                        else { bd[j] = d; bi[j] = n; placed = true; }
                    }
                }
                if (!placed) { bd[0] = d; bi[0] = n; }
            }
        }

#pragma unroll
        for (int half = 0; half < 2; half++) {
            float acc[16];
#pragma unroll
            for (int o = 0; o < 16; o++) acc[o] = bb[half * 16 + o];
#pragma unroll
            for (int k = 0; k < 9; k++) {
                const float* mrow = &Mt[(k * 64 + bi[k]) * 33 + half * 16];
#pragma unroll
                for (int o = 0; o < 16; o++) acc[o] += mrow[o];
            }
#pragma unroll
            for (int j = 0; j < 8; j++)
                c2_store((long)b * 16384 + t * 64 + 32 + half * 16 + 2 * j,
                         fmaxf(acc[2 * j], 0.f), fmaxf(acc[2 * j + 1], 0.f));
        }
    }
}

// ======== Layer 2 pw as bf16 split mma: C[128][256] = W[128x64] * cat2 ==========
// smem: Bh 32K | Bl 32K | Ah 16K | Al 16K = 96K. 128B rows, chunk^=(row&7).
__global__ __launch_bounds__(256) void k_l2_pw(const float* __restrict__ bp) {
    extern __shared__ __align__(16) char smem[];
    unsigned sb = smem_u32(smem);
    int b = blockIdx.x, tid = threadIdx.x, lane = tid & 31, warp = tid >> 5;

    // load B planes (cat2 [t][c]): 2048 chunks each
#pragma unroll
    for (int j = 0; j < 8; j++) {
        int q = tid + j * 256;
        int row = q >> 3, ch = q & 7;
        unsigned dst = sb + row * 128 + ((ch ^ (row & 7)) << 4);
        cpa16(dst, g_c2h + (long)b * 16384 + row * 64 + ch * 8);
        cpa16(dst + 32768, g_c2l + (long)b * 16384 + row * 64 + ch * 8);
    }
    // load A planes (weights [oc][c]): 1024 chunks each
#pragma unroll
    for (int j = 0; j < 4; j++) {
        int q = tid + j * 256;
        int row = q >> 3, ch = q & 7;
        unsigned dst = sb + 65536 + row * 128 + ((ch ^ (row & 7)) << 4);
        cpa16(dst, g_wph + row * 64 + ch * 8);
        cpa16(dst + 16384, g_wpl + row * 64 + ch * 8);
    }
    cpa_commit();
    cpa_wait0();
    __syncthreads();

    int m_base = (warp & 1) * 64;       // 2 m groups
    int n_base = (warp >> 1) * 64;      // 4 n groups
    int ri = lane & 7, mat = lane >> 3;

    float acc[4][8][4];
#pragma unroll
    for (int i = 0; i < 4; i++)
#pragma unroll
        for (int j = 0; j < 8; j++)
#pragma unroll
            for (int q = 0; q < 4; q++) acc[i][j][q] = 0.f;

#pragma unroll
    for (int kk = 0; kk < 4; kk++) {
        unsigned af[4][4], bh[8][2], bl[8][2];
#pragma unroll
        for (int ng = 0; ng < 4; ng++) {
            int row = n_base + ng * 16 + ri + ((mat >> 1) << 3);
            int ch = kk * 2 + (mat & 1);
            unsigned bd_ = sb + row * 128 + ((ch ^ (row & 7)) << 4);
            unsigned r0, r1, r2, r3;
            ldsm4(r0, r1, r2, r3, bd_);
            bh[2 * ng][0] = r0; bh[2 * ng][1] = r1;
            bh[2 * ng + 1][0] = r2; bh[2 * ng + 1][1] = r3;
            ldsm4(r0, r1, r2, r3, bd_ + 32768);
            bl[2 * ng][0] = r0; bl[2 * ng][1] = r1;
            bl[2 * ng + 1][0] = r2; bl[2 * ng + 1][1] = r3;
        }
#pragma unroll
        for (int mi = 0; mi < 4; mi++) {
            int row = m_base + mi * 16 + ri + ((mat & 1) << 3);
            int ch = kk * 2 + (mat >> 1);
            unsigned ad = sb + 65536 + row * 128 + ((ch ^ (row & 7)) << 4);
            ldsm4(af[mi][0], af[mi][1], af[mi][2], af[mi][3], ad);
        }
#pragma unroll
        for (int mi = 0; mi < 4; mi++)
#pragma unroll
            for (int ni = 0; ni < 8; ni++) {
                mma16816(acc[mi][ni], af[mi], bh[ni]);
                mma16816(acc[mi][ni], af[mi], bl[ni]);
            }
#pragma unroll
        for (int mi = 0; mi < 4; mi++) {
            int row = m_base + mi * 16 + ri + ((mat & 1) << 3);
            int ch = kk * 2 + (mat >> 1);
            unsigned ad = sb + 81920 + row * 128 + ((ch ^ (row & 7)) << 4);
            ldsm4(af[mi][0], af[mi][1], af[mi][2], af[mi][3], ad);
        }
#pragma unroll
        for (int mi = 0; mi < 4; mi++)
#pragma unroll
            for (int ni = 0; ni < 8; ni++)
                mma16816(acc[mi][ni], af[mi], bh[ni]);
    }

    // epilogue: bias, pixel-shuffle position, bf16 hi/lo split to g_ahi/g_alo
#pragma unroll
    for (int mi = 0; mi < 4; mi++) {
        int oc0 = m_base + mi * 16 + (lane >> 2);
        float bias0 = bp[oc0], bias1 = bp[oc0 + 8];
#pragma unroll
        for (int ni = 0; ni < 8; ni++) {
            int t0 = n_base + ni * 8 + (lane & 3) * 2;
#pragma unroll
            for (int q = 0; q < 4; q++) {
                int oc = (q < 2) ? oc0 : oc0 + 8;
                float v = acc[mi][ni][q] + ((q < 2) ? bias0 : bias1);
                int t = t0 + (q & 1);
                int cp = oc >> 2, ii = (oc >> 1) & 1, jj = oc & 1;
                int h = t >> 4, w = t & 15;
                long pos = (long)b * 32768 + cp * 1024 + (2 * h + ii) * 32 + 2 * w + jj;
                __nv_bfloat16 hi = __float2bfloat16(v);
                g_ahi[pos] = hi;
                g_alo[pos] = __float2bfloat16(v - __bfloat162float(hi));
            }
        }
    }
}

// ======================= fc1: bf16 split GEMM, 3-stage pipeline =================
// 512 threads, 16 warps (4m x 4n), warp tile 64x32. CTA tile M=256 N=128 kc=32.
// Stage: Ah 16K | Al 16K | Wh 8K | Wl 8K = 48K; x3 = 144K.
__global__ __launch_bounds__(512) void k_fc1t(const float* __restrict__ W) {
    extern __shared__ __align__(16) char smem[];
    unsigned sbase = smem_u32(smem);
    int tid = threadIdx.x, lane = tid & 31, warp = tid >> 5;
    int n0 = blockIdx.x * 128, sk = blockIdx.z;
    long kbase = (long)sk * 2048;

    int m_base = (warp & 3) * 64;
    int n_base = (warp >> 2) * 32;

    int aq[2], ac[2];
#pragma unroll
    for (int j = 0; j < 2; j++) { int q = tid + j * 512; aq[j] = q >> 2; ac[j] = q & 3; }
    int wr = tid >> 2, wc = tid & 3;

    float acc[4][4][4];
#pragma unroll
    for (int i = 0; i < 4; i++)
#pragma unroll
        for (int j = 0; j < 4; j++)
#pragma unroll
            for (int q = 0; q < 4; q++) acc[i][j][q] = 0.f;

    const float* wgp = W + (long)(n0 + wr) * 32768 + kbase + wc * 8;

    // ---- prologue: stages 0, 1 ----
    float4 wa0 = *(const float4*)(wgp), wb0 = *(const float4*)(wgp + 4);
    float4 wa1 = *(const float4*)(wgp + 32), wb1 = *(const float4*)(wgp + 36);
#pragma unroll
    for (int j = 0; j < 2; j++) {
        int r = aq[j], c = ac[j];
        unsigned sw = (unsigned)(r * 64 + ((c ^ ((r >> 1) & 3)) << 4));
        cpa16(sbase + sw, g_ahi + (long)r * 32768 + kbase + c * 8);
        cpa16(sbase + 16384 + sw, g_alo + (long)r * 32768 + kbase + c * 8);
    }
    cpa_commit();
#pragma unroll
    for (int j = 0; j < 2; j++) {
        int r = aq[j], c = ac[j];
        unsigned sw = (unsigned)(r * 64 + ((c ^ ((r >> 1) & 3)) << 4));
        cpa16(sbase + 49152 + sw, g_ahi + (long)r * 32768 + kbase + 32 + c * 8);
        cpa16(sbase + 49152 + 16384 + sw, g_alo + (long)r * 32768 + kbase + 32 + c * 8);
    }
    cpa_commit();
    wsplit_store(sbase + 32768, wr, wc, wa0, wb0);
    wsplit_store(sbase + 49152 + 32768, wr, wc, wa1, wb1);

    int ri = lane & 7, mat = lane >> 3;

    for (int it = 0; it < 64; it++) {
        unsigned stb = sbase + (unsigned)(it % 3) * 49152u;
        cpa_wait1();
        __syncthreads();

        float4 wna, wnb;
        unsigned nb = sbase + (unsigned)((it + 2) % 3) * 49152u;
        if (it < 62) {
            long ko = kbase + (it + 2) * 32;
            wna = *(const float4*)(wgp + (it + 2) * 32);
            wnb = *(const float4*)(wgp + (it + 2) * 32 + 4);
#pragma unroll
            for (int j = 0; j < 2; j++) {
                int r = aq[j], c = ac[j];
                unsigned sw = (unsigned)(r * 64 + ((c ^ ((r >> 1) & 3)) << 4));
                cpa16(nb + sw, g_ahi + (long)r * 32768 + ko + c * 8);
                cpa16(nb + 16384 + sw, g_alo + (long)r * 32768 + ko + c * 8);
            }
        }
        cpa_commit();   // always commit (possibly empty) to keep group count exact

#pragma unroll
        for (int k16 = 0; k16 < 2; k16++) {
            unsigned af[4][4], bh[4][2], bl[4][2];
#pragma unroll
            for (int ng = 0; ng < 2; ng++) {
                int row = n_base + ng * 16 + ri + ((mat >> 1) << 3);
                int c = k16 * 2 + (mat & 1);
                unsigned bd_ = stb + 32768 + row * 64 + ((c ^ ((row >> 1) & 3)) << 4);
                unsigned r0, r1, r2, r3;
                ldsm4(r0, r1, r2, r3, bd_);
                bh[2 * ng][0] = r0; bh[2 * ng][1] = r1;
                bh[2 * ng + 1][0] = r2; bh[2 * ng + 1][1] = r3;
                ldsm4(r0, r1, r2, r3, bd_ + 8192);
                bl[2 * ng][0] = r0; bl[2 * ng][1] = r1;
                bl[2 * ng + 1][0] = r2; bl[2 * ng + 1][1] = r3;
            }
#pragma unroll
            for (int mi = 0; mi < 4; mi++) {
                int row = m_base + mi * 16 + ri + ((mat & 1) << 3);
                int c = k16 * 2 + (mat >> 1);
                unsigned ad = stb + row * 64 + ((c ^ ((row >> 1) & 3)) << 4);
                ldsm4(af[mi][0], af[mi][1], af[mi][2], af[mi][3], ad);
            }
#pragma unroll
            for (int mi = 0; mi < 4; mi++)
#pragma unroll
                for (int ni = 0; ni < 4; ni++) {
                    mma16816(acc[mi][ni], af[mi], bh[ni]);
                    mma16816(acc[mi][ni], af[mi], bl[ni]);
                }
#pragma unroll
            for (int mi = 0; mi < 4; mi++) {
                int row = m_base + mi * 16 + ri + ((mat & 1) << 3);
                int c = k16 * 2 + (mat >> 1);
                unsigned ad = stb + 16384 + row * 64 + ((c ^ ((row >> 1) & 3)) << 4);
                ldsm4(af[mi][0], af[mi][1], af[mi][2], af[mi][3], ad);
            }
#pragma unroll
            for (int mi = 0; mi < 4; mi++)
#pragma unroll
                for (int ni = 0; ni < 4; ni++)
                    mma16816(acc[mi][ni], af[mi], bh[ni]);
        }

        if (it < 62)
            wsplit_store(nb + 32768, wr, wc, wna, wnb);
    }

    float* slab = g_fc1p + (long)sk * BATCH * 1024;
#pragma unroll
    for (int mi = 0; mi < 4; mi++)
#pragma unroll
        for (int ni = 0; ni < 4; ni++) {
            int m = m_base + mi * 16 + (lane >> 2);
            int n = n0 + n_base + ni * 8 + (lane & 3) * 2;
            *(float2*)&slab[(long)m * 1024 + n] =
                make_float2(acc[mi][ni][0], acc[mi][ni][1]);
            *(float2*)&slab[(long)(m + 8) * 1024 + n] =
                make_float2(acc[mi][ni][2], acc[mi][ni][3]);
        }
}

// ======================= fc2 (fused slab-reduce + relu + fc2) ===================
__global__ __launch_bounds__(256) void k_fc2(const float* __restrict__ fc1b,
                                             const float* __restrict__ w2,
                                             const float* __restrict__ b2,
                                             float* __restrict__ out) {
    __shared__ __align__(16) float hs[1024];
    __shared__ float red[10 * 256];
    int b = blockIdx.x, tid = threadIdx.x;
    for (int j = tid; j < 1024; j += 256) {
        float s = 0.f;
#pragma unroll
        for (int q = 0; q < 16; q++) s += g_fc1p[(long)q * BATCH * 1024 + b * 1024 + j];
        hs[j] = fmaxf(s + fc1b[j], 0.f);
    }
    __syncthreads();
    float p[10];
#pragma unroll
    for (int n = 0; n < 10; n++) p[n] = 0.f;
    for (int j = tid; j < 1024; j += 256) {
        float hv = hs[j];
#pragma unroll
        for (int n = 0; n < 10; n++) p[n] += hv * w2[n * 1024 + j];
    }
#pragma unroll
    for (int n = 0; n < 10; n++) red[n * 256 + tid] = p[n];
    __syncthreads();
    for (int s = 128; s > 0; s >>= 1) {
        if (tid < s) {
#pragma unroll
            for (int n = 0; n < 10; n++) red[n * 256 + tid] += red[n * 256 + tid + s];
        }
        __syncthreads();
    }
    if (tid < 10) out[b * 10 + tid] = red[tid * 256] + b2[tid];
}

// =================================================================================
extern "C" void kernel_launch(void* const* d_in, const int* in_sizes, int n_in,
                              void* d_out, int out_size) {
    const float* x    = (const float*)d_in[0];
    const int*   idx1 = (const int*)d_in[1];
    const int*   idx2 = (const int*)d_in[2];
    const float* w1a  = (const float*)d_in[3];
    const float* b1a  = (const float*)d_in[4];
    const float* w1b  = (const float*)d_in[5];
    const float* b1b  = (const float*)d_in[6];
    const float* w1p  = (const float*)d_in[7];
    const float* b1p  = (const float*)d_in[8];
    const float* w2a  = (const float*)d_in[9];
    const float* b2a  = (const float*)d_in[10];
    const float* w2b  = (const float*)d_in[11];
    const float* b2b  = (const float*)d_in[12];
    const float* w2p  = (const float*)d_in[13];
    const float* b2p  = (const float*)d_in[14];
    const float* fc1w = (const float*)d_in[15];
    const float* fc1b = (const float*)d_in[16];
    const float* fc2w = (const float*)d_in[17];
    const float* fc2b = (const float*)d_in[18];
    float* out = (float*)d_out;

    const int smem_l2   = (64 * 256 + 576 * 16) * 4;   // 102400
    const int smem_pw   = 98304;
    const int smem_fc1t = 147456;
    cudaFuncSetAttribute(k_l2,    cudaFuncAttributeMaxDynamicSharedMemorySize, smem_l2);
    cudaFuncSetAttribute(k_l2_pw, cudaFuncAttributeMaxDynamicSharedMemorySize, smem_pw);
    cudaFuncSetAttribute(k_fc1t,  cudaFuncAttributeMaxDynamicSharedMemorySize, smem_fc1t);

    k_repack<<<72, 256>>>(w1a, w1b, w2a, w2b, w2p);
    k_l1<<<dim3(BATCH, 2), 128>>>(x, idx1, b1a, b1b, w1p, b1p);
    k_l2<<<dim3(BATCH, 3), 288, smem_l2>>>(idx2, b2a, b2b);
    k_l2_pw<<<BATCH, 256, smem_pw>>>(b2p);
    k_fc1t<<<dim3(8, 1, 16), 512, smem_fc1t>>>(fc1w);
    k_fc2<<<BATCH, 256>>>(fc1b, fc2w, fc2b, out);
}

// round 12
// speedup vs baseline: 2.8239x; 1.1622x over previous
#include <cuda_runtime.h>
#include <cuda_bf16.h>

typedef unsigned long long ull;
constexpr int BATCH = 256;

// ---------------- scratch (device globals) ----------------
__device__ __align__(16) float g_out1[BATCH * 64 * 256];
__device__ __align__(16) float g_fc1p[16 * BATCH * 1024];
__device__ __align__(16) float g_r1a[1728];
__device__ __align__(16) float g_r1b[1728];
__device__ __align__(16) float g_r2b[18432];                  // [k][c][oc]
__device__ __align__(16) __nv_bfloat16 g_o1h[BATCH * 16384];  // out1 hi [t][c]
__device__ __align__(16) __nv_bfloat16 g_o1l[BATCH * 16384];
__device__ __align__(16) __nv_bfloat16 g_w2ah[9 * 32 * 64];   // conv W [tap][oc][c]
__device__ __align__(16) __nv_bfloat16 g_w2al[9 * 32 * 64];
__device__ __align__(16) __nv_bfloat16 g_c2h[BATCH * 16384];  // cat2 hi [t][c]
__device__ __align__(16) __nv_bfloat16 g_c2l[BATCH * 16384];
__device__ __align__(16) __nv_bfloat16 g_wph[8192];           // w2p hi [oc][c]
__device__ __align__(16) __nv_bfloat16 g_wpl[8192];
__device__ __align__(16) __nv_bfloat16 g_ahi[BATCH * 32768];
__device__ __align__(16) __nv_bfloat16 g_alo[BATCH * 32768];

// ---------------- f32x2 helpers ----------------
__device__ __forceinline__ ull pack2(float lo, float hi) {
    ull r;
    asm("mov.b64 %0, {%1, %2};" : "=l"(r) : "r"(__float_as_uint(lo)), "r"(__float_as_uint(hi)));
    return r;
}
__device__ __forceinline__ ull packd(float s) { return pack2(s, s); }
__device__ __forceinline__ void fma2(ull& d, ull a, ull b) {
    asm("fma.rn.f32x2 %0, %1, %2, %3;" : "=l"(d) : "l"(a), "l"(b), "l"(d));
}
__device__ __forceinline__ float2 unpk(ull v) {
    unsigned lo, hi;
    asm("mov.b64 {%0, %1}, %2;" : "=r"(lo), "=r"(hi) : "l"(v));
    float2 f; f.x = __uint_as_float(lo); f.y = __uint_as_float(hi);
    return f;
}

// ---------------- mma.sync helpers ----------------
__device__ __forceinline__ unsigned smem_u32(const void* p) {
    unsigned a;
    asm("{ .reg .u64 t; cvta.to.shared.u64 t, %1; cvt.u32.u64 %0, t; }" : "=r"(a) : "l"(p));
    return a;
}
__device__ __forceinline__ void ldsm4(unsigned& r0, unsigned& r1, unsigned& r2, unsigned& r3,
                                      unsigned addr) {
    asm volatile("ldmatrix.sync.aligned.m8n8.x4.shared.b16 {%0,%1,%2,%3}, [%4];"
                 : "=r"(r0), "=r"(r1), "=r"(r2), "=r"(r3) : "r"(addr));
}
__device__ __forceinline__ void mma16816(float* c, const unsigned* a, const unsigned* b) {
    asm volatile(
        "mma.sync.aligned.m16n8k16.row.col.f32.bf16.bf16.f32 "
        "{%0,%1,%2,%3},{%4,%5,%6,%7},{%8,%9},{%0,%1,%2,%3};"
        : "+f"(c[0]), "+f"(c[1]), "+f"(c[2]), "+f"(c[3])
        : "r"(a[0]), "r"(a[1]), "r"(a[2]), "r"(a[3]), "r"(b[0]), "r"(b[1]));
}
__device__ __forceinline__ void cpa16(unsigned dst, const void* src) {
    asm volatile("cp.async.cg.shared.global [%0], [%1], 16;" :: "r"(dst), "l"(src));
}
__device__ __forceinline__ void cpa_commit() { asm volatile("cp.async.commit_group;"); }
__device__ __forceinline__ void cpa_wait0() {
    asm volatile("cp.async.wait_group 0;" ::: "memory");
}
__device__ __forceinline__ void cpa_wait1() {
    asm volatile("cp.async.wait_group 1;" ::: "memory");
}
__device__ __forceinline__ void sts128(unsigned addr, uint4 v) {
    asm volatile("st.shared.v4.b32 [%0], {%1,%2,%3,%4};"
                 :: "r"(addr), "r"(v.x), "r"(v.y), "r"(v.z), "r"(v.w));
}
__device__ __forceinline__ unsigned pkbf(float a, float b) {
    __nv_bfloat16 ha = __float2bfloat16(a), hb = __float2bfloat16(b);
    return ((unsigned)__bfloat16_as_ushort(hb) << 16) | __bfloat16_as_ushort(ha);
}
__device__ __forceinline__ void wsplit_store(unsigned hi_base, int row, int c,
                                             float4 a, float4 b) {
    unsigned sw = (unsigned)(row * 64 + ((c ^ ((row >> 1) & 3)) << 4));
    uint4 hi, lo;
    hi.x = pkbf(a.x, a.y); hi.y = pkbf(a.z, a.w);
    hi.z = pkbf(b.x, b.y); hi.w = pkbf(b.z, b.w);
    __nv_bfloat16 t0 = __float2bfloat16(a.x), t1 = __float2bfloat16(a.y);
    __nv_bfloat16 t2 = __float2bfloat16(a.z), t3 = __float2bfloat16(a.w);
    __nv_bfloat16 t4 = __float2bfloat16(b.x), t5 = __float2bfloat16(b.y);
    __nv_bfloat16 t6 = __float2bfloat16(b.z), t7 = __float2bfloat16(b.w);
    lo.x = pkbf(a.x - __bfloat162float(t0), a.y - __bfloat162float(t1));
    lo.y = pkbf(a.z - __bfloat162float(t2), a.w - __bfloat162float(t3));
    lo.z = pkbf(b.x - __bfloat162float(t4), b.y - __bfloat162float(t5));
    lo.w = pkbf(b.z - __bfloat162float(t6), b.w - __bfloat162float(t7));
    sts128(hi_base + sw, hi);
    sts128(hi_base + 8192 + sw, lo);
}
__device__ __forceinline__ void c2_store(long base, float r0, float r1) {
    __nv_bfloat16 h0 = __float2bfloat16(r0), h1 = __float2bfloat16(r1);
    *(unsigned*)&g_c2h[base] = pkbf(r0, r1);
    *(unsigned*)&g_c2l[base] = pkbf(r0 - __bfloat162float(h0), r1 - __bfloat162float(h1));
}

// ---------------- weight repack ----------------
__global__ __launch_bounds__(256) void k_repack(const float* __restrict__ w1a,
                                                const float* __restrict__ w1b,
                                                const float* __restrict__ w2a,
                                                const float* __restrict__ w2b,
                                                const float* __restrict__ w2p) {
    int i = blockIdx.x * 256 + threadIdx.x;
    if (i < 1728) {
        int oc = i / 108, rest = i % 108;
        g_r1a[rest * 16 + oc] = w1a[i];
        g_r1b[rest * 16 + oc] = w1b[i];
    }
    if (i < 8192) {
        float v = w2p[i];
        __nv_bfloat16 h = __float2bfloat16(v);
        g_wph[i] = h;
        g_wpl[i] = __float2bfloat16(v - __bfloat162float(h));
    }
    if (i < 18432) {
        int oc = i / 576, rest = i % 576;
        int c = rest / 9, k = rest % 9;
        g_r2b[(k * 64 + c) * 32 + oc] = w2b[i];
        // conv weights: [tap][oc][c] bf16 hi/lo
        float v = w2a[i];
        __nv_bfloat16 h = __float2bfloat16(v);
        g_w2ah[(k * 32 + oc) * 64 + c] = h;
        g_w2al[(k * 32 + oc) * 64 + c] = __float2bfloat16(v - __bfloat162float(h));
    }
}

// ======================= Layer 1 FUSED, pixel-split x2 ==========================
__global__ __launch_bounds__(128) void k_l1(const float* __restrict__ x,
                                            const int* __restrict__ idx,
                                            const float* __restrict__ b1a,
                                            const float* __restrict__ b1b,
                                            const float* __restrict__ wp,
                                            const float* __restrict__ bp) {
    __shared__ __align__(16) float xs[12 * 256];
    __shared__ __align__(16) float ss[12 * 64];
    __shared__ float sn[64];
    __shared__ __align__(16) float wsa[1728];
    __shared__ __align__(16) float wsb[1728];
    __shared__ __align__(16) float wsp[64 * 32];
    int b = blockIdx.x, tid = threadIdx.x;
    int p = blockIdx.y * 128 + tid;

    for (int i = tid; i < 12 * 256; i += 128) {
        int cu = i >> 8, t = i & 255;
        int h = t >> 4, w = t & 15;
        int c = cu >> 2, ii = (cu >> 1) & 1, jj = cu & 1;
        xs[i] = x[((b * 3 + c) * 32 + (2 * h + ii)) * 32 + 2 * w + jj];
    }
    for (int i = tid; i < 1728; i += 128) { wsa[i] = g_r1a[i]; wsb[i] = g_r1b[i]; }
    for (int i = tid; i < 64 * 32; i += 128) wsp[i] = wp[i];
    __syncthreads();
    for (int i = tid; i < 12 * 64; i += 128)
        ss[i] = xs[(i >> 6) * 256 + idx[i & 63]];
    __syncthreads();
    if (tid < 64) {
        float s = 0.f;
#pragma unroll
        for (int c = 0; c < 12; c++) { float v = ss[c * 64 + tid]; s += v * v; }
        sn[tid] = s;
    }
    __syncthreads();

    int h = p >> 4, w = p & 15;

    ull acv[8];
#pragma unroll
    for (int o = 0; o < 8; o++) acv[o] = pack2(b1a[2 * o], b1a[2 * o + 1]);
    for (int c = 0; c < 12; c++) {
        float pp[9];
#pragma unroll
        for (int dy = 0; dy < 3; dy++)
#pragma unroll
            for (int dx = 0; dx < 3; dx++) {
                int y = h + dy - 1, xq = w + dx - 1;
                pp[dy * 3 + dx] = (y >= 0 && y < 16 && xq >= 0 && xq < 16)
                                      ? xs[c * 256 + y * 16 + xq] : 0.f;
            }
#pragma unroll
        for (int tap = 0; tap < 9; tap++) {
            ull s2 = packd(pp[tap]);
            const longlong2* wv = (const longlong2*)&wsa[(c * 9 + tap) * 16];
#pragma unroll
            for (int q = 0; q < 4; q++) {
                longlong2 w4 = wv[q];
                fma2(acv[q * 2 + 0], s2, (ull)w4.x);
                fma2(acv[q * 2 + 1], s2, (ull)w4.y);
            }
        }
    }

    float xr[12]; float xn = 0.f;
#pragma unroll
    for (int c = 0; c < 12; c++) { float v = xs[c * 256 + p]; xr[c] = v; xn += v * v; }

    float bd[9]; int bi[9];
#pragma unroll
    for (int k = 0; k < 9; k++) { bd[k] = 3.0e38f; bi[k] = 0; }
    for (int n = 0; n < 64; n++) {
        float dot = 0.f;
#pragma unroll
        for (int c = 0; c < 12; c++) dot += xr[c] * ss[c * 64 + n];
        float d = xn + sn[n] - 2.f * dot;
        if (d < bd[8]) {
            bool placed = false;
#pragma unroll
            for (int j = 8; j > 0; --j) {
                if (!placed) {
                    if (d < bd[j - 1]) { bd[j] = bd[j - 1]; bi[j] = bi[j - 1]; }
                    else { bd[j] = d; bi[j] = n; placed = true; }
                }
            }
            if (!placed) { bd[0] = d; bi[0] = n; }
        }
    }

    ull akn[8];
#pragma unroll
    for (int o = 0; o < 8; o++) akn[o] = pack2(b1b[2 * o], b1b[2 * o + 1]);
#pragma unroll
    for (int c = 0; c < 12; c++) {
#pragma unroll
        for (int k = 0; k < 9; k++) {
            ull s2 = packd(ss[c * 64 + bi[k]]);
            const longlong2* wv = (const longlong2*)&wsb[(c * 9 + k) * 16];
#pragma unroll
            for (int q = 0; q < 4; q++) {
                longlong2 w4 = wv[q];
                fma2(akn[q * 2 + 0], s2, (ull)w4.x);
                fma2(akn[q * 2 + 1], s2, (ull)w4.y);
            }
        }
    }

    ull xv[16];
#pragma unroll
    for (int o = 0; o < 8; o++) {
        float2 v = unpk(acv[o]);
        xv[o] = pack2(fmaxf(v.x, 0.f), fmaxf(v.y, 0.f));
        float2 u = unpk(akn[o]);
        xv[8 + o] = pack2(fmaxf(u.x, 0.f), fmaxf(u.y, 0.f));
    }
    float vb[8];
    for (int oc = 0; oc < 64; oc++) {
        ull a2 = 0ull;
        const longlong2* wv = (const longlong2*)&wsp[oc * 32];
#pragma unroll
        for (int q = 0; q < 8; q++) {
            longlong2 w4 = wv[q];
            fma2(a2, xv[q * 2 + 0], (ull)w4.x);
            fma2(a2, xv[q * 2 + 1], (ull)w4.y);
        }
        float2 v = unpk(a2);
        float val = v.x + v.y + bp[oc];
        g_out1[(b * 64 + oc) * 256 + p] = val;
        vb[oc & 7] = val;
        if ((oc & 7) == 7) {
            uint4 hi, lo;
            hi.x = pkbf(vb[0], vb[1]); hi.y = pkbf(vb[2], vb[3]);
            hi.z = pkbf(vb[4], vb[5]); hi.w = pkbf(vb[6], vb[7]);
            float l[8];
#pragma unroll
            for (int j = 0; j < 8; j++)
                l[j] = vb[j] - __bfloat162float(__float2bfloat16(vb[j]));
            lo.x = pkbf(l[0], l[1]); lo.y = pkbf(l[2], l[3]);
            lo.z = pkbf(l[4], l[5]); lo.w = pkbf(l[6], l[7]);
            long base = (long)b * 16384 + p * 64 + (oc - 7);
            *(uint4*)&g_o1h[base] = hi;
            *(uint4*)&g_o1l[base] = lo;
        }
    }
}

// ========== Layer 2 conv 3x3 (64->32) as implicit-GEMM bf16 split mma ===========
// smem: Xh 33024 | Xl 33024 | Ah 36864 | Al 36864 = 139776 B.
// X rows: 256 pixel rows (128B each) + row 256 = zero row for boundary taps.
__global__ __launch_bounds__(256) void k_l2c(const float* __restrict__ ba) {
    extern __shared__ __align__(16) char smem[];
    unsigned sb = smem_u32(smem);
    const unsigned XH = 0, XL = 33024, AH = 66048, AL = 102912;
    int b = blockIdx.x, tid = threadIdx.x, lane = tid & 31, warp = tid >> 5;

    // zero row 256 of both X planes
    if (tid < 16) {
        uint4 z = make_uint4(0, 0, 0, 0);
        unsigned pl = (tid >> 3) ? XL : XH;
        sts128(sb + pl + 256 * 128 + ((tid & 7) << 4), z);
    }
    // load X planes: 2048 chunks each
#pragma unroll
    for (int j = 0; j < 8; j++) {
        int q = tid + j * 256;
        int row = q >> 3, ch = q & 7;
        unsigned sw = (unsigned)(row * 128 + ((ch ^ (row & 7)) << 4));
        cpa16(sb + XH + sw, g_o1h + (long)b * 16384 + row * 64 + ch * 8);
        cpa16(sb + XL + sw, g_o1l + (long)b * 16384 + row * 64 + ch * 8);
    }
    // load A planes: 288 rows x 8 chunks = 2304 each
#pragma unroll
    for (int j = 0; j < 9; j++) {
        int q = tid + j * 256;
        int row = q >> 3, ch = q & 7;
        unsigned sw = (unsigned)(row * 128 + ((ch ^ (row & 7)) << 4));
        cpa16(sb + AH + sw, g_w2ah + row * 64 + ch * 8);
        cpa16(sb + AL + sw, g_w2al + row * 64 + ch * 8);
    }
    cpa_commit();
    cpa_wait0();
    __syncthreads();

    int n_base = warp * 32;           // 32 output pixels per warp
    int ri = lane & 7, mat = lane >> 3;

    float acc[2][4][4];
#pragma unroll
    for (int i = 0; i < 2; i++)
#pragma unroll
        for (int j = 0; j < 4; j++)
#pragma unroll
            for (int q = 0; q < 4; q++) acc[i][j][q] = 0.f;

#pragma unroll
    for (int tap = 0; tap < 9; tap++) {
        int dy = tap / 3, dx = tap % 3;
        int rin[2];
#pragma unroll
        for (int ng = 0; ng < 2; ng++) {
            int t = n_base + ng * 16 + ri + ((mat >> 1) << 3);
            int h = (t >> 4) + dy - 1, w = (t & 15) + dx - 1;
            rin[ng] = ((unsigned)h < 16u && (unsigned)w < 16u) ? h * 16 + w : 256;
        }
#pragma unroll
        for (int k16 = 0; k16 < 4; k16++) {
            unsigned af[2][4], bh[4][2], bl[4][2];
            int chb = k16 * 2 + (mat & 1);
#pragma unroll
            for (int ng = 0; ng < 2; ng++) {
                int r = rin[ng];
                unsigned sw = (unsigned)(r * 128 + ((chb ^ (r & 7)) << 4));
                unsigned r0, r1, r2, r3;
                ldsm4(r0, r1, r2, r3, sb + XH + sw);
                bh[2 * ng][0] = r0; bh[2 * ng][1] = r1;
                bh[2 * ng + 1][0] = r2; bh[2 * ng + 1][1] = r3;
                ldsm4(r0, r1, r2, r3, sb + XL + sw);
                bl[2 * ng][0] = r0; bl[2 * ng][1] = r1;
                bl[2 * ng + 1][0] = r2; bl[2 * ng + 1][1] = r3;
            }
            int cha = k16 * 2 + (mat >> 1);
#pragma unroll
            for (int mi = 0; mi < 2; mi++) {
                int row = tap * 32 + mi * 16 + ri + ((mat & 1) << 3);
                unsigned ad = sb + AH + row * 128 + ((cha ^ (row & 7)) << 4);
                ldsm4(af[mi][0], af[mi][1], af[mi][2], af[mi][3], ad);
            }
#pragma unroll
            for (int mi = 0; mi < 2; mi++)
#pragma unroll
                for (int ni = 0; ni < 4; ni++) {
                    mma16816(acc[mi][ni], af[mi], bh[ni]);
                    mma16816(acc[mi][ni], af[mi], bl[ni]);
                }
#pragma unroll
            for (int mi = 0; mi < 2; mi++) {
                int row = tap * 32 + mi * 16 + ri + ((mat & 1) << 3);
                unsigned ad = sb + AL + row * 128 + ((cha ^ (row & 7)) << 4);
                ldsm4(af[mi][0], af[mi][1], af[mi][2], af[mi][3], ad);
            }
#pragma unroll
            for (int mi = 0; mi < 2; mi++)
#pragma unroll
                for (int ni = 0; ni < 4; ni++)
                    mma16816(acc[mi][ni], af[mi], bh[ni]);
        }
    }

    // epilogue: bias + relu + bf16 hi/lo split into cat2 [t][c], c = oc (0..31)
#pragma unroll
    for (int mi = 0; mi < 2; mi++) {
        int oc0 = mi * 16 + (lane >> 2);
        float bias0 = ba[oc0], bias1 = ba[oc0 + 8];
#pragma unroll
        for (int ni = 0; ni < 4; ni++) {
            int t0 = n_base + ni * 8 + (lane & 3) * 2;
#pragma unroll
            for (int q = 0; q < 4; q++) {
                int oc = (q < 2) ? oc0 : oc0 + 8;
                float v = fmaxf(acc[mi][ni][q] + ((q < 2) ? bias0 : bias1), 0.f);
                int t = t0 + (q & 1);
                long base = (long)b * 16384 + t * 64 + oc;
                __nv_bfloat16 h = __float2bfloat16(v);
                g_c2h[base] = h;
                g_c2l[base] = __float2bfloat16(v - __bfloat162float(h));
            }
        }
    }
}

// ======================= Layer 2 kNN branch (M-table) ===========================
__global__ __launch_bounds__(288, 2) void k_l2_knn(const int* __restrict__ idx,
                                                   const float* __restrict__ bb) {
    extern __shared__ __align__(16) float sm[];
    float* ss = sm;              // [n][c], stride 66
    float* Mt = sm + 4224;       // [(k*64+n)][o], stride 33
    float* sn = Mt + 19008;      // 64
    int b = blockIdx.x, tid = threadIdx.x, lane = tid & 31, wid = tid >> 5;

    for (int i = tid; i < 4096; i += 288) {
        int n = i & 63, c = i >> 6;
        ss[n * 66 + c] = g_out1[(b * 64 + c) * 256 + idx[n]];
    }
    __syncthreads();
    if (tid < 64) {
        float s = 0.f;
#pragma unroll 16
        for (int c = 0; c < 64; c++) { float v = ss[tid * 66 + c]; s += v * v; }
        sn[tid] = s;
    }

    {
        int k = wid;
        ull a0[16], a1[16];
#pragma unroll
        for (int j = 0; j < 16; j++) { a0[j] = 0ull; a1[j] = 0ull; }
        const longlong2* wrow = (const longlong2*)(g_r2b + (k * 64) * 32);
        int n0 = lane, n1 = lane + 32;
        for (int c = 0; c < 64; c++) {
            ull s0 = packd(ss[n0 * 66 + c]);
            ull s1 = packd(ss[n1 * 66 + c]);
#pragma unroll
            for (int q = 0; q < 8; q++) {
                longlong2 w4 = wrow[c * 8 + q];
                fma2(a0[q * 2 + 0], s0, (ull)w4.x);
                fma2(a0[q * 2 + 1], s0, (ull)w4.y);
                fma2(a1[q * 2 + 0], s1, (ull)w4.x);
                fma2(a1[q * 2 + 1], s1, (ull)w4.y);
            }
        }
        float* m0 = &Mt[(k * 64 + n0) * 33];
        float* m1 = &Mt[(k * 64 + n1) * 33];
#pragma unroll
        for (int j = 0; j < 16; j++) {
            float2 v0 = unpk(a0[j]); m0[2 * j] = v0.x; m0[2 * j + 1] = v0.y;
            float2 v1 = unpk(a1[j]); m1[2 * j] = v1.x; m1[2 * j + 1] = v1.y;
        }
    }
    __syncthreads();

    if (tid < 256) {
        int t = tid;
        ull xr2[32]; float xn = 0.f;
#pragma unroll
        for (int c2 = 0; c2 < 32; c2++) {
            float f0 = g_out1[(b * 64 + 2 * c2) * 256 + t];
            float f1 = g_out1[(b * 64 + 2 * c2 + 1) * 256 + t];
            xn += f0 * f0 + f1 * f1;
            xr2[c2] = pack2(f0, f1);
        }

        float bd[9]; int bi[9];
#pragma unroll
        for (int k = 0; k < 9; k++) { bd[k] = 3.0e38f; bi[k] = 0; }
        for (int n = 0; n < 64; n++) {
            const ull* sp = (const ull*)&ss[n * 66];
            ull d2 = 0ull;
#pragma unroll
            for (int j = 0; j < 32; j++) fma2(d2, xr2[j], sp[j]);
            float2 dv = unpk(d2);
            float d = xn + sn[n] - 2.f * (dv.x + dv.y);
            if (d < bd[8]) {
                bool placed = false;
#pragma unroll
                for (int j = 8; j > 0; --j) {
                    if (!placed) {
                        if (d < bd[j - 1]) { bd[j] = bd[j - 1]; bi[j] = bi[j - 1]; }
                        else { bd[j] = d; bi[j] = n; placed = true; }
                    }
                }
                if (!placed) { bd[0] = d; bi[0] = n; }
            }
        }

#pragma unroll
        for (int half = 0; half < 2; half++) {
            float acc[16];
#pragma unroll
            for (int o = 0; o < 16; o++) acc[o] = bb[half * 16 + o];
#pragma unroll
            for (int k = 0; k < 9; k++) {
                const float* mrow = &Mt[(k * 64 + bi[k]) * 33 + half * 16];
#pragma unroll
                for (int o = 0; o < 16; o++) acc[o] += mrow[o];
            }
#pragma unroll
            for (int j = 0; j < 8; j++)
                c2_store((long)b * 16384 + t * 64 + 32 + half * 16 + 2 * j,
                         fmaxf(acc[2 * j], 0.f), fmaxf(acc[2 * j + 1], 0.f));
        }
    }
}

// ======== Layer 2 pw as bf16 split mma: C[128][256] = W[128x64] * cat2 ==========
__global__ __launch_bounds__(256) void k_l2_pw(const float* __restrict__ bp) {
    extern __shared__ __align__(16) char smem[];
    unsigned sb = smem_u32(smem);
    int b = blockIdx.x, tid = threadIdx.x, lane = tid & 31, warp = tid >> 5;

#pragma unroll
    for (int j = 0; j < 8; j++) {
        int q = tid + j * 256;
        int row = q >> 3, ch = q & 7;
        unsigned dst = sb + row * 128 + ((ch ^ (row & 7)) << 4);
        cpa16(dst, g_c2h + (long)b * 16384 + row * 64 + ch * 8);
        cpa16(dst + 32768, g_c2l + (long)b * 16384 + row * 64 + ch * 8);
    }
#pragma unroll
    for (int j = 0; j < 4; j++) {
        int q = tid + j * 256;
        int row = q >> 3, ch = q & 7;
        unsigned dst = sb + 65536 + row * 128 + ((ch ^ (row & 7)) << 4);
        cpa16(dst, g_wph + row * 64 + ch * 8);
        cpa16(dst + 16384, g_wpl + row * 64 + ch * 8);
    }
    cpa_commit();
    cpa_wait0();
    __syncthreads();

    int m_base = (warp & 1) * 64;
    int n_base = (warp >> 1) * 64;
    int ri = lane & 7, mat = lane >> 3;

    float acc[4][8][4];
#pragma unroll
    for (int i = 0; i < 4; i++)
#pragma unroll
        for (int j = 0; j < 8; j++)
#pragma unroll
            for (int q = 0; q < 4; q++) acc[i][j][q] = 0.f;

#pragma unroll
    for (int kk = 0; kk < 4; kk++) {
        unsigned af[4][4], bh[8][2], bl[8][2];
#pragma unroll
        for (int ng = 0; ng < 4; ng++) {
            int row = n_base + ng * 16 + ri + ((mat >> 1) << 3);
            int ch = kk * 2 + (mat & 1);
            unsigned bd_ = sb + row * 128 + ((ch ^ (row & 7)) << 4);
            unsigned r0, r1, r2, r3;
            ldsm4(r0, r1, r2, r3, bd_);
            bh[2 * ng][0] = r0; bh[2 * ng][1] = r1;
            bh[2 * ng + 1][0] = r2; bh[2 * ng + 1][1] = r3;
            ldsm4(r0, r1, r2, r3, bd_ + 32768);
            bl[2 * ng][0] = r0; bl[2 * ng][1] = r1;
            bl[2 * ng + 1][0] = r2; bl[2 * ng + 1][1] = r3;
        }
#pragma unroll
        for (int mi = 0; mi < 4; mi++) {
            int row = m_base + mi * 16 + ri + ((mat & 1) << 3);
            int ch = kk * 2 + (mat >> 1);
            unsigned ad = sb + 65536 + row * 128 + ((ch ^ (row & 7)) << 4);
            ldsm4(af[mi][0], af[mi][1], af[mi][2], af[mi][3], ad);
        }
#pragma unroll
        for (int mi = 0; mi < 4; mi++)
#pragma unroll
            for (int ni = 0; ni < 8; ni++) {
                mma16816(acc[mi][ni], af[mi], bh[ni]);
                mma16816(acc[mi][ni], af[mi], bl[ni]);
            }
#pragma unroll
        for (int mi = 0; mi < 4; mi++) {
            int row = m_base + mi * 16 + ri + ((mat & 1) << 3);
            int ch = kk * 2 + (mat >> 1);
            unsigned ad = sb + 81920 + row * 128 + ((ch ^ (row & 7)) << 4);
            ldsm4(af[mi][0], af[mi][1], af[mi][2], af[mi][3], ad);
        }
#pragma unroll
        for (int mi = 0; mi < 4; mi++)
#pragma unroll
            for (int ni = 0; ni < 8; ni++)
                mma16816(acc[mi][ni], af[mi], bh[ni]);
    }

#pragma unroll
    for (int mi = 0; mi < 4; mi++) {
        int oc0 = m_base + mi * 16 + (lane >> 2);
        float bias0 = bp[oc0], bias1 = bp[oc0 + 8];
#pragma unroll
        for (int ni = 0; ni < 8; ni++) {
            int t0 = n_base + ni * 8 + (lane & 3) * 2;
#pragma unroll
            for (int q = 0; q < 4; q++) {
                int oc = (q < 2) ? oc0 : oc0 + 8;
                float v = acc[mi][ni][q] + ((q < 2) ? bias0 : bias1);
                int t = t0 + (q & 1);
                int cp = oc >> 2, ii = (oc >> 1) & 1, jj = oc & 1;
                int h = t >> 4, w = t & 15;
                long pos = (long)b * 32768 + cp * 1024 + (2 * h + ii) * 32 + 2 * w + jj;
                __nv_bfloat16 hi = __float2bfloat16(v);
                g_ahi[pos] = hi;
                g_alo[pos] = __float2bfloat16(v - __bfloat162float(hi));
            }
        }
    }
}

// ======================= fc1: bf16 split GEMM, 3-stage pipeline =================
__global__ __launch_bounds__(512) void k_fc1t(const float* __restrict__ W) {
    extern __shared__ __align__(16) char smem[];
    unsigned sbase = smem_u32(smem);
    int tid = threadIdx.x, lane = tid & 31, warp = tid >> 5;
    int n0 = blockIdx.x * 128, sk = blockIdx.z;
    long kbase = (long)sk * 2048;

    int m_base = (warp & 3) * 64;
    int n_base = (warp >> 2) * 32;

    int aq[2], ac[2];
#pragma unroll
    for (int j = 0; j < 2; j++) { int q = tid + j * 512; aq[j] = q >> 2; ac[j] = q & 3; }
    int wr = tid >> 2, wc = tid & 3;

    float acc[4][4][4];
#pragma unroll
    for (int i = 0; i < 4; i++)
#pragma unroll
        for (int j = 0; j < 4; j++)
#pragma unroll
            for (int q = 0; q < 4; q++) acc[i][j][q] = 0.f;

    const float* wgp = W + (long)(n0 + wr) * 32768 + kbase + wc * 8;

    float4 wa0 = *(const float4*)(wgp), wb0 = *(const float4*)(wgp + 4);
    float4 wa1 = *(const float4*)(wgp + 32), wb1 = *(const float4*)(wgp + 36);
#pragma unroll
    for (int j = 0; j < 2; j++) {
        int r = aq[j], c = ac[j];
        unsigned sw = (unsigned)(r * 64 + ((c ^ ((r >> 1) & 3)) << 4));
        cpa16(sbase + sw, g_ahi + (long)r * 32768 + kbase + c * 8);
        cpa16(sbase + 16384 + sw, g_alo + (long)r * 32768 + kbase + c * 8);
    }
    cpa_commit();
#pragma unroll
    for (int j = 0; j < 2; j++) {
        int r = aq[j], c = ac[j];
        unsigned sw = (unsigned)(r * 64 + ((c ^ ((r >> 1) & 3)) << 4));
        cpa16(sbase + 49152 + sw, g_ahi + (long)r * 32768 + kbase + 32 + c * 8);
        cpa16(sbase + 49152 + 16384 + sw, g_alo + (long)r * 32768 + kbase + 32 + c * 8);
    }
    cpa_commit();
    wsplit_store(sbase + 32768, wr, wc, wa0, wb0);
    wsplit_store(sbase + 49152 + 32768, wr, wc, wa1, wb1);

    int ri = lane & 7, mat = lane >> 3;

    for (int it = 0; it < 64; it++) {
        unsigned stb = sbase + (unsigned)(it % 3) * 49152u;
        cpa_wait1();
        __syncthreads();

        float4 wna, wnb;
        unsigned nb = sbase + (unsigned)((it + 2) % 3) * 49152u;
        if (it < 62) {
            long ko = kbase + (it + 2) * 32;
            wna = *(const float4*)(wgp + (it + 2) * 32);
            wnb = *(const float4*)(wgp + (it + 2) * 32 + 4);
#pragma unroll
            for (int j = 0; j < 2; j++) {
                int r = aq[j], c = ac[j];
                unsigned sw = (unsigned)(r * 64 + ((c ^ ((r >> 1) & 3)) << 4));
                cpa16(nb + sw, g_ahi + (long)r * 32768 + ko + c * 8);
                cpa16(nb + 16384 + sw, g_alo + (long)r * 32768 + ko + c * 8);
            }
        }
        cpa_commit();

#pragma unroll
        for (int k16 = 0; k16 < 2; k16++) {
            unsigned af[4][4], bh[4][2], bl[4][2];
#pragma unroll
            for (int ng = 0; ng < 2; ng++) {
                int row = n_base + ng * 16 + ri + ((mat >> 1) << 3);
                int c = k16 * 2 + (mat & 1);
                unsigned bd_ = stb + 32768 + row * 64 + ((c ^ ((row >> 1) & 3)) << 4);
                unsigned r0, r1, r2, r3;
                ldsm4(r0, r1, r2, r3, bd_);
                bh[2 * ng][0] = r0; bh[2 * ng][1] = r1;
                bh[2 * ng + 1][0] = r2; bh[2 * ng + 1][1] = r3;
                ldsm4(r0, r1, r2, r3, bd_ + 8192);
                bl[2 * ng][0] = r0; bl[2 * ng][1] = r1;
                bl[2 * ng + 1][0] = r2; bl[2 * ng + 1][1] = r3;
            }
#pragma unroll
            for (int mi = 0; mi < 4; mi++) {
                int row = m_base + mi * 16 + ri + ((mat & 1) << 3);
                int c = k16 * 2 + (mat >> 1);
                unsigned ad = stb + row * 64 + ((c ^ ((row >> 1) & 3)) << 4);
                ldsm4(af[mi][0], af[mi][1], af[mi][2], af[mi][3], ad);
            }
#pragma unroll
            for (int mi = 0; mi < 4; mi++)
#pragma unroll
                for (int ni = 0; ni < 4; ni++) {
                    mma16816(acc[mi][ni], af[mi], bh[ni]);
                    mma16816(acc[mi][ni], af[mi], bl[ni]);
                }
#pragma unroll
            for (int mi = 0; mi < 4; mi++) {
                int row = m_base + mi * 16 + ri + ((mat & 1) << 3);
                int c = k16 * 2 + (mat >> 1);
                unsigned ad = stb + 16384 + row * 64 + ((c ^ ((row >> 1) & 3)) << 4);
                ldsm4(af[mi][0], af[mi][1], af[mi][2], af[mi][3], ad);
            }
#pragma unroll
            for (int mi = 0; mi < 4; mi++)
#pragma unroll
                for (int ni = 0; ni < 4; ni++)
                    mma16816(acc[mi][ni], af[mi], bh[ni]);
        }

        if (it < 62)
            wsplit_store(nb + 32768, wr, wc, wna, wnb);
    }

    float* slab = g_fc1p + (long)sk * BATCH * 1024;
#pragma unroll
    for (int mi = 0; mi < 4; mi++)
#pragma unroll
        for (int ni = 0; ni < 4; ni++) {
            int m = m_base + mi * 16 + (lane >> 2);
            int n = n0 + n_base + ni * 8 + (lane & 3) * 2;
            *(float2*)&slab[(long)m * 1024 + n] =
                make_float2(acc[mi][ni][0], acc[mi][ni][1]);
            *(float2*)&slab[(long)(m + 8) * 1024 + n] =
                make_float2(acc[mi][ni][2], acc[mi][ni][3]);
        }
}

// ======================= fc2 (fused slab-reduce + relu + fc2) ===================
__global__ __launch_bounds__(256) void k_fc2(const float* __restrict__ fc1b,
                                             const float* __restrict__ w2,
                                             const float* __restrict__ b2,
                                             float* __restrict__ out) {
    __shared__ __align__(16) float hs[1024];
    __shared__ float red[10 * 256];
    int b = blockIdx.x, tid = threadIdx.x;
    for (int j = tid; j < 1024; j += 256) {
        float s = 0.f;
#pragma unroll
        for (int q = 0; q < 16; q++) s += g_fc1p[(long)q * BATCH * 1024 + b * 1024 + j];
        hs[j] = fmaxf(s + fc1b[j], 0.f);
    }
    __syncthreads();
    float p[10];
#pragma unroll
    for (int n = 0; n < 10; n++) p[n] = 0.f;
    for (int j = tid; j < 1024; j += 256) {
        float hv = hs[j];
#pragma unroll
        for (int n = 0; n < 10; n++) p[n] += hv * w2[n * 1024 + j];
    }
#pragma unroll
    for (int n = 0; n < 10; n++) red[n * 256 + tid] = p[n];
    __syncthreads();
    for (int s = 128; s > 0; s >>= 1) {
        if (tid < s) {
#pragma unroll
            for (int n = 0; n < 10; n++) red[n * 256 + tid] += red[n * 256 + tid + s];
        }
        __syncthreads();
    }
    if (tid < 10) out[b * 10 + tid] = red[tid * 256] + b2[tid];
}

// =================================================================================
extern "C" void kernel_launch(void* const* d_in, const int* in_sizes, int n_in,
                              void* d_out, int out_size) {
    const float* x    = (const float*)d_in[0];
    const int*   idx1 = (const int*)d_in[1];
    const int*   idx2 = (const int*)d_in[2];
    const float* w1a  = (const float*)d_in[3];
    const float* b1a  = (const float*)d_in[4];
    const float* w1b  = (const float*)d_in[5];
    const float* b1b  = (const float*)d_in[6];
    const float* w1p  = (const float*)d_in[7];
    const float* b1p  = (const float*)d_in[8];
    const float* w2a  = (const float*)d_in[9];
    const float* b2a  = (const float*)d_in[10];
    const float* w2b  = (const float*)d_in[11];
    const float* b2b  = (const float*)d_in[12];
    const float* w2p  = (const float*)d_in[13];
    const float* b2p  = (const float*)d_in[14];
    const float* fc1w = (const float*)d_in[15];
    const float* fc1b = (const float*)d_in[16];
    const float* fc2w = (const float*)d_in[17];
    const float* fc2b = (const float*)d_in[18];
    float* out = (float*)d_out;

    const int smem_l2c  = 139776;
    const int smem_knn  = (4224 + 19008 + 64) * 4;   // 93184
    const int smem_pw   = 98304;
    const int smem_fc1t = 147456;
    cudaFuncSetAttribute(k_l2c,    cudaFuncAttributeMaxDynamicSharedMemorySize, smem_l2c);
    cudaFuncSetAttribute(k_l2_knn, cudaFuncAttributeMaxDynamicSharedMemorySize, smem_knn);
    cudaFuncSetAttribute(k_l2_pw,  cudaFuncAttributeMaxDynamicSharedMemorySize, smem_pw);
    cudaFuncSetAttribute(k_fc1t,   cudaFuncAttributeMaxDynamicSharedMemorySize, smem_fc1t);

    k_repack<<<72, 256>>>(w1a, w1b, w2a, w2b, w2p);
    k_l1<<<dim3(BATCH, 2), 128>>>(x, idx1, b1a, b1b, w1p, b1p);
    k_l2_knn<<<BATCH, 288, smem_knn>>>(idx2, b2b);
    k_l2c<<<BATCH, 256, smem_l2c>>>(b2a);
    k_l2_pw<<<BATCH, 256, smem_pw>>>(b2p);
    k_fc1t<<<dim3(8, 1, 16), 512, smem_fc1t>>>(fc1w);
    k_fc2<<<BATCH, 256>>>(fc1b, fc2w, fc2b, out);
}

// round 13
// speedup vs baseline: 2.9642x; 1.0497x over previous
#include <cuda_runtime.h>
#include <cuda_bf16.h>

typedef unsigned long long ull;
constexpr int BATCH = 256;

// ---------------- scratch (device globals) ----------------
__device__ __align__(16) float g_out1[BATCH * 64 * 256];
__device__ __align__(16) float g_fc1p[16 * BATCH * 1024];
__device__ __align__(16) float g_r1a[1728];
__device__ __align__(16) float g_r1b[1728];
__device__ __align__(16) __nv_bfloat16 g_o1h[BATCH * 16384];  // out1 hi [t][c]
__device__ __align__(16) __nv_bfloat16 g_o1l[BATCH * 16384];
__device__ __align__(16) __nv_bfloat16 g_w2ah[9 * 32 * 64];   // conv W [tap][oc][c]
__device__ __align__(16) __nv_bfloat16 g_w2al[9 * 32 * 64];
__device__ __align__(16) __nv_bfloat16 g_w2bh[9 * 32 * 64];   // knn W [tap][oc][c]
__device__ __align__(16) __nv_bfloat16 g_w2bl[9 * 32 * 64];
__device__ __align__(16) __nv_bfloat16 g_c2h[BATCH * 16384];  // cat2 hi [t][c]
__device__ __align__(16) __nv_bfloat16 g_c2l[BATCH * 16384];
__device__ __align__(16) __nv_bfloat16 g_wph[8192];           // w2p hi [oc][c]
__device__ __align__(16) __nv_bfloat16 g_wpl[8192];
__device__ __align__(16) __nv_bfloat16 g_ahi[BATCH * 32768];
__device__ __align__(16) __nv_bfloat16 g_alo[BATCH * 32768];

// ---------------- f32x2 helpers ----------------
__device__ __forceinline__ ull pack2(float lo, float hi) {
    ull r;
    asm("mov.b64 %0, {%1, %2};" : "=l"(r) : "r"(__float_as_uint(lo)), "r"(__float_as_uint(hi)));
    return r;
}
__device__ __forceinline__ ull packd(float s) { return pack2(s, s); }
__device__ __forceinline__ void fma2(ull& d, ull a, ull b) {
    asm("fma.rn.f32x2 %0, %1, %2, %3;" : "=l"(d) : "l"(a), "l"(b), "l"(d));
}
__device__ __forceinline__ float2 unpk(ull v) {
    unsigned lo, hi;
    asm("mov.b64 {%0, %1}, %2;" : "=r"(lo), "=r"(hi) : "l"(v));
    float2 f; f.x = __uint_as_float(lo); f.y = __uint_as_float(hi);
    return f;
}

// ---------------- mma.sync helpers ----------------
__device__ __forceinline__ unsigned smem_u32(const void* p) {
    unsigned a;
    asm("{ .reg .u64 t; cvta.to.shared.u64 t, %1; cvt.u32.u64 %0, t; }" : "=r"(a) : "l"(p));
    return a;
}
__device__ __forceinline__ void ldsm4(unsigned& r0, unsigned& r1, unsigned& r2, unsigned& r3,
                                      unsigned addr) {
    asm volatile("ldmatrix.sync.aligned.m8n8.x4.shared.b16 {%0,%1,%2,%3}, [%4];"
                 : "=r"(r0), "=r"(r1), "=r"(r2), "=r"(r3) : "r"(addr));
}
__device__ __forceinline__ void mma16816(float* c, const unsigned* a, const unsigned* b) {
    asm volatile(
        "mma.sync.aligned.m16n8k16.row.col.f32.bf16.bf16.f32 "
        "{%0,%1,%2,%3},{%4,%5,%6,%7},{%8,%9},{%0,%1,%2,%3};"
        : "+f"(c[0]), "+f"(c[1]), "+f"(c[2]), "+f"(c[3])
        : "r"(a[0]), "r"(a[1]), "r"(a[2]), "r"(a[3]), "r"(b[0]), "r"(b[1]));
}
__device__ __forceinline__ void cpa16(unsigned dst, const void* src) {
    asm volatile("cp.async.cg.shared.global [%0], [%1], 16;" :: "r"(dst), "l"(src));
}
__device__ __forceinline__ void cpa_commit() { asm volatile("cp.async.commit_group;"); }
__device__ __forceinline__ void cpa_wait0() {
    asm volatile("cp.async.wait_group 0;" ::: "memory");
}
__device__ __forceinline__ void cpa_wait1() {
    asm volatile("cp.async.wait_group 1;" ::: "memory");
}
__device__ __forceinline__ void sts128(unsigned addr, uint4 v) {
    asm volatile("st.shared.v4.b32 [%0], {%1,%2,%3,%4};"
                 :: "r"(addr), "r"(v.x), "r"(v.y), "r"(v.z), "r"(v.w));
}
__device__ __forceinline__ unsigned pkbf(float a, float b) {
    __nv_bfloat16 ha = __float2bfloat16(a), hb = __float2bfloat16(b);
    return ((unsigned)__bfloat16_as_ushort(hb) << 16) | __bfloat16_as_ushort(ha);
}
__device__ __forceinline__ void wsplit_store(unsigned hi_base, int row, int c,
                                             float4 a, float4 b) {
    unsigned sw = (unsigned)(row * 64 + ((c ^ ((row >> 1) & 3)) << 4));
    uint4 hi, lo;
    hi.x = pkbf(a.x, a.y); hi.y = pkbf(a.z, a.w);
    hi.z = pkbf(b.x, b.y); hi.w = pkbf(b.z, b.w);
    __nv_bfloat16 t0 = __float2bfloat16(a.x), t1 = __float2bfloat16(a.y);
    __nv_bfloat16 t2 = __float2bfloat16(a.z), t3 = __float2bfloat16(a.w);
    __nv_bfloat16 t4 = __float2bfloat16(b.x), t5 = __float2bfloat16(b.y);
    __nv_bfloat16 t6 = __float2bfloat16(b.z), t7 = __float2bfloat16(b.w);
    lo.x = pkbf(a.x - __bfloat162float(t0), a.y - __bfloat162float(t1));
    lo.y = pkbf(a.z - __bfloat162float(t2), a.w - __bfloat162float(t3));
    lo.z = pkbf(b.x - __bfloat162float(t4), b.y - __bfloat162float(t5));
    lo.w = pkbf(b.z - __bfloat162float(t6), b.w - __bfloat162float(t7));
    sts128(hi_base + sw, hi);
    sts128(hi_base + 8192 + sw, lo);
}
__device__ __forceinline__ void c2_store(long base, float r0, float r1) {
    __nv_bfloat16 h0 = __float2bfloat16(r0), h1 = __float2bfloat16(r1);
    *(unsigned*)&g_c2h[base] = pkbf(r0, r1);
    *(unsigned*)&g_c2l[base] = pkbf(r0 - __bfloat162float(h0), r1 - __bfloat162float(h1));
}

// ---------------- weight repack ----------------
__global__ __launch_bounds__(256) void k_repack(const float* __restrict__ w1a,
                                                const float* __restrict__ w1b,
                                                const float* __restrict__ w2a,
                                                const float* __restrict__ w2b,
                                                const float* __restrict__ w2p) {
    int i = blockIdx.x * 256 + threadIdx.x;
    if (i < 1728) {
        int oc = i / 108, rest = i % 108;
        g_r1a[rest * 16 + oc] = w1a[i];
        g_r1b[rest * 16 + oc] = w1b[i];
    }
    if (i < 8192) {
        float v = w2p[i];
        __nv_bfloat16 h = __float2bfloat16(v);
        g_wph[i] = h;
        g_wpl[i] = __float2bfloat16(v - __bfloat162float(h));
    }
    if (i < 18432) {
        int oc = i / 576, rest = i % 576;
        int c = rest / 9, k = rest % 9;
        float va = w2a[i];
        __nv_bfloat16 ha = __float2bfloat16(va);
        g_w2ah[(k * 32 + oc) * 64 + c] = ha;
        g_w2al[(k * 32 + oc) * 64 + c] = __float2bfloat16(va - __bfloat162float(ha));
        float vb = w2b[i];
        __nv_bfloat16 hb = __float2bfloat16(vb);
        g_w2bh[(k * 32 + oc) * 64 + c] = hb;
        g_w2bl[(k * 32 + oc) * 64 + c] = __float2bfloat16(vb - __bfloat162float(hb));
    }
}

// ======================= Layer 1 FUSED, pixel-split x2 ==========================
__global__ __launch_bounds__(128) void k_l1(const float* __restrict__ x,
                                            const int* __restrict__ idx,
                                            const float* __restrict__ b1a,
                                            const float* __restrict__ b1b,
                                            const float* __restrict__ wp,
                                            const float* __restrict__ bp) {
    __shared__ __align__(16) float xs[12 * 256];
    __shared__ __align__(16) float ss[12 * 64];
    __shared__ float sn[64];
    __shared__ __align__(16) float wsa[1728];
    __shared__ __align__(16) float wsb[1728];
    __shared__ __align__(16) float wsp[64 * 32];
    int b = blockIdx.x, tid = threadIdx.x;
    int p = blockIdx.y * 128 + tid;

    for (int i = tid; i < 12 * 256; i += 128) {
        int cu = i >> 8, t = i & 255;
        int h = t >> 4, w = t & 15;
        int c = cu >> 2, ii = (cu >> 1) & 1, jj = cu & 1;
        xs[i] = x[((b * 3 + c) * 32 + (2 * h + ii)) * 32 + 2 * w + jj];
    }
    for (int i = tid; i < 1728; i += 128) { wsa[i] = g_r1a[i]; wsb[i] = g_r1b[i]; }
    for (int i = tid; i < 64 * 32; i += 128) wsp[i] = wp[i];
    __syncthreads();
    for (int i = tid; i < 12 * 64; i += 128)
        ss[i] = xs[(i >> 6) * 256 + idx[i & 63]];
    __syncthreads();
    if (tid < 64) {
        float s = 0.f;
#pragma unroll
        for (int c = 0; c < 12; c++) { float v = ss[c * 64 + tid]; s += v * v; }
        sn[tid] = s;
    }
    __syncthreads();

    int h = p >> 4, w = p & 15;

    ull acv[8];
#pragma unroll
    for (int o = 0; o < 8; o++) acv[o] = pack2(b1a[2 * o], b1a[2 * o + 1]);
    for (int c = 0; c < 12; c++) {
        float pp[9];
#pragma unroll
        for (int dy = 0; dy < 3; dy++)
#pragma unroll
            for (int dx = 0; dx < 3; dx++) {
                int y = h + dy - 1, xq = w + dx - 1;
                pp[dy * 3 + dx] = (y >= 0 && y < 16 && xq >= 0 && xq < 16)
                                      ? xs[c * 256 + y * 16 + xq] : 0.f;
            }
#pragma unroll
        for (int tap = 0; tap < 9; tap++) {
            ull s2 = packd(pp[tap]);
            const longlong2* wv = (const longlong2*)&wsa[(c * 9 + tap) * 16];
#pragma unroll
            for (int q = 0; q < 4; q++) {
                longlong2 w4 = wv[q];
                fma2(acv[q * 2 + 0], s2, (ull)w4.x);
                fma2(acv[q * 2 + 1], s2, (ull)w4.y);
            }
        }
    }

    float xr[12]; float xn = 0.f;
#pragma unroll
    for (int c = 0; c < 12; c++) { float v = xs[c * 256 + p]; xr[c] = v; xn += v * v; }

    float bd[9]; int bi[9];
#pragma unroll
    for (int k = 0; k < 9; k++) { bd[k] = 3.0e38f; bi[k] = 0; }
    for (int n = 0; n < 64; n++) {
        float dot = 0.f;
#pragma unroll
        for (int c = 0; c < 12; c++) dot += xr[c] * ss[c * 64 + n];
        float d = xn + sn[n] - 2.f * dot;
        if (d < bd[8]) {
            bool placed = false;
#pragma unroll
            for (int j = 8; j > 0; --j) {
                if (!placed) {
                    if (d < bd[j - 1]) { bd[j] = bd[j - 1]; bi[j] = bi[j - 1]; }
                    else { bd[j] = d; bi[j] = n; placed = true; }
                }
            }
            if (!placed) { bd[0] = d; bi[0] = n; }
        }
    }

    ull akn[8];
#pragma unroll
    for (int o = 0; o < 8; o++) akn[o] = pack2(b1b[2 * o], b1b[2 * o + 1]);
#pragma unroll
    for (int c = 0; c < 12; c++) {
#pragma unroll
        for (int k = 0; k < 9; k++) {
            ull s2 = packd(ss[c * 64 + bi[k]]);
            const longlong2* wv = (const longlong2*)&wsb[(c * 9 + k) * 16];
#pragma unroll
            for (int q = 0; q < 4; q++) {
                longlong2 w4 = wv[q];
                fma2(akn[q * 2 + 0], s2, (ull)w4.x);
                fma2(akn[q * 2 + 1], s2, (ull)w4.y);
            }
        }
    }

    ull xv[16];
#pragma unroll
    for (int o = 0; o < 8; o++) {
        float2 v = unpk(acv[o]);
        xv[o] = pack2(fmaxf(v.x, 0.f), fmaxf(v.y, 0.f));
        float2 u = unpk(akn[o]);
        xv[8 + o] = pack2(fmaxf(u.x, 0.f), fmaxf(u.y, 0.f));
    }
    float vb[8];
    for (int oc = 0; oc < 64; oc++) {
        ull a2 = 0ull;
        const longlong2* wv = (const longlong2*)&wsp[oc * 32];
#pragma unroll
        for (int q = 0; q < 8; q++) {
            longlong2 w4 = wv[q];
            fma2(a2, xv[q * 2 + 0], (ull)w4.x);
            fma2(a2, xv[q * 2 + 1], (ull)w4.y);
        }
        float2 v = unpk(a2);
        float val = v.x + v.y + bp[oc];
        g_out1[(b * 64 + oc) * 256 + p] = val;
        vb[oc & 7] = val;
        if ((oc & 7) == 7) {
            uint4 hi, lo;
            hi.x = pkbf(vb[0], vb[1]); hi.y = pkbf(vb[2], vb[3]);
            hi.z = pkbf(vb[4], vb[5]); hi.w = pkbf(vb[6], vb[7]);
            float l[8];
#pragma unroll
            for (int j = 0; j < 8; j++)
                l[j] = vb[j] - __bfloat162float(__float2bfloat16(vb[j]));
            lo.x = pkbf(l[0], l[1]); lo.y = pkbf(l[2], l[3]);
            lo.z = pkbf(l[4], l[5]); lo.w = pkbf(l[6], l[7]);
            long base = (long)b * 16384 + p * 64 + (oc - 7);
            *(uint4*)&g_o1h[base] = hi;
            *(uint4*)&g_o1l[base] = lo;
        }
    }
}

// ========== Layer 2 conv 3x3 (64->32) as implicit-GEMM bf16 split mma ===========
__global__ __launch_bounds__(256) void k_l2c(const float* __restrict__ ba) {
    extern __shared__ __align__(16) char smem[];
    unsigned sb = smem_u32(smem);
    const unsigned XH = 0, XL = 33024, AH = 66048, AL = 102912;
    int b = blockIdx.x, tid = threadIdx.x, lane = tid & 31, warp = tid >> 5;

    if (tid < 16) {
        uint4 z = make_uint4(0, 0, 0, 0);
        unsigned pl = (tid >> 3) ? XL : XH;
        sts128(sb + pl + 256 * 128 + ((tid & 7) << 4), z);
    }
#pragma unroll
    for (int j = 0; j < 8; j++) {
        int q = tid + j * 256;
        int row = q >> 3, ch = q & 7;
        unsigned sw = (unsigned)(row * 128 + ((ch ^ (row & 7)) << 4));
        cpa16(sb + XH + sw, g_o1h + (long)b * 16384 + row * 64 + ch * 8);
        cpa16(sb + XL + sw, g_o1l + (long)b * 16384 + row * 64 + ch * 8);
    }
#pragma unroll
    for (int j = 0; j < 9; j++) {
        int q = tid + j * 256;
        int row = q >> 3, ch = q & 7;
        unsigned sw = (unsigned)(row * 128 + ((ch ^ (row & 7)) << 4));
        cpa16(sb + AH + sw, g_w2ah + row * 64 + ch * 8);
        cpa16(sb + AL + sw, g_w2al + row * 64 + ch * 8);
    }
    cpa_commit();
    cpa_wait0();
    __syncthreads();

    int n_base = warp * 32;
    int ri = lane & 7, mat = lane >> 3;

    float acc[2][4][4];
#pragma unroll
    for (int i = 0; i < 2; i++)
#pragma unroll
        for (int j = 0; j < 4; j++)
#pragma unroll
            for (int q = 0; q < 4; q++) acc[i][j][q] = 0.f;

#pragma unroll
    for (int tap = 0; tap < 9; tap++) {
        int dy = tap / 3, dx = tap % 3;
        int rin[2];
#pragma unroll
        for (int ng = 0; ng < 2; ng++) {
            int t = n_base + ng * 16 + ri + ((mat >> 1) << 3);
            int h = (t >> 4) + dy - 1, w = (t & 15) + dx - 1;
            rin[ng] = ((unsigned)h < 16u && (unsigned)w < 16u) ? h * 16 + w : 256;
        }
#pragma unroll
        for (int k16 = 0; k16 < 4; k16++) {
            unsigned af[2][4], bh[4][2], bl[4][2];
            int chb = k16 * 2 + (mat & 1);
#pragma unroll
            for (int ng = 0; ng < 2; ng++) {
                int r = rin[ng];
                unsigned sw = (unsigned)(r * 128 + ((chb ^ (r & 7)) << 4));
                unsigned r0, r1, r2, r3;
                ldsm4(r0, r1, r2, r3, sb + XH + sw);
                bh[2 * ng][0] = r0; bh[2 * ng][1] = r1;
                bh[2 * ng + 1][0] = r2; bh[2 * ng + 1][1] = r3;
                ldsm4(r0, r1, r2, r3, sb + XL + sw);
                bl[2 * ng][0] = r0; bl[2 * ng][1] = r1;
                bl[2 * ng + 1][0] = r2; bl[2 * ng + 1][1] = r3;
            }
            int cha = k16 * 2 + (mat >> 1);
#pragma unroll
            for (int mi = 0; mi < 2; mi++) {
                int row = tap * 32 + mi * 16 + ri + ((mat & 1) << 3);
                unsigned ad = sb + AH + row * 128 + ((cha ^ (row & 7)) << 4);
                ldsm4(af[mi][0], af[mi][1], af[mi][2], af[mi][3], ad);
            }
#pragma unroll
            for (int mi = 0; mi < 2; mi++)
#pragma unroll
                for (int ni = 0; ni < 4; ni++) {
                    mma16816(acc[mi][ni], af[mi], bh[ni]);
                    mma16816(acc[mi][ni], af[mi], bl[ni]);
                }
#pragma unroll
            for (int mi = 0; mi < 2; mi++) {
                int row = tap * 32 + mi * 16 + ri + ((mat & 1) << 3);
                unsigned ad = sb + AL + row * 128 + ((cha ^ (row & 7)) << 4);
                ldsm4(af[mi][0], af[mi][1], af[mi][2], af[mi][3], ad);
            }
#pragma unroll
            for (int mi = 0; mi < 2; mi++)
#pragma unroll
                for (int ni = 0; ni < 4; ni++)
                    mma16816(acc[mi][ni], af[mi], bh[ni]);
        }
    }

#pragma unroll
    for (int mi = 0; mi < 2; mi++) {
        int oc0 = mi * 16 + (lane >> 2);
        float bias0 = ba[oc0], bias1 = ba[oc0 + 8];
#pragma unroll
        for (int ni = 0; ni < 4; ni++) {
            int t0 = n_base + ni * 8 + (lane & 3) * 2;
#pragma unroll
            for (int q = 0; q < 4; q++) {
                int oc = (q < 2) ? oc0 : oc0 + 8;
                float v = fmaxf(acc[mi][ni][q] + ((q < 2) ? bias0 : bias1), 0.f);
                int t = t0 + (q & 1);
                long base = (long)b * 16384 + t * 64 + oc;
                __nv_bfloat16 h = __float2bfloat16(v);
                g_c2h[base] = h;
                g_c2l[base] = __float2bfloat16(v - __bfloat162float(h));
            }
        }
    }
}

// ======================= Layer 2 kNN branch (mma M-table) =======================
// smem: ss fp32 [n][66] 16896 | sn 256 | region @17152:
//   phase 1: Sh [n][c] bf16 8192 | Sl 8192   (M-GEMM input planes)
//   phase 2: Mt [(k*64+n)][36] fp32 82944    (aliases phase-1 region)
// total 100096 B -> 2 blocks/SM.
__global__ __launch_bounds__(288, 2) void k_l2_knn(const int* __restrict__ idx,
                                                   const float* __restrict__ bb) {
    extern __shared__ __align__(16) char smem[];
    unsigned sb = smem_u32(smem);
    float* ss = (float*)smem;
    float* sn = (float*)(smem + 16896);
    const unsigned SH = 17152, SL = 17152 + 8192;
    float* Mt = (float*)(smem + 17152);
    int b = blockIdx.x, tid = threadIdx.x, lane = tid & 31, wid = tid >> 5;

    for (int i = tid; i < 4096; i += 288) {
        int n = i & 63, c = i >> 6;
        ss[n * 66 + c] = g_out1[(b * 64 + c) * 256 + idx[n]];
    }
    __syncthreads();
    // bf16 hi/lo planes of S + sample norms
    for (int i = tid; i < 2048; i += 288) {
        int n = i >> 5, cp = (i & 31) * 2;
        float f0 = ss[n * 66 + cp], f1 = ss[n * 66 + cp + 1];
        int ch = cp >> 3;
        unsigned off = (unsigned)(n * 128 + ((ch ^ (n & 7)) << 4) + (cp & 7) * 2);
        __nv_bfloat16 h0 = __float2bfloat16(f0), h1 = __float2bfloat16(f1);
        *(unsigned*)(smem + SH + off) = pkbf(f0, f1);
        *(unsigned*)(smem + SL + off) =
            pkbf(f0 - __bfloat162float(h0), f1 - __bfloat162float(h1));
    }
    if (tid < 64) {
        float s = 0.f;
#pragma unroll 16
        for (int c = 0; c < 64; c++) { float v = ss[tid * 66 + c]; s += v * v; }
        sn[tid] = s;
    }
    __syncthreads();

    // ---- M-GEMM: warp w computes M[tap=w][n 0..63][oc 0..31] via 3-term mma ----
    int ri = lane & 7, mat = lane >> 3;
    float acc[2][8][4];
#pragma unroll
    for (int i = 0; i < 2; i++)
#pragma unroll
        for (int j = 0; j < 8; j++)
#pragma unroll
            for (int q = 0; q < 4; q++) acc[i][j][q] = 0.f;

    {
        int w = wid;
        int arow = (lane >> 2), acol = (lane & 3) * 2;
#pragma unroll
        for (int k16 = 0; k16 < 4; k16++) {
#pragma unroll
            for (int half = 0; half < 2; half++) {
                unsigned bh[4][2], bl[4][2];
                int chb = k16 * 2 + (mat & 1);
#pragma unroll
                for (int ng = 0; ng < 2; ng++) {
                    int row = half * 32 + ng * 16 + ri + ((mat >> 1) << 3);
                    unsigned sw = (unsigned)(row * 128 + ((chb ^ (row & 7)) << 4));
                    unsigned r0, r1, r2, r3;
                    ldsm4(r0, r1, r2, r3, sb + SH + sw);
                    bh[2 * ng][0] = r0; bh[2 * ng][1] = r1;
                    bh[2 * ng + 1][0] = r2; bh[2 * ng + 1][1] = r3;
                    ldsm4(r0, r1, r2, r3, sb + SL + sw);
                    bl[2 * ng][0] = r0; bl[2 * ng][1] = r1;
                    bl[2 * ng + 1][0] = r2; bl[2 * ng + 1][1] = r3;
                }
#pragma unroll
                for (int mi = 0; mi < 2; mi++) {
                    long wbase = (long)(w * 32 + mi * 16 + arow) * 64 + k16 * 16 + acol;
                    unsigned ah[4];
                    ah[0] = *(const unsigned*)(g_w2bh + wbase);
                    ah[1] = *(const unsigned*)(g_w2bh + wbase + 8 * 64);
                    ah[2] = *(const unsigned*)(g_w2bh + wbase + 8);
                    ah[3] = *(const unsigned*)(g_w2bh + wbase + 8 * 64 + 8);
#pragma unroll
                    for (int nj = 0; nj < 4; nj++) {
                        mma16816(acc[mi][half * 4 + nj], ah, bh[nj]);
                        mma16816(acc[mi][half * 4 + nj], ah, bl[nj]);
                    }
                    ah[0] = *(const unsigned*)(g_w2bl + wbase);
                    ah[1] = *(const unsigned*)(g_w2bl + wbase + 8 * 64);
                    ah[2] = *(const unsigned*)(g_w2bl + wbase + 8);
                    ah[3] = *(const unsigned*)(g_w2bl + wbase + 8 * 64 + 8);
#pragma unroll
                    for (int nj = 0; nj < 4; nj++)
                        mma16816(acc[mi][half * 4 + nj], ah, bh[nj]);
                }
            }
        }
    }
    __syncthreads();   // all SH/SL reads done; Mt may now overwrite that region

    // write M: fragment (mi, nj, q) -> oc row, n col
    {
        int w = wid;
#pragma unroll
        for (int mi = 0; mi < 2; mi++) {
            int oc0 = mi * 16 + (lane >> 2);
#pragma unroll
            for (int nj = 0; nj < 8; nj++) {
                int n0 = nj * 8 + (lane & 3) * 2;
#pragma unroll
                for (int q = 0; q < 4; q++) {
                    int oc = (q < 2) ? oc0 : oc0 + 8;
                    int n = n0 + (q & 1);
                    Mt[(w * 64 + n) * 36 + oc] = acc[mi][nj][q];
                }
            }
        }
    }
    __syncthreads();

    if (tid < 256) {
        int t = tid;
        ull xr2[32]; float xn = 0.f;
#pragma unroll
        for (int c2 = 0; c2 < 32; c2++) {
            float f0 = g_out1[(b * 64 + 2 * c2) * 256 + t];
            float f1 = g_out1[(b * 64 + 2 * c2 + 1) * 256 + t];
            xn += f0 * f0 + f1 * f1;
            xr2[c2] = pack2(f0, f1);
        }

        float bd[9]; int bi[9];
#pragma unroll
        for (int k = 0; k < 9; k++) { bd[k] = 3.0e38f; bi[k] = 0; }
        for (int n = 0; n < 64; n++) {
            const ull* sp = (const ull*)&ss[n * 66];
            ull d2 = 0ull;
#pragma unroll
            for (int j = 0; j < 32; j++) fma2(d2, xr2[j], sp[j]);
            float2 dv = unpk(d2);
            float d = xn + sn[n] - 2.f * (dv.x + dv.y);
            if (d < bd[8]) {
                bool placed = false;
#pragma unroll
                for (int j = 8; j > 0; --j) {
                    if (!placed) {
                        if (d < bd[j - 1]) { bd[j] = bd[j - 1]; bi[j] = bi[j - 1]; }
                        else { bd[j] = d; bi[j] = n; placed = true; }
                    }
                }
                if (!placed) { bd[0] = d; bi[0] = n; }
            }
        }

#pragma unroll
        for (int half = 0; half < 2; half++) {
            float acm[16];
#pragma unroll
            for (int o = 0; o < 16; o++) acm[o] = bb[half * 16 + o];
#pragma unroll
            for (int k = 0; k < 9; k++) {
                const float4* m4 = (const float4*)&Mt[(k * 64 + bi[k]) * 36 + half * 16];
                float4 v0 = m4[0], v1 = m4[1], v2 = m4[2], v3 = m4[3];
                acm[0] += v0.x; acm[1] += v0.y; acm[2] += v0.z; acm[3] += v0.w;
                acm[4] += v1.x; acm[5] += v1.y; acm[6] += v1.z; acm[7] += v1.w;
                acm[8] += v2.x; acm[9] += v2.y; acm[10] += v2.z; acm[11] += v2.w;
                acm[12] += v3.x; acm[13] += v3.y; acm[14] += v3.z; acm[15] += v3.w;
            }
#pragma unroll
            for (int j = 0; j < 8; j++)
                c2_store((long)b * 16384 + t * 64 + 32 + half * 16 + 2 * j,
                         fmaxf(acm[2 * j], 0.f), fmaxf(acm[2 * j + 1], 0.f));
        }
    }
}

// ======== Layer 2 pw as bf16 split mma: C[128][256] = W[128x64] * cat2 ==========
__global__ __launch_bounds__(256) void k_l2_pw(const float* __restrict__ bp) {
    extern __shared__ __align__(16) char smem[];
    unsigned sb = smem_u32(smem);
    int b = blockIdx.x, tid = threadIdx.x, lane = tid & 31, warp = tid >> 5;

#pragma unroll
    for (int j = 0; j < 8; j++) {
        int q = tid + j * 256;
        int row = q >> 3, ch = q & 7;
        unsigned dst = sb + row * 128 + ((ch ^ (row & 7)) << 4);
        cpa16(dst, g_c2h + (long)b * 16384 + row * 64 + ch * 8);
        cpa16(dst + 32768, g_c2l + (long)b * 16384 + row * 64 + ch * 8);
    }
#pragma unroll
    for (int j = 0; j < 4; j++) {
        int q = tid + j * 256;
        int row = q >> 3, ch = q & 7;
        unsigned dst = sb + 65536 + row * 128 + ((ch ^ (row & 7)) << 4);
        cpa16(dst, g_wph + row * 64 + ch * 8);
        cpa16(dst + 16384, g_wpl + row * 64 + ch * 8);
    }
    cpa_commit();
    cpa_wait0();
    __syncthreads();

    int m_base = (warp & 1) * 64;
    int n_base = (warp >> 1) * 64;
    int ri = lane & 7, mat = lane >> 3;

    float acc[4][8][4];
#pragma unroll
    for (int i = 0; i < 4; i++)
#pragma unroll
        for (int j = 0; j < 8; j++)
#pragma unroll
            for (int q = 0; q < 4; q++) acc[i][j][q] = 0.f;

#pragma unroll
    for (int kk = 0; kk < 4; kk++) {
        unsigned af[4][4], bh[8][2], bl[8][2];
#pragma unroll
        for (int ng = 0; ng < 4; ng++) {
            int row = n_base + ng * 16 + ri + ((mat >> 1) << 3);
            int ch = kk * 2 + (mat & 1);
            unsigned bd_ = sb + row * 128 + ((ch ^ (row & 7)) << 4);
            unsigned r0, r1, r2, r3;
            ldsm4(r0, r1, r2, r3, bd_);
            bh[2 * ng][0] = r0; bh[2 * ng][1] = r1;
            bh[2 * ng + 1][0] = r2; bh[2 * ng + 1][1] = r3;
            ldsm4(r0, r1, r2, r3, bd_ + 32768);
            bl[2 * ng][0] = r0; bl[2 * ng][1] = r1;
            bl[2 * ng + 1][0] = r2; bl[2 * ng + 1][1] = r3;
        }
#pragma unroll
        for (int mi = 0; mi < 4; mi++) {
            int row = m_base + mi * 16 + ri + ((mat & 1) << 3);
            int ch = kk * 2 + (mat >> 1);
            unsigned ad = sb + 65536 + row * 128 + ((ch ^ (row & 7)) << 4);
            ldsm4(af[mi][0], af[mi][1], af[mi][2], af[mi][3], ad);
        }
#pragma unroll
        for (int mi = 0; mi < 4; mi++)
#pragma unroll
            for (int ni = 0; ni < 8; ni++) {
                mma16816(acc[mi][ni], af[mi], bh[ni]);
                mma16816(acc[mi][ni], af[mi], bl[ni]);
            }
#pragma unroll
        for (int mi = 0; mi < 4; mi++) {
            int row = m_base + mi * 16 + ri + ((mat & 1) << 3);
            int ch = kk * 2 + (mat >> 1);
            unsigned ad = sb + 81920 + row * 128 + ((ch ^ (row & 7)) << 4);
            ldsm4(af[mi][0], af[mi][1], af[mi][2], af[mi][3], ad);
        }
#pragma unroll
        for (int mi = 0; mi < 4; mi++)
#pragma unroll
            for (int ni = 0; ni < 8; ni++)
                mma16816(acc[mi][ni], af[mi], bh[ni]);
    }

#pragma unroll
    for (int mi = 0; mi < 4; mi++) {
        int oc0 = m_base + mi * 16 + (lane >> 2);
        float bias0 = bp[oc0], bias1 = bp[oc0 + 8];
#pragma unroll
        for (int ni = 0; ni < 8; ni++) {
            int t0 = n_base + ni * 8 + (lane & 3) * 2;
#pragma unroll
            for (int q = 0; q < 4; q++) {
                int oc = (q < 2) ? oc0 : oc0 + 8;
                float v = acc[mi][ni][q] + ((q < 2) ? bias0 : bias1);
                int t = t0 + (q & 1);
                int cp = oc >> 2, ii = (oc >> 1) & 1, jj = oc & 1;
                int h = t >> 4, w = t & 15;
                long pos = (long)b * 32768 + cp * 1024 + (2 * h + ii) * 32 + 2 * w + jj;
                __nv_bfloat16 hi = __float2bfloat16(v);
                g_ahi[pos] = hi;
                g_alo[pos] = __float2bfloat16(v - __bfloat162float(hi));
            }
        }
    }
}

// ======================= fc1: bf16 split GEMM, 3-stage pipeline =================
__global__ __launch_bounds__(512) void k_fc1t(const float* __restrict__ W) {
    extern __shared__ __align__(16) char smem[];
    unsigned sbase = smem_u32(smem);
    int tid = threadIdx.x, lane = tid & 31, warp = tid >> 5;
    int n0 = blockIdx.x * 128, sk = blockIdx.z;
    long kbase = (long)sk * 2048;

    int m_base = (warp & 3) * 64;
    int n_base = (warp >> 2) * 32;

    int aq[2], ac[2];
#pragma unroll
    for (int j = 0; j < 2; j++) { int q = tid + j * 512; aq[j] = q >> 2; ac[j] = q & 3; }
    int wr = tid >> 2, wc = tid & 3;

    float acc[4][4][4];
#pragma unroll
    for (int i = 0; i < 4; i++)
#pragma unroll
        for (int j = 0; j < 4; j++)
#pragma unroll
            for (int q = 0; q < 4; q++) acc[i][j][q] = 0.f;

    const float* wgp = W + (long)(n0 + wr) * 32768 + kbase + wc * 8;

    float4 wa0 = *(const float4*)(wgp), wb0 = *(const float4*)(wgp + 4);
    float4 wa1 = *(const float4*)(wgp + 32), wb1 = *(const float4*)(wgp + 36);
#pragma unroll
    for (int j = 0; j < 2; j++) {
        int r = aq[j], c = ac[j];
        unsigned sw = (unsigned)(r * 64 + ((c ^ ((r >> 1) & 3)) << 4));
        cpa16(sbase + sw, g_ahi + (long)r * 32768 + kbase + c * 8);
        cpa16(sbase + 16384 + sw, g_alo + (long)r * 32768 + kbase + c * 8);
    }
    cpa_commit();
#pragma unroll
    for (int j = 0; j < 2; j++) {
        int r = aq[j], c = ac[j];
        unsigned sw = (unsigned)(r * 64 + ((c ^ ((r >> 1) & 3)) << 4));
        cpa16(sbase + 49152 + sw, g_ahi + (long)r * 32768 + kbase + 32 + c * 8);
        cpa16(sbase + 49152 + 16384 + sw, g_alo + (long)r * 32768 + kbase + 32 + c * 8);
    }
    cpa_commit();
    wsplit_store(sbase + 32768, wr, wc, wa0, wb0);
    wsplit_store(sbase + 49152 + 32768, wr, wc, wa1, wb1);

    int ri = lane & 7, mat = lane >> 3;

    for (int it = 0; it < 64; it++) {
        unsigned stb = sbase + (unsigned)(it % 3) * 49152u;
        cpa_wait1();
        __syncthreads();

        float4 wna, wnb;
        unsigned nb = sbase + (unsigned)((it + 2) % 3) * 49152u;
        if (it < 62) {
            long ko = kbase + (it + 2) * 32;
            wna = *(const float4*)(wgp + (it + 2) * 32);
            wnb = *(const float4*)(wgp + (it + 2) * 32 + 4);
#pragma unroll
            for (int j = 0; j < 2; j++) {
                int r = aq[j], c = ac[j];
                unsigned sw = (unsigned)(r * 64 + ((c ^ ((r >> 1) & 3)) << 4));
                cpa16(nb + sw, g_ahi + (long)r * 32768 + ko + c * 8);
                cpa16(nb + 16384 + sw, g_alo + (long)r * 32768 + ko + c * 8);
            }
        }
        cpa_commit();

#pragma unroll
        for (int k16 = 0; k16 < 2; k16++) {
            unsigned af[4][4], bh[4][2], bl[4][2];
#pragma unroll
            for (int ng = 0; ng < 2; ng++) {
                int row = n_base + ng * 16 + ri + ((mat >> 1) << 3);
                int c = k16 * 2 + (mat & 1);
                unsigned bd_ = stb + 32768 + row * 64 + ((c ^ ((row >> 1) & 3)) << 4);
                unsigned r0, r1, r2, r3;
                ldsm4(r0, r1, r2, r3, bd_);
                bh[2 * ng][0] = r0; bh[2 * ng][1] = r1;
                bh[2 * ng + 1][0] = r2; bh[2 * ng + 1][1] = r3;
                ldsm4(r0, r1, r2, r3, bd_ + 8192);
                bl[2 * ng][0] = r0; bl[2 * ng][1] = r1;
                bl[2 * ng + 1][0] = r2; bl[2 * ng + 1][1] = r3;
            }
#pragma unroll
            for (int mi = 0; mi < 4; mi++) {
                int row = m_base + mi * 16 + ri + ((mat & 1) << 3);
                int c = k16 * 2 + (mat >> 1);
                unsigned ad = stb + row * 64 + ((c ^ ((row >> 1) & 3)) << 4);
                ldsm4(af[mi][0], af[mi][1], af[mi][2], af[mi][3], ad);
            }
#pragma unroll
            for (int mi = 0; mi < 4; mi++)
#pragma unroll
                for (int ni = 0; ni < 4; ni++) {
                    mma16816(acc[mi][ni], af[mi], bh[ni]);
                    mma16816(acc[mi][ni], af[mi], bl[ni]);
                }
#pragma unroll
            for (int mi = 0; mi < 4; mi++) {
                int row = m_base + mi * 16 + ri + ((mat & 1) << 3);
                int c = k16 * 2 + (mat >> 1);
                unsigned ad = stb + 16384 + row * 64 + ((c ^ ((row >> 1) & 3)) << 4);
                ldsm4(af[mi][0], af[mi][1], af[mi][2], af[mi][3], ad);
            }
#pragma unroll
            for (int mi = 0; mi < 4; mi++)
#pragma unroll
                for (int ni = 0; ni < 4; ni++)
                    mma16816(acc[mi][ni], af[mi], bh[ni]);
        }

        if (it < 62)
            wsplit_store(nb + 32768, wr, wc, wna, wnb);
    }

    float* slab = g_fc1p + (long)sk * BATCH * 1024;
#pragma unroll
    for (int mi = 0; mi < 4; mi++)
#pragma unroll
        for (int ni = 0; ni < 4; ni++) {
            int m = m_base + mi * 16 + (lane >> 2);
            int n = n0 + n_base + ni * 8 + (lane & 3) * 2;
            *(float2*)&slab[(long)m * 1024 + n] =
                make_float2(acc[mi][ni][0], acc[mi][ni][1]);
            *(float2*)&slab[(long)(m + 8) * 1024 + n] =
                make_float2(acc[mi][ni][2], acc[mi][ni][3]);
        }
}

// ======================= fc2 (fused slab-reduce + relu + fc2) ===================
__global__ __launch_bounds__(256) void k_fc2(const float* __restrict__ fc1b,
                                             const float* __restrict__ w2,
                                             const float* __restrict__ b2,
                                             float* __restrict__ out) {
    __shared__ __align__(16) float hs[1024];
    __shared__ float red[10 * 256];
    int b = blockIdx.x, tid = threadIdx.x;
    for (int j = tid; j < 1024; j += 256) {
        float s = 0.f;
#pragma unroll
        for (int q = 0; q < 16; q++) s += g_fc1p[(long)q * BATCH * 1024 + b * 1024 + j];
        hs[j] = fmaxf(s + fc1b[j], 0.f);
    }
    __syncthreads();
    float p[10];
#pragma unroll
    for (int n = 0; n < 10; n++) p[n] = 0.f;
    for (int j = tid; j < 1024; j += 256) {
        float hv = hs[j];
#pragma unroll
        for (int n = 0; n < 10; n++) p[n] += hv * w2[n * 1024 + j];
    }
#pragma unroll
    for (int n = 0; n < 10; n++) red[n * 256 + tid] = p[n];
    __syncthreads();
    for (int s = 128; s > 0; s >>= 1) {
        if (tid < s) {
#pragma unroll
            for (int n = 0; n < 10; n++) red[n * 256 + tid] += red[n * 256 + tid + s];
        }
        __syncthreads();
    }
    if (tid < 10) out[b * 10 + tid] = red[tid * 256] + b2[tid];
}

// =================================================================================
extern "C" void kernel_launch(void* const* d_in, const int* in_sizes, int n_in,
                              void* d_out, int out_size) {
    const float* x    = (const float*)d_in[0];
    const int*   idx1 = (const int*)d_in[1];
    const int*   idx2 = (const int*)d_in[2];
    const float* w1a  = (const float*)d_in[3];
    const float* b1a  = (const float*)d_in[4];
    const float* w1b  = (const float*)d_in[5];
    const float* b1b  = (const float*)d_in[6];
    const float* w1p  = (const float*)d_in[7];
    const float* b1p  = (const float*)d_in[8];
    const float* w2a  = (const float*)d_in[9];
    const float* b2a  = (const float*)d_in[10];
    const float* w2b  = (const float*)d_in[11];
    const float* b2b  = (const float*)d_in[12];
    const float* w2p  = (const float*)d_in[13];
    const float* b2p  = (const float*)d_in[14];
    const float* fc1w = (const float*)d_in[15];
    const float* fc1b = (const float*)d_in[16];
    const float* fc2w = (const float*)d_in[17];
    const float* fc2b = (const float*)d_in[18];
    float* out = (float*)d_out;

    const int smem_l2c  = 139776;
    const int smem_knn  = 100096;
    const int smem_pw   = 98304;
    const int smem_fc1t = 147456;
    cudaFuncSetAttribute(k_l2c,    cudaFuncAttributeMaxDynamicSharedMemorySize, smem_l2c);
    cudaFuncSetAttribute(k_l2_knn, cudaFuncAttributeMaxDynamicSharedMemorySize, smem_knn);
    cudaFuncSetAttribute(k_l2_pw,  cudaFuncAttributeMaxDynamicSharedMemorySize, smem_pw);
    cudaFuncSetAttribute(k_fc1t,   cudaFuncAttributeMaxDynamicSharedMemorySize, smem_fc1t);

    k_repack<<<72, 256>>>(w1a, w1b, w2a, w2b, w2p);
    k_l1<<<dim3(BATCH, 2), 128>>>(x, idx1, b1a, b1b, w1p, b1p);
    k_l2_knn<<<BATCH, 288, smem_knn>>>(idx2, b2b);
    k_l2c<<<BATCH, 256, smem_l2c>>>(b2a);
    k_l2_pw<<<BATCH, 256, smem_pw>>>(b2p);
    k_fc1t<<<dim3(8, 1, 16), 512, smem_fc1t>>>(fc1w);
    k_fc2<<<BATCH, 256>>>(fc1b, fc2w, fc2b, out);
}